// round 7
// baseline (speedup 1.0000x reference)
#include <cuda_runtime.h>
#include <cuda_bf16.h>
#include <math.h>

#define NBATCH 2
#define NLR    4096
#define NPTS   (NBATCH*NLR)
#define SPLITS 8
#define KT     32
#define RT     128

#define W3J_TOTAL   13318
#define W3J_OUT_OFF 2670

__device__ float d_feat0[NPTS*22];
__device__ float d_feat1[NPTS*22];
__device__ float d_qvT[22*NPTS];
__device__ float d_kvT[22*NPTS];
__device__ __align__(16) float d_gv  [NPTS*68];
__device__ __align__(16) float d_part[SPLITS*NPTS*68];
__device__ float d_G   [66*NPTS];
__device__ float d_sh  [NLR*6];
__device__ float d_eb  [2*NLR];
__device__ float d_w3j [W3J_TOTAL];
__device__ float d_coef[2*8*3];

__constant__ int PATH_L[14][3] = {
  {4,0,4},{4,2,4},{6,2,4},{6,0,6},{4,2,6},{6,2,6},
  {4,4,4},{4,6,4},{6,4,4},{6,6,4},{4,4,6},{4,6,6},{6,4,6},{6,6,6}};
__constant__ int PATH_OFF[15] = {
  0,81,486,1071,1240,1825,2670,3399,4452,5505,7026,8079,9600,11121,13318};

// ---------------- f32x2 packed helpers ----------------
__device__ __forceinline__ unsigned long long pack2(float lo, float hi){
  unsigned long long r;
  asm("mov.b64 %0, {%1, %2};" : "=l"(r) : "f"(lo), "f"(hi));
  return r;
}
__device__ __forceinline__ void unpack2(unsigned long long v, float& lo, float& hi){
  asm("mov.b64 {%0, %1}, %2;" : "=f"(lo), "=f"(hi) : "l"(v));
}
__device__ __forceinline__ unsigned long long fma2(unsigned long long a,
                                                   unsigned long long b,
                                                   unsigned long long c){
  unsigned long long d;
  asm("fma.rn.f32x2 %0, %1, %2, %3;" : "=l"(d) : "l"(a), "l"(b), "l"(c));
  return d;
}

// ---------------- W3J (real Wigner/CG) ----------------
struct Cpx { double re, im; };

__device__ __forceinline__ double dev_cg(int j1,int m1,int j2,int m2,int j3,int m3,const double* f){
  if (m1+m2 != m3) return 0.0;
  if (j3 < abs(j1-j2) || j3 > j1+j2) return 0.0;
  double pref = sqrt((2.0*j3+1.0)*f[j3+j1-j2]*f[j3-j1+j2]*f[j1+j2-j3]/f[j1+j2+j3+1]);
  pref *= sqrt(f[j3+m3]*f[j3-m3]*f[j1-m1]*f[j1+m1]*f[j2-m2]*f[j2+m2]);
  double s = 0.0;
  int kmax = j1+j2-j3;
  for (int k=0;k<=kmax;k++){
    int a3=j1-m1-k, a4=j2+m2-k, a5=j3-j2+m1+k, a6=j3-j1-m2+k;
    if (a3<0||a4<0||a5<0||a6<0) continue;
    double t = 1.0/(f[k]*f[kmax-k]*f[a3]*f[a4]*f[a5]*f[a6]);
    s += (k&1)? -t : t;
  }
  return pref*s;
}

__device__ __forceinline__ int unz(int l, int r, int* cols, Cpx* vals){
  const double s2 = 0.70710678118654752440;
  if (r == l){ cols[0]=l; vals[0]=Cpx{1.0,0.0}; return 1; }
  if (r > l){ int m=r-l; double sg=(m&1)?-1.0:1.0;
    cols[0]=l+m; vals[0]=Cpx{sg*s2,0.0};
    cols[1]=l-m; vals[1]=Cpx{s2,0.0}; return 2; }
  int m=l-r; double sg=(m&1)?-1.0:1.0;
  cols[0]=l-m; vals[0]=Cpx{0.0,s2};
  cols[1]=l+m; vals[1]=Cpx{0.0,-sg*s2}; return 2;
}

__device__ __forceinline__ Cpx uent(int l,int r,int c){
  const double s2 = 0.70710678118654752440;
  Cpx z = Cpx{0.0,0.0};
  if (r==l){ if (c==l) z = Cpx{1.0,0.0}; return z; }
  if (r>l){ int m=r-l; double sg=(m&1)?-1.0:1.0;
    if (c==l+m) z = Cpx{sg*s2,0.0}; else if (c==l-m) z = Cpx{s2,0.0}; return z; }
  int m=l-r; double sg=(m&1)?-1.0:1.0;
  if (c==l-m) z = Cpx{0.0,s2}; else if (c==l+m) z = Cpx{0.0,-sg*s2};
  return z;
}

__global__ void k_w3j(){
  int path = blockIdx.x;
  int l1=PATH_L[path][0], l2=PATH_L[path][1], l3=PATH_L[path][2];
  int d1=2*l1+1, d2=2*l2+1, d3=2*l3+1;
  int off=PATH_OFF[path];
  int total=d1*d2*d3;
  __shared__ double Cc[169];
  __shared__ double red[256];
  int tid=threadIdx.x;
  double fct[20]; fct[0]=1.0;
  for (int i=1;i<20;i++) fct[i]=fct[i-1]*(double)i;
  for (int e=tid; e<d1*d2; e+=256){
    int a=e/d2, b=e%d2;
    int m1=a-l1, m2=b-l2, m3=m1+m2;
    Cc[e] = (abs(m3)<=l3) ? dev_cg(l1,m1,l2,m2,l3,m3,fct) : 0.0;
  }
  __syncthreads();
  double tv[9]; double ss=0.0; int cnt=0;
  for (int e=tid; e<total; e+=256){
    int i=e/(d2*d3); int j=(e/d3)%d2; int k=e%d3;
    int c1[2], c2[2]; Cpx u1[2], u2[2];
    int n1 = unz(l1,i,c1,u1);
    int n2 = unz(l2,j,c2,u2);
    double re=0.0;
    for (int ii=0;ii<n1;ii++)
      for (int jj=0;jj<n2;jj++){
        int c = c1[ii]-l1 + c2[jj]-l2 + l3;
        if (c<0 || c>2*l3) continue;
        Cpx u3 = uent(l3,k,c);
        if (u3.re==0.0 && u3.im==0.0) continue;
        double cgv = Cc[c1[ii]*d2 + c2[jj]];
        if (cgv==0.0) continue;
        double pr = u1[ii].re*u2[jj].re - u1[ii].im*u2[jj].im;
        double pi = u1[ii].re*u2[jj].im + u1[ii].im*u2[jj].re;
        re += (pr*u3.re + pi*u3.im)*cgv;
      }
    tv[cnt++]=re; ss+=re*re;
  }
  red[tid]=ss; __syncthreads();
  for (int s=128;s>0;s>>=1){ if (tid<s) red[tid]+=red[tid+s]; __syncthreads(); }
  double rnorm = rsqrt(red[0]);
  cnt=0;
  for (int e=tid; e<total; e+=256) d_w3j[off+e] = (float)(tv[cnt++]*rnorm);
}

// ---------------- spherical harmonics + exp(key bias) ----------------
__global__ void k_sh(const float* __restrict__ pbw, const float* __restrict__ pbb){
  int n = blockIdx.x*256 + threadIdx.x;
  if (n>=NLR) return;
  int h=n>>6, w=n&63;
  double y = -1.0 + 2.0*(double)h/63.0;
  double x = -1.0 + 2.0*(double)w/63.0;
  double r = sqrt(x*x+y*y); if (r < 1e-8) r = 1e-8;
  double xn=x/r, yn=y/r;
  const double c0=0.28209479177387814, c2=1.0925484305920792, c20=0.31539156525252005;
  float sh[6];
  sh[0]=(float)c0;
  sh[1]=(float)(c2*xn*yn);
  sh[2]=0.0f;
  sh[3]=(float)(-c20);
  sh[4]=0.0f;
  sh[5]=(float)(0.5*c2*(xn*xn-yn*yn));
  #pragma unroll
  for (int i=0;i<6;i++) d_sh[n*6+i]=sh[i];
  for (int blk=0;blk<2;blk++){
    float b = pbb[blk];
    #pragma unroll
    for (int i=0;i<6;i++) b = fmaf(sh[i], pbw[blk*6+i], b);
    d_eb[blk*NLR+n]=expf(b);
  }
}

// ---------------- coefficient precompute ----------------
__global__ void k_coef(const float* __restrict__ liw4, const float* __restrict__ liw6,
                       const float* __restrict__ tvw,  const float* __restrict__ tow,
                       const float* __restrict__ low4, const float* __restrict__ low6){
  __shared__ float a_s[96];
  int tid = threadIdx.x;
  if (tid < 96){
    int c = tid & 7; int pp = (tid>>3)%6; int blk = tid/48;
    const float* liw = (pp==0||pp==1||pp==4) ? (liw4+blk*8) : (liw6+blk*8);
    float s=0.f;
    for (int u=0;u<8;u++) s = fmaf(liw[u], tvw[((blk*6+pp)*8+u)*8 + c], s);
    a_s[tid]=s;
  }
  __syncthreads();
  if (tid < 16){
    int q = tid&7, blk = tid>>3;
    const float* liw = (q==0||q==1||q==4||q==5)? (liw4+blk*8) : (liw6+blk*8);
    const float* low = (q<4)? (low4+blk*8) : (low6+blk*8);
    float b[8];
    #pragma unroll
    for (int v=0;v<8;v++){
      float s=0.f;
      for (int u=0;u<8;u++){
        float lu = liw[u];
        for (int w=0;w<8;w++)
          s = fmaf(lu*tow[(((blk*8+q)*8+u)*8+v)*8+w], low[w], s);
      }
      b[v]=s;
    }
    int pbase = (q&1)? 3 : 0;
    const float invs = (1.0f/sqrtf(24.0f)) * (1.0f/16.0f) * (1.0f/sqrtf(8.0f));
    for (int pp=0;pp<3;pp++){
      float s=0.f;
      #pragma unroll
      for (int v=0;v<8;v++) s = fmaf(b[v], a_s[(blk*6+pbase+pp)*8 + v], s);
      d_coef[(blk*8+q)*3+pp] = s*invs;
    }
  }
}

// ---------------- feature init ----------------
__global__ void k_featinit(const float* __restrict__ f4, const float* __restrict__ f6){
  int p = blockIdx.x*256 + threadIdx.x;
  if (p>=NPTS) return;
  #pragma unroll
  for (int i=0;i<9;i++)  d_feat0[p*22+i]   = f4[p*9+i];
  #pragma unroll
  for (int j=0;j<13;j++) d_feat0[p*22+9+j] = f6[p*13+j];
}

// ---------------- per-point prep: qT, kT, value tensors g (eb folded) -----
__global__ void __launch_bounds__(128) k_prepare(const float* __restrict__ ls4,
                                                 const float* __restrict__ ls6,
                                                 int blk, int sel){
  const float* fin = sel ? d_feat1 : d_feat0;
  __shared__ float wv[W3J_OUT_OFF];
  int tid = threadIdx.x;
  for (int i=tid;i<W3J_OUT_OFF;i+=128) wv[i]=d_w3j[i];
  __syncthreads();
  int p = blockIdx.x*128 + tid;
  float f[22];
  float s4=0.f, s6=0.f;
  #pragma unroll
  for (int i=0;i<9;i++){ f[i]=fin[p*22+i]; s4=fmaf(f[i],f[i],s4); }
  #pragma unroll
  for (int i=9;i<22;i++){ f[i]=fin[p*22+i]; s6=fmaf(f[i],f[i],s6); }
  float inv4=1.f/fmaxf(sqrtf(s4),1e-12f);
  float inv6=1.f/fmaxf(sqrtf(s6),1e-12f);
  float e4=expf(ls4[blk]), e6=expf(ls6[blk]);
  #pragma unroll
  for (int i=0;i<9;i++){ float kk=f[i]*inv4; d_kvT[i*NPTS+p]=kk; d_qvT[i*NPTS+p]=kk*e4; }
  #pragma unroll
  for (int i=9;i<22;i++){ float kk=f[i]*inv6; d_kvT[i*NPTS+p]=kk; d_qvT[i*NPTS+p]=kk*e6; }
  int n = p & (NLR-1);
  float ebv = d_eb[blk*NLR+n];
  float sh0=d_sh[n*6];
  float sh2[5];
  #pragma unroll
  for (int j=0;j<5;j++) sh2[j]=d_sh[n*6+1+j];
  float* g = d_gv + p*68;
  { float a[9];
    #pragma unroll
    for (int k=0;k<9;k++) a[k]=0.f;
    #pragma unroll 1
    for (int i=0;i<9;i++){ float fi=f[i];
      #pragma unroll
      for (int k=0;k<9;k++) a[k]=fmaf(fi,wv[i*9+k],a[k]); }
    #pragma unroll
    for (int k=0;k<9;k++) g[k]=a[k]*sh0*ebv; }
  { float a[9];
    #pragma unroll
    for (int k=0;k<9;k++) a[k]=0.f;
    #pragma unroll 1
    for (int i=0;i<9;i++){ float fi=f[i];
      #pragma unroll 1
      for (int j=0;j<5;j++){ float c=fi*sh2[j];
        #pragma unroll
        for (int k=0;k<9;k++) a[k]=fmaf(c,wv[81+(i*5+j)*9+k],a[k]); } }
    #pragma unroll
    for (int k=0;k<9;k++) g[9+k]=a[k]*ebv; }
  { float a[9];
    #pragma unroll
    for (int k=0;k<9;k++) a[k]=0.f;
    #pragma unroll 1
    for (int i=0;i<13;i++){ float fi=f[9+i];
      #pragma unroll 1
      for (int j=0;j<5;j++){ float c=fi*sh2[j];
        #pragma unroll
        for (int k=0;k<9;k++) a[k]=fmaf(c,wv[486+(i*5+j)*9+k],a[k]); } }
    #pragma unroll
    for (int k=0;k<9;k++) g[18+k]=a[k]*ebv; }
  { float a[13];
    #pragma unroll
    for (int k=0;k<13;k++) a[k]=0.f;
    #pragma unroll 1
    for (int i=0;i<13;i++){ float fi=f[9+i];
      #pragma unroll
      for (int k=0;k<13;k++) a[k]=fmaf(fi,wv[1071+i*13+k],a[k]); }
    #pragma unroll
    for (int k=0;k<13;k++) g[27+k]=a[k]*sh0*ebv; }
  { float a[13];
    #pragma unroll
    for (int k=0;k<13;k++) a[k]=0.f;
    #pragma unroll 1
    for (int i=0;i<9;i++){ float fi=f[i];
      #pragma unroll 1
      for (int j=0;j<5;j++){ float c=fi*sh2[j];
        #pragma unroll
        for (int k=0;k<13;k++) a[k]=fmaf(c,wv[1240+(i*5+j)*13+k],a[k]); } }
    #pragma unroll
    for (int k=0;k<13;k++) g[40+k]=a[k]*ebv; }
  { float a[13];
    #pragma unroll
    for (int k=0;k<13;k++) a[k]=0.f;
    #pragma unroll 1
    for (int i=0;i<13;i++){ float fi=f[9+i];
      #pragma unroll 1
      for (int j=0;j<5;j++){ float c=fi*sh2[j];
        #pragma unroll
        for (int k=0;k<13;k++) a[k]=fmaf(c,wv[1825+(i*5+j)*13+k],a[k]); } }
    #pragma unroll
    for (int k=0;k<13;k++) g[53+k]=a[k]*ebv; }
  g[66]=ebv; g[67]=0.f;
}

// ---------------- tiled attention (static smem, KT=32, f32x2) ----------------
// Phase A: S = Q K^T (K=22), thread tile 4 rows x 4 keys (key-paired FFMA2)
// Phase B: acc += W^T G, thread tile 8 rows x 4 cols (row-paired FFMA2, G dup)
__global__ void __launch_bounds__(288,2) k_attn(){
  __shared__ float Qs [22*RT];    // 2816 f
  __shared__ float Ks [22*KT];    // 704 f
  __shared__ float Gs2[KT*136];   // 4352 f (columns duplicated: (g,g) pairs)
  __shared__ float Ws [KT*RT];    // 4096 f
  const int tid = threadIdx.x;
  const int batch = blockIdx.y, split = blockIdx.z;
  const int prow = batch*NLR + blockIdx.x*RT;

  for (int i=tid;i<22*RT;i+=288) Qs[i] = d_qvT[(i>>7)*NPTS + prow + (i&127)];

  const int rgA = tid & 31, kgA = tid >> 5;   // phase A: 4 rows x 4 keys
  const int rgB = tid & 15, cgB = tid >> 4;   // phase B: 8 rows x 4 cols
  unsigned long long acc2[16];
  #pragma unroll
  for (int i=0;i<16;i++) acc2[i]=0ull;

  const int m0 = split*(NLR/SPLITS);
  for (int t=0;t<(NLR/SPLITS)/KT;t++){
    const int mbase = batch*NLR + m0 + t*KT;
    __syncthreads();
    for (int i=tid;i<22*KT;i+=288) Ks[i] = d_kvT[(i>>5)*NPTS + mbase + (i&31)];
    for (int i=tid;i<KT*34;i+=288){
      int key=i/34, c2=i-key*34;
      float2 v = *(const float2*)(d_gv + (size_t)(mbase+key)*68 + c2*2);
      *(float4*)(Gs2 + key*136 + c2*4) = make_float4(v.x,v.x,v.y,v.y);
    }
    __syncthreads();
    if (tid < 256){
      unsigned long long s2[8];   // [key-pair][row]
      #pragma unroll
      for (int i=0;i<8;i++) s2[i]=0ull;
      #pragma unroll 2
      for (int kk=0;kk<22;kk++){
        float4 q4 = *(const float4*)(Qs + kk*RT + rgA*4);
        ulonglong2 k2 = *(const ulonglong2*)(Ks + kk*KT + kgA*4);
        unsigned long long qd0 = pack2(q4.x,q4.x);
        unsigned long long qd1 = pack2(q4.y,q4.y);
        unsigned long long qd2 = pack2(q4.z,q4.z);
        unsigned long long qd3 = pack2(q4.w,q4.w);
        s2[0]=fma2(k2.x,qd0,s2[0]); s2[1]=fma2(k2.x,qd1,s2[1]);
        s2[2]=fma2(k2.x,qd2,s2[2]); s2[3]=fma2(k2.x,qd3,s2[3]);
        s2[4]=fma2(k2.y,qd0,s2[4]); s2[5]=fma2(k2.y,qd1,s2[5]);
        s2[6]=fma2(k2.y,qd2,s2[6]); s2[7]=fma2(k2.y,qd3,s2[7]);
      }
      float sv[4][4];   // [key][row]
      #pragma unroll
      for (int kp=0;kp<2;kp++)
        #pragma unroll
        for (int r=0;r<4;r++)
          unpack2(s2[kp*4+r], sv[2*kp][r], sv[2*kp+1][r]);
      #pragma unroll
      for (int j=0;j<4;j++){
        float4 w;
        w.x = __expf(sv[j][0]);
        w.y = __expf(sv[j][1]);
        w.z = __expf(sv[j][2]);
        w.w = __expf(sv[j][3]);
        *(float4*)(Ws + (kgA*4+j)*RT + rgA*4) = w;
      }
    }
    __syncthreads();
    if (cgB < 17){
      #pragma unroll 2
      for (int key=0;key<KT;key++){
        ulonglong2 wa = *(const ulonglong2*)(Ws + key*RT + rgB*8);
        ulonglong2 wb = *(const ulonglong2*)(Ws + key*RT + rgB*8 + 4);
        ulonglong2 ga = *(const ulonglong2*)(Gs2 + key*136 + cgB*8);
        ulonglong2 gb = *(const ulonglong2*)(Gs2 + key*136 + cgB*8 + 4);
        acc2[0*4+0]=fma2(wa.x,ga.x,acc2[0*4+0]);
        acc2[0*4+1]=fma2(wa.y,ga.x,acc2[0*4+1]);
        acc2[0*4+2]=fma2(wb.x,ga.x,acc2[0*4+2]);
        acc2[0*4+3]=fma2(wb.y,ga.x,acc2[0*4+3]);
        acc2[1*4+0]=fma2(wa.x,ga.y,acc2[1*4+0]);
        acc2[1*4+1]=fma2(wa.y,ga.y,acc2[1*4+1]);
        acc2[1*4+2]=fma2(wb.x,ga.y,acc2[1*4+2]);
        acc2[1*4+3]=fma2(wb.y,ga.y,acc2[1*4+3]);
        acc2[2*4+0]=fma2(wa.x,gb.x,acc2[2*4+0]);
        acc2[2*4+1]=fma2(wa.y,gb.x,acc2[2*4+1]);
        acc2[2*4+2]=fma2(wb.x,gb.x,acc2[2*4+2]);
        acc2[2*4+3]=fma2(wb.y,gb.x,acc2[2*4+3]);
        acc2[3*4+0]=fma2(wa.x,gb.y,acc2[3*4+0]);
        acc2[3*4+1]=fma2(wa.y,gb.y,acc2[3*4+1]);
        acc2[3*4+2]=fma2(wb.x,gb.y,acc2[3*4+2]);
        acc2[3*4+3]=fma2(wb.y,gb.y,acc2[3*4+3]);
      }
    }
  }
  if (cgB < 17){
    #pragma unroll
    for (int rp=0;rp<4;rp++){
      float lo[4], hi[4];
      #pragma unroll
      for (int c=0;c<4;c++) unpack2(acc2[c*4+rp], lo[c], hi[c]);
      int p = prow + rgB*8 + rp*2;
      *(float4*)(d_part + ((size_t)split*NPTS + p)*68 + cgB*4) =
        make_float4(lo[0],lo[1],lo[2],lo[3]);
      *(float4*)(d_part + ((size_t)split*NPTS + p + 1)*68 + cgB*4) =
        make_float4(hi[0],hi[1],hi[2],hi[3]);
    }
  }
}

// ---------------- split reduce + transpose to [c][p] ----------------
__global__ void k_reduce(){
  int p = blockIdx.x*128 + threadIdx.x;
  if (p>=NPTS) return;
  float accv[68];
  #pragma unroll
  for (int i=0;i<68;i++) accv[i]=0.f;
  #pragma unroll
  for (int sp=0;sp<SPLITS;sp++){
    const float4* b = (const float4*)(d_part + ((size_t)sp*NPTS+p)*68);
    #pragma unroll
    for (int i=0;i<17;i++){
      float4 v=b[i];
      accv[i*4+0]+=v.x; accv[i*4+1]+=v.y; accv[i*4+2]+=v.z; accv[i*4+3]+=v.w;
    }
  }
  float inv = 1.f/accv[66];
  #pragma unroll 1
  for (int c=0;c<66;c++) d_G[c*NPTS+p] = accv[c]*inv;
}

// ---------------- per-point output tensor products ----------------
template<int D1,int D2,int D3>
__device__ __forceinline__ void qpath(const float* __restrict__ w3, const float* __restrict__ f,
                                      int p, float c0, float c1, float c2,
                                      int g0, int g1, int g2, float* out){
  #pragma unroll 1
  for (int j=0;j<D2;j++){
    float gm = c0*d_G[(g0+j)*NPTS+p] + c1*d_G[(g1+j)*NPTS+p] + c2*d_G[(g2+j)*NPTS+p];
    #pragma unroll
    for (int i=0;i<D1;i++){
      float cf = gm*f[i];
      #pragma unroll
      for (int k=0;k<D3;k++) out[k] = fmaf(cf, w3[(i*D2+j)*D3+k], out[k]);
    }
  }
}

__global__ void __launch_bounds__(256) k_output(int blk, int sel){
  const float* fin = sel ? d_feat1 : d_feat0;
  float* fout = sel ? d_feat0 : d_feat1;
  __shared__ float w3s[6292];
  int tid = threadIdx.x;
  int half = blockIdx.y;
  int base = half ? 7026 : 2670;
  int len  = half ? 6292 : 4356;
  for (int i=tid;i<len;i+=256) w3s[i]=d_w3j[base+i];
  __syncthreads();
  int p = blockIdx.x*256 + tid;
  float f4[9], f6[13];
  #pragma unroll
  for (int i=0;i<9;i++) f4[i]=fin[p*22+i];
  #pragma unroll
  for (int i=0;i<13;i++) f6[i]=fin[p*22+9+i];
  const float* cf = d_coef + blk*24;
  if (half==0){
    float d4[9];
    #pragma unroll
    for (int k=0;k<9;k++) d4[k]=0.f;
    qpath<9,9,9>   (w3s+0,    f4, p, cf[0], cf[1], cf[2],  0, 9,18, d4);
    qpath<9,13,9>  (w3s+729,  f4, p, cf[3], cf[4], cf[5], 27,40,53, d4);
    qpath<13,9,9>  (w3s+1782, f6, p, cf[6], cf[7], cf[8],  0, 9,18, d4);
    qpath<13,13,9> (w3s+2835, f6, p, cf[9], cf[10],cf[11],27,40,53, d4);
    #pragma unroll
    for (int k=0;k<9;k++) fout[p*22+k] = f4[k]+d4[k];
  } else {
    float d6[13];
    #pragma unroll
    for (int k=0;k<13;k++) d6[k]=0.f;
    qpath<9,9,13>  (w3s+0,    f4, p, cf[12],cf[13],cf[14], 0, 9,18, d6);
    qpath<9,13,13> (w3s+1053, f4, p, cf[15],cf[16],cf[17],27,40,53, d6);
    qpath<13,9,13> (w3s+2574, f6, p, cf[18],cf[19],cf[20], 0, 9,18, d6);
    qpath<13,13,13>(w3s+4095, f6, p, cf[21],cf[22],cf[23],27,40,53, d6);
    #pragma unroll
    for (int k=0;k<13;k++) fout[p*22+9+k] = f6[k]+d6[k];
  }
}

// ---------------- upsample ----------------
__global__ void k_upsample(const float* __restrict__ upw, float* __restrict__ out){
  int idx = blockIdx.x*256 + threadIdx.x;
  if (idx >= NBATCH*65536) return;
  int b = idx >> 16;
  int nh = idx & 65535;
  int rw = nh & 3; int t = nh >> 2; int w = t & 63; t >>= 6; int rh = t & 3; int h = t >> 2;
  int p = b*NLR + h*64 + w;
  float u4 = upw[(rh*4+rw)*2 + 0];
  float u6 = upw[(rh*4+rw)*2 + 1];
  float* o4 = out + (size_t)idx*9;
  float* o6 = out + 1179648 + (size_t)idx*13;
  #pragma unroll
  for (int k=0;k<9;k++)  o4[k] = d_feat0[p*22+k]*u4;
  #pragma unroll
  for (int k=0;k<13;k++) o6[k] = d_feat0[p*22+9+k]*u6;
}

extern "C" void kernel_launch(void* const* d_in, const int* in_sizes, int n_in,
                              void* d_out, int out_size) {
  const float* f4   = (const float*)d_in[0];
  const float* f6   = (const float*)d_in[1];
  const float* ls4  = (const float*)d_in[2];
  const float* ls6  = (const float*)d_in[3];
  const float* pbw  = (const float*)d_in[4];
  const float* pbb  = (const float*)d_in[5];
  const float* liw4 = (const float*)d_in[6];
  const float* liw6 = (const float*)d_in[7];
  const float* tvw  = (const float*)d_in[8];
  const float* tow  = (const float*)d_in[9];
  const float* low4 = (const float*)d_in[10];
  const float* low6 = (const float*)d_in[11];
  const float* upw  = (const float*)d_in[12];
  float* out = (float*)d_out;

  k_w3j<<<14,256>>>();
  k_sh<<<16,256>>>(pbw, pbb);
  k_coef<<<1,128>>>(liw4, liw6, tvw, tow, low4, low6);
  k_featinit<<<32,256>>>(f4, f6);
  for (int blk=0; blk<2; blk++){
    k_prepare<<<64,128>>>(ls4, ls6, blk, blk&1);
    k_attn<<<dim3(NLR/RT, NBATCH, SPLITS), 288>>>();
    k_reduce<<<NPTS/128,128>>>();
    k_output<<<dim3(32,2),256>>>(blk, blk&1);
  }
  k_upsample<<<512,256>>>(upw, out);
}

// round 8
// speedup vs baseline: 1.1977x; 1.1977x over previous
#include <cuda_runtime.h>
#include <cuda_bf16.h>
#include <math.h>

#define NBATCH 2
#define NLR    4096
#define NPTS   (NBATCH*NLR)
#define SPLITS 16
#define KT     32
#define RT     128

#define W3J_TOTAL   13318
#define W3J_OUT_OFF 2670

__device__ float d_feat0[NPTS*22];
__device__ float d_feat1[NPTS*22];
__device__ float d_qvT[22*NPTS];
__device__ float d_kvT[22*NPTS];
__device__ __align__(16) float d_gv  [NPTS*68];
__device__ __align__(16) float d_part[SPLITS*NPTS*68];
__device__ float d_G   [66*NPTS];
__device__ float d_sh  [NLR*6];
__device__ float d_eb  [2*NLR];
__device__ float d_w3j [W3J_TOTAL];
__device__ float d_coef[2*8*3];

__constant__ int PATH_L[14][3] = {
  {4,0,4},{4,2,4},{6,2,4},{6,0,6},{4,2,6},{6,2,6},
  {4,4,4},{4,6,4},{6,4,4},{6,6,4},{4,4,6},{4,6,6},{6,4,6},{6,6,6}};
__constant__ int PATH_OFF[15] = {
  0,81,486,1071,1240,1825,2670,3399,4452,5505,7026,8079,9600,11121,13318};

// ---------------- W3J (real Wigner/CG) ----------------
struct Cpx { double re, im; };

__device__ __forceinline__ double dev_cg(int j1,int m1,int j2,int m2,int j3,int m3,const double* f){
  if (m1+m2 != m3) return 0.0;
  if (j3 < abs(j1-j2) || j3 > j1+j2) return 0.0;
  double pref = sqrt((2.0*j3+1.0)*f[j3+j1-j2]*f[j3-j1+j2]*f[j1+j2-j3]/f[j1+j2+j3+1]);
  pref *= sqrt(f[j3+m3]*f[j3-m3]*f[j1-m1]*f[j1+m1]*f[j2-m2]*f[j2+m2]);
  double s = 0.0;
  int kmax = j1+j2-j3;
  for (int k=0;k<=kmax;k++){
    int a3=j1-m1-k, a4=j2+m2-k, a5=j3-j2+m1+k, a6=j3-j1-m2+k;
    if (a3<0||a4<0||a5<0||a6<0) continue;
    double t = 1.0/(f[k]*f[kmax-k]*f[a3]*f[a4]*f[a5]*f[a6]);
    s += (k&1)? -t : t;
  }
  return pref*s;
}

__device__ __forceinline__ int unz(int l, int r, int* cols, Cpx* vals){
  const double s2 = 0.70710678118654752440;
  if (r == l){ cols[0]=l; vals[0]=Cpx{1.0,0.0}; return 1; }
  if (r > l){ int m=r-l; double sg=(m&1)?-1.0:1.0;
    cols[0]=l+m; vals[0]=Cpx{sg*s2,0.0};
    cols[1]=l-m; vals[1]=Cpx{s2,0.0}; return 2; }
  int m=l-r; double sg=(m&1)?-1.0:1.0;
  cols[0]=l-m; vals[0]=Cpx{0.0,s2};
  cols[1]=l+m; vals[1]=Cpx{0.0,-sg*s2}; return 2;
}

__device__ __forceinline__ Cpx uent(int l,int r,int c){
  const double s2 = 0.70710678118654752440;
  Cpx z = Cpx{0.0,0.0};
  if (r==l){ if (c==l) z = Cpx{1.0,0.0}; return z; }
  if (r>l){ int m=r-l; double sg=(m&1)?-1.0:1.0;
    if (c==l+m) z = Cpx{sg*s2,0.0}; else if (c==l-m) z = Cpx{s2,0.0}; return z; }
  int m=l-r; double sg=(m&1)?-1.0:1.0;
  if (c==l-m) z = Cpx{0.0,s2}; else if (c==l+m) z = Cpx{0.0,-sg*s2};
  return z;
}

__global__ void k_w3j(){
  int path = blockIdx.x;
  int l1=PATH_L[path][0], l2=PATH_L[path][1], l3=PATH_L[path][2];
  int d1=2*l1+1, d2=2*l2+1, d3=2*l3+1;
  int off=PATH_OFF[path];
  int total=d1*d2*d3;
  __shared__ double Cc[169];
  __shared__ double red[256];
  int tid=threadIdx.x;
  double fct[20]; fct[0]=1.0;
  for (int i=1;i<20;i++) fct[i]=fct[i-1]*(double)i;
  for (int e=tid; e<d1*d2; e+=256){
    int a=e/d2, b=e%d2;
    int m1=a-l1, m2=b-l2, m3=m1+m2;
    Cc[e] = (abs(m3)<=l3) ? dev_cg(l1,m1,l2,m2,l3,m3,fct) : 0.0;
  }
  __syncthreads();
  double tv[9]; double ss=0.0; int cnt=0;
  for (int e=tid; e<total; e+=256){
    int i=e/(d2*d3); int j=(e/d3)%d2; int k=e%d3;
    int c1[2], c2[2]; Cpx u1[2], u2[2];
    int n1 = unz(l1,i,c1,u1);
    int n2 = unz(l2,j,c2,u2);
    double re=0.0;
    for (int ii=0;ii<n1;ii++)
      for (int jj=0;jj<n2;jj++){
        int c = c1[ii]-l1 + c2[jj]-l2 + l3;
        if (c<0 || c>2*l3) continue;
        Cpx u3 = uent(l3,k,c);
        if (u3.re==0.0 && u3.im==0.0) continue;
        double cgv = Cc[c1[ii]*d2 + c2[jj]];
        if (cgv==0.0) continue;
        double pr = u1[ii].re*u2[jj].re - u1[ii].im*u2[jj].im;
        double pi = u1[ii].re*u2[jj].im + u1[ii].im*u2[jj].re;
        re += (pr*u3.re + pi*u3.im)*cgv;
      }
    tv[cnt++]=re; ss+=re*re;
  }
  red[tid]=ss; __syncthreads();
  for (int s=128;s>0;s>>=1){ if (tid<s) red[tid]+=red[tid+s]; __syncthreads(); }
  double rnorm = rsqrt(red[0]);
  cnt=0;
  for (int e=tid; e<total; e+=256) d_w3j[off+e] = (float)(tv[cnt++]*rnorm);
}

// ---------------- spherical harmonics + exp(key bias) ----------------
__global__ void k_sh(const float* __restrict__ pbw, const float* __restrict__ pbb){
  int n = blockIdx.x*256 + threadIdx.x;
  if (n>=NLR) return;
  int h=n>>6, w=n&63;
  double y = -1.0 + 2.0*(double)h/63.0;
  double x = -1.0 + 2.0*(double)w/63.0;
  double r = sqrt(x*x+y*y); if (r < 1e-8) r = 1e-8;
  double xn=x/r, yn=y/r;
  const double c0=0.28209479177387814, c2=1.0925484305920792, c20=0.31539156525252005;
  float sh[6];
  sh[0]=(float)c0;
  sh[1]=(float)(c2*xn*yn);
  sh[2]=0.0f;
  sh[3]=(float)(-c20);
  sh[4]=0.0f;
  sh[5]=(float)(0.5*c2*(xn*xn-yn*yn));
  #pragma unroll
  for (int i=0;i<6;i++) d_sh[n*6+i]=sh[i];
  for (int blk=0;blk<2;blk++){
    float b = pbb[blk];
    #pragma unroll
    for (int i=0;i<6;i++) b = fmaf(sh[i], pbw[blk*6+i], b);
    d_eb[blk*NLR+n]=expf(b);
  }
}

// ---------------- coefficient precompute ----------------
__global__ void k_coef(const float* __restrict__ liw4, const float* __restrict__ liw6,
                       const float* __restrict__ tvw,  const float* __restrict__ tow,
                       const float* __restrict__ low4, const float* __restrict__ low6){
  __shared__ float a_s[96];
  int tid = threadIdx.x;
  if (tid < 96){
    int c = tid & 7; int pp = (tid>>3)%6; int blk = tid/48;
    const float* liw = (pp==0||pp==1||pp==4) ? (liw4+blk*8) : (liw6+blk*8);
    float s=0.f;
    for (int u=0;u<8;u++) s = fmaf(liw[u], tvw[((blk*6+pp)*8+u)*8 + c], s);
    a_s[tid]=s;
  }
  __syncthreads();
  if (tid < 16){
    int q = tid&7, blk = tid>>3;
    const float* liw = (q==0||q==1||q==4||q==5)? (liw4+blk*8) : (liw6+blk*8);
    const float* low = (q<4)? (low4+blk*8) : (low6+blk*8);
    float b[8];
    #pragma unroll
    for (int v=0;v<8;v++){
      float s=0.f;
      for (int u=0;u<8;u++){
        float lu = liw[u];
        for (int w=0;w<8;w++)
          s = fmaf(lu*tow[(((blk*8+q)*8+u)*8+v)*8+w], low[w], s);
      }
      b[v]=s;
    }
    int pbase = (q&1)? 3 : 0;
    const float invs = (1.0f/sqrtf(24.0f)) * (1.0f/16.0f) * (1.0f/sqrtf(8.0f));
    for (int pp=0;pp<3;pp++){
      float s=0.f;
      #pragma unroll
      for (int v=0;v<8;v++) s = fmaf(b[v], a_s[(blk*6+pbase+pp)*8 + v], s);
      d_coef[(blk*8+q)*3+pp] = s*invs;
    }
  }
}

// ---------------- feature init ----------------
__global__ void k_featinit(const float* __restrict__ f4, const float* __restrict__ f6){
  int p = blockIdx.x*256 + threadIdx.x;
  if (p>=NPTS) return;
  #pragma unroll
  for (int i=0;i<9;i++)  d_feat0[p*22+i]   = f4[p*9+i];
  #pragma unroll
  for (int j=0;j<13;j++) d_feat0[p*22+9+j] = f6[p*13+j];
}

// ---------------- per-point prep: qT, kT, value tensors g (eb folded) -----
__global__ void __launch_bounds__(128) k_prepare(const float* __restrict__ ls4,
                                                 const float* __restrict__ ls6,
                                                 int blk, int sel){
  const float* fin = sel ? d_feat1 : d_feat0;
  __shared__ float wv[W3J_OUT_OFF];
  int tid = threadIdx.x;
  for (int i=tid;i<W3J_OUT_OFF;i+=128) wv[i]=d_w3j[i];
  __syncthreads();
  int p = blockIdx.x*128 + tid;
  float f[22];
  float s4=0.f, s6=0.f;
  #pragma unroll
  for (int i=0;i<9;i++){ f[i]=fin[p*22+i]; s4=fmaf(f[i],f[i],s4); }
  #pragma unroll
  for (int i=9;i<22;i++){ f[i]=fin[p*22+i]; s6=fmaf(f[i],f[i],s6); }
  float inv4=1.f/fmaxf(sqrtf(s4),1e-12f);
  float inv6=1.f/fmaxf(sqrtf(s6),1e-12f);
  float e4=expf(ls4[blk]), e6=expf(ls6[blk]);
  #pragma unroll
  for (int i=0;i<9;i++){ float kk=f[i]*inv4; d_kvT[i*NPTS+p]=kk; d_qvT[i*NPTS+p]=kk*e4; }
  #pragma unroll
  for (int i=9;i<22;i++){ float kk=f[i]*inv6; d_kvT[i*NPTS+p]=kk; d_qvT[i*NPTS+p]=kk*e6; }
  int n = p & (NLR-1);
  float ebv = d_eb[blk*NLR+n];
  float sh0=d_sh[n*6];
  float sh2[5];
  #pragma unroll
  for (int j=0;j<5;j++) sh2[j]=d_sh[n*6+1+j];
  float* g = d_gv + p*68;
  { float a[9];
    #pragma unroll
    for (int k=0;k<9;k++) a[k]=0.f;
    #pragma unroll 1
    for (int i=0;i<9;i++){ float fi=f[i];
      #pragma unroll
      for (int k=0;k<9;k++) a[k]=fmaf(fi,wv[i*9+k],a[k]); }
    #pragma unroll
    for (int k=0;k<9;k++) g[k]=a[k]*sh0*ebv; }
  { float a[9];
    #pragma unroll
    for (int k=0;k<9;k++) a[k]=0.f;
    #pragma unroll 1
    for (int i=0;i<9;i++){ float fi=f[i];
      #pragma unroll 1
      for (int j=0;j<5;j++){ float c=fi*sh2[j];
        #pragma unroll
        for (int k=0;k<9;k++) a[k]=fmaf(c,wv[81+(i*5+j)*9+k],a[k]); } }
    #pragma unroll
    for (int k=0;k<9;k++) g[9+k]=a[k]*ebv; }
  { float a[9];
    #pragma unroll
    for (int k=0;k<9;k++) a[k]=0.f;
    #pragma unroll 1
    for (int i=0;i<13;i++){ float fi=f[9+i];
      #pragma unroll 1
      for (int j=0;j<5;j++){ float c=fi*sh2[j];
        #pragma unroll
        for (int k=0;k<9;k++) a[k]=fmaf(c,wv[486+(i*5+j)*9+k],a[k]); } }
    #pragma unroll
    for (int k=0;k<9;k++) g[18+k]=a[k]*ebv; }
  { float a[13];
    #pragma unroll
    for (int k=0;k<13;k++) a[k]=0.f;
    #pragma unroll 1
    for (int i=0;i<13;i++){ float fi=f[9+i];
      #pragma unroll
      for (int k=0;k<13;k++) a[k]=fmaf(fi,wv[1071+i*13+k],a[k]); }
    #pragma unroll
    for (int k=0;k<13;k++) g[27+k]=a[k]*sh0*ebv; }
  { float a[13];
    #pragma unroll
    for (int k=0;k<13;k++) a[k]=0.f;
    #pragma unroll 1
    for (int i=0;i<9;i++){ float fi=f[i];
      #pragma unroll 1
      for (int j=0;j<5;j++){ float c=fi*sh2[j];
        #pragma unroll
        for (int k=0;k<13;k++) a[k]=fmaf(c,wv[1240+(i*5+j)*13+k],a[k]); } }
    #pragma unroll
    for (int k=0;k<13;k++) g[40+k]=a[k]*ebv; }
  { float a[13];
    #pragma unroll
    for (int k=0;k<13;k++) a[k]=0.f;
    #pragma unroll 1
    for (int i=0;i<13;i++){ float fi=f[9+i];
      #pragma unroll 1
      for (int j=0;j<5;j++){ float c=fi*sh2[j];
        #pragma unroll
        for (int k=0;k<13;k++) a[k]=fmaf(c,wv[1825+(i*5+j)*13+k],a[k]); } }
    #pragma unroll
    for (int k=0;k<13;k++) g[53+k]=a[k]*ebv; }
  g[66]=ebv; g[67]=0.f;
}

// ---------------- tiled attention (static smem, KT=32, scalar, occ 3) -----
// Phase A: S = Q K^T (K=22), thread tile 4 rows x 4 keys -> exp -> Ws[key][row]
// Phase B: acc += W^T G, thread tile 8 rows x 4 cols
__global__ void __launch_bounds__(288,3) k_attn(){
  __shared__ float Qs[22*RT];   // 2816 f
  __shared__ float Ks[22*KT];   // 704 f
  __shared__ float Gs[KT*68];   // 2176 f
  __shared__ float Ws[KT*RT];   // 4096 f
  const int tid = threadIdx.x;
  const int batch = blockIdx.y, split = blockIdx.z;
  const int prow = batch*NLR + blockIdx.x*RT;

  for (int i=tid;i<22*RT;i+=288) Qs[i] = d_qvT[(i>>7)*NPTS + prow + (i&127)];

  const int rgA = tid & 31, kgA = tid >> 5;   // phase A: 4 rows x 4 keys
  const int rgB = tid & 15, cgB = tid >> 4;   // phase B: 8 rows x 4 cols
  float acc[32];
  #pragma unroll
  for (int i=0;i<32;i++) acc[i]=0.f;

  const int m0 = split*(NLR/SPLITS);
  for (int t=0;t<(NLR/SPLITS)/KT;t++){
    const int mbase = batch*NLR + m0 + t*KT;
    __syncthreads();
    for (int i=tid;i<22*KT;i+=288) Ks[i] = d_kvT[(i>>5)*NPTS + mbase + (i&31)];
    { const float4* src = (const float4*)(d_gv) + (size_t)mbase*17;
      float4* dst = (float4*)Gs;
      for (int i=tid;i<KT*17;i+=288) dst[i]=src[i]; }
    __syncthreads();
    if (tid < 256){
      float s[16];
      #pragma unroll
      for (int i=0;i<16;i++) s[i]=0.f;
      #pragma unroll 2
      for (int kk=0;kk<22;kk++){
        float4 q4 = *(const float4*)(Qs + kk*RT + rgA*4);
        float4 k4 = *(const float4*)(Ks + kk*KT + kgA*4);
        #pragma unroll
        for (int r=0;r<4;r++){
          float qv = (r==0)?q4.x:(r==1)?q4.y:(r==2)?q4.z:q4.w;
          s[0*4+r]=fmaf(qv,k4.x,s[0*4+r]);
          s[1*4+r]=fmaf(qv,k4.y,s[1*4+r]);
          s[2*4+r]=fmaf(qv,k4.z,s[2*4+r]);
          s[3*4+r]=fmaf(qv,k4.w,s[3*4+r]);
        }
      }
      #pragma unroll
      for (int j=0;j<4;j++){
        float4 w;
        w.x = __expf(s[j*4+0]);
        w.y = __expf(s[j*4+1]);
        w.z = __expf(s[j*4+2]);
        w.w = __expf(s[j*4+3]);
        *(float4*)(Ws + (kgA*4+j)*RT + rgA*4) = w;
      }
    }
    __syncthreads();
    if (cgB < 17){
      #pragma unroll 2
      for (int key=0;key<KT;key++){
        float4 wa = *(const float4*)(Ws + key*RT + rgB*8);
        float4 wb = *(const float4*)(Ws + key*RT + rgB*8 + 4);
        float4 g4 = *(const float4*)(Gs + key*68 + cgB*4);
        #pragma unroll
        for (int r=0;r<8;r++){
          float wv = (r==0)?wa.x:(r==1)?wa.y:(r==2)?wa.z:(r==3)?wa.w:
                     (r==4)?wb.x:(r==5)?wb.y:(r==6)?wb.z:wb.w;
          acc[r*4+0]=fmaf(wv,g4.x,acc[r*4+0]);
          acc[r*4+1]=fmaf(wv,g4.y,acc[r*4+1]);
          acc[r*4+2]=fmaf(wv,g4.z,acc[r*4+2]);
          acc[r*4+3]=fmaf(wv,g4.w,acc[r*4+3]);
        }
      }
    }
  }
  if (cgB < 17){
    #pragma unroll
    for (int r=0;r<8;r++){
      int p = prow + rgB*8 + r;
      *(float4*)(d_part + ((size_t)split*NPTS + p)*68 + cgB*4) =
        make_float4(acc[r*4],acc[r*4+1],acc[r*4+2],acc[r*4+3]);
    }
  }
}

// ---------------- split reduce + transpose to [c][p] ----------------
__global__ void k_reduce(){
  int p = blockIdx.x*128 + threadIdx.x;
  if (p>=NPTS) return;
  float accv[68];
  #pragma unroll
  for (int i=0;i<68;i++) accv[i]=0.f;
  #pragma unroll 4
  for (int sp=0;sp<SPLITS;sp++){
    const float4* b = (const float4*)(d_part + ((size_t)sp*NPTS+p)*68);
    #pragma unroll
    for (int i=0;i<17;i++){
      float4 v=b[i];
      accv[i*4+0]+=v.x; accv[i*4+1]+=v.y; accv[i*4+2]+=v.z; accv[i*4+3]+=v.w;
    }
  }
  float inv = 1.f/accv[66];
  #pragma unroll 1
  for (int c=0;c<66;c++) d_G[c*NPTS+p] = accv[c]*inv;
}

// ---------------- per-point output tensor products ----------------
template<int D1,int D2,int D3>
__device__ __forceinline__ void qpath(const float* __restrict__ w3, const float* __restrict__ f,
                                      int p, float c0, float c1, float c2,
                                      int g0, int g1, int g2, float* out){
  #pragma unroll 1
  for (int j=0;j<D2;j++){
    float gm = c0*d_G[(g0+j)*NPTS+p] + c1*d_G[(g1+j)*NPTS+p] + c2*d_G[(g2+j)*NPTS+p];
    #pragma unroll
    for (int i=0;i<D1;i++){
      float cf = gm*f[i];
      #pragma unroll
      for (int k=0;k<D3;k++) out[k] = fmaf(cf, w3[(i*D2+j)*D3+k], out[k]);
    }
  }
}

__global__ void __launch_bounds__(256) k_output(int blk, int sel){
  const float* fin = sel ? d_feat1 : d_feat0;
  float* fout = sel ? d_feat0 : d_feat1;
  __shared__ float w3s[6292];
  int tid = threadIdx.x;
  int half = blockIdx.y;
  int base = half ? 7026 : 2670;
  int len  = half ? 6292 : 4356;
  for (int i=tid;i<len;i+=256) w3s[i]=d_w3j[base+i];
  __syncthreads();
  int p = blockIdx.x*256 + tid;
  float f4[9], f6[13];
  #pragma unroll
  for (int i=0;i<9;i++) f4[i]=fin[p*22+i];
  #pragma unroll
  for (int i=0;i<13;i++) f6[i]=fin[p*22+9+i];
  const float* cf = d_coef + blk*24;
  if (half==0){
    float d4[9];
    #pragma unroll
    for (int k=0;k<9;k++) d4[k]=0.f;
    qpath<9,9,9>   (w3s+0,    f4, p, cf[0], cf[1], cf[2],  0, 9,18, d4);
    qpath<9,13,9>  (w3s+729,  f4, p, cf[3], cf[4], cf[5], 27,40,53, d4);
    qpath<13,9,9>  (w3s+1782, f6, p, cf[6], cf[7], cf[8],  0, 9,18, d4);
    qpath<13,13,9> (w3s+2835, f6, p, cf[9], cf[10],cf[11],27,40,53, d4);
    #pragma unroll
    for (int k=0;k<9;k++) fout[p*22+k] = f4[k]+d4[k];
  } else {
    float d6[13];
    #pragma unroll
    for (int k=0;k<13;k++) d6[k]=0.f;
    qpath<9,9,13>  (w3s+0,    f4, p, cf[12],cf[13],cf[14], 0, 9,18, d6);
    qpath<9,13,13> (w3s+1053, f4, p, cf[15],cf[16],cf[17],27,40,53, d6);
    qpath<13,9,13> (w3s+2574, f6, p, cf[18],cf[19],cf[20], 0, 9,18, d6);
    qpath<13,13,13>(w3s+4095, f6, p, cf[21],cf[22],cf[23],27,40,53, d6);
    #pragma unroll
    for (int k=0;k<13;k++) fout[p*22+9+k] = f6[k]+d6[k];
  }
}

// ---------------- upsample ----------------
__global__ void k_upsample(const float* __restrict__ upw, float* __restrict__ out){
  int idx = blockIdx.x*256 + threadIdx.x;
  if (idx >= NBATCH*65536) return;
  int b = idx >> 16;
  int nh = idx & 65535;
  int rw = nh & 3; int t = nh >> 2; int w = t & 63; t >>= 6; int rh = t & 3; int h = t >> 2;
  int p = b*NLR + h*64 + w;
  float u4 = upw[(rh*4+rw)*2 + 0];
  float u6 = upw[(rh*4+rw)*2 + 1];
  float* o4 = out + (size_t)idx*9;
  float* o6 = out + 1179648 + (size_t)idx*13;
  #pragma unroll
  for (int k=0;k<9;k++)  o4[k] = d_feat0[p*22+k]*u4;
  #pragma unroll
  for (int k=0;k<13;k++) o6[k] = d_feat0[p*22+9+k]*u6;
}

extern "C" void kernel_launch(void* const* d_in, const int* in_sizes, int n_in,
                              void* d_out, int out_size) {
  const float* f4   = (const float*)d_in[0];
  const float* f6   = (const float*)d_in[1];
  const float* ls4  = (const float*)d_in[2];
  const float* ls6  = (const float*)d_in[3];
  const float* pbw  = (const float*)d_in[4];
  const float* pbb  = (const float*)d_in[5];
  const float* liw4 = (const float*)d_in[6];
  const float* liw6 = (const float*)d_in[7];
  const float* tvw  = (const float*)d_in[8];
  const float* tow  = (const float*)d_in[9];
  const float* low4 = (const float*)d_in[10];
  const float* low6 = (const float*)d_in[11];
  const float* upw  = (const float*)d_in[12];
  float* out = (float*)d_out;

  k_w3j<<<14,256>>>();
  k_sh<<<16,256>>>(pbw, pbb);
  k_coef<<<1,128>>>(liw4, liw6, tvw, tow, low4, low6);
  k_featinit<<<32,256>>>(f4, f6);
  for (int blk=0; blk<2; blk++){
    k_prepare<<<64,128>>>(ls4, ls6, blk, blk&1);
    k_attn<<<dim3(NLR/RT, NBATCH, SPLITS), 288>>>();
    k_reduce<<<NPTS/128,128>>>();
    k_output<<<dim3(32,2),256>>>(blk, blk&1);
  }
  k_upsample<<<512,256>>>(upw, out);
}

// round 9
// speedup vs baseline: 1.2115x; 1.0116x over previous
#include <cuda_runtime.h>
#include <cuda_bf16.h>
#include <math.h>

#define NBATCH 2
#define NLR    4096
#define NPTS   (NBATCH*NLR)
#define SPLITS 16
#define KT     16
#define RT     128

#define W3J_TOTAL   13318
#define W3J_OUT_OFF 2670

__device__ float d_feat0[NPTS*22];
__device__ float d_feat1[NPTS*22];
__device__ float d_qvT[22*NPTS];
__device__ float d_kvT[22*NPTS];
__device__ __align__(16) float d_gv  [NPTS*68];
__device__ __align__(16) float d_part[SPLITS*NPTS*68];
__device__ float d_G   [66*NPTS];
__device__ float d_sh  [NLR*6];
__device__ float d_eb  [2*NLR];
__device__ float d_w3j [W3J_TOTAL];
__device__ float d_coef[2*8*3];

__constant__ int PATH_L[14][3] = {
  {4,0,4},{4,2,4},{6,2,4},{6,0,6},{4,2,6},{6,2,6},
  {4,4,4},{4,6,4},{6,4,4},{6,6,4},{4,4,6},{4,6,6},{6,4,6},{6,6,6}};
__constant__ int PATH_OFF[15] = {
  0,81,486,1071,1240,1825,2670,3399,4452,5505,7026,8079,9600,11121,13318};

// ---------------- W3J (real Wigner/CG) ----------------
struct Cpx { double re, im; };

__device__ __forceinline__ double dev_cg(int j1,int m1,int j2,int m2,int j3,int m3,const double* f){
  if (m1+m2 != m3) return 0.0;
  if (j3 < abs(j1-j2) || j3 > j1+j2) return 0.0;
  double pref = sqrt((2.0*j3+1.0)*f[j3+j1-j2]*f[j3-j1+j2]*f[j1+j2-j3]/f[j1+j2+j3+1]);
  pref *= sqrt(f[j3+m3]*f[j3-m3]*f[j1-m1]*f[j1+m1]*f[j2-m2]*f[j2+m2]);
  double s = 0.0;
  int kmax = j1+j2-j3;
  for (int k=0;k<=kmax;k++){
    int a3=j1-m1-k, a4=j2+m2-k, a5=j3-j2+m1+k, a6=j3-j1-m2+k;
    if (a3<0||a4<0||a5<0||a6<0) continue;
    double t = 1.0/(f[k]*f[kmax-k]*f[a3]*f[a4]*f[a5]*f[a6]);
    s += (k&1)? -t : t;
  }
  return pref*s;
}

__device__ __forceinline__ int unz(int l, int r, int* cols, Cpx* vals){
  const double s2 = 0.70710678118654752440;
  if (r == l){ cols[0]=l; vals[0]=Cpx{1.0,0.0}; return 1; }
  if (r > l){ int m=r-l; double sg=(m&1)?-1.0:1.0;
    cols[0]=l+m; vals[0]=Cpx{sg*s2,0.0};
    cols[1]=l-m; vals[1]=Cpx{s2,0.0}; return 2; }
  int m=l-r; double sg=(m&1)?-1.0:1.0;
  cols[0]=l-m; vals[0]=Cpx{0.0,s2};
  cols[1]=l+m; vals[1]=Cpx{0.0,-sg*s2}; return 2;
}

__device__ __forceinline__ Cpx uent(int l,int r,int c){
  const double s2 = 0.70710678118654752440;
  Cpx z = Cpx{0.0,0.0};
  if (r==l){ if (c==l) z = Cpx{1.0,0.0}; return z; }
  if (r>l){ int m=r-l; double sg=(m&1)?-1.0:1.0;
    if (c==l+m) z = Cpx{sg*s2,0.0}; else if (c==l-m) z = Cpx{s2,0.0}; return z; }
  int m=l-r; double sg=(m&1)?-1.0:1.0;
  if (c==l-m) z = Cpx{0.0,s2}; else if (c==l+m) z = Cpx{0.0,-sg*s2};
  return z;
}

__global__ void k_w3j(){
  int path = blockIdx.x;
  int l1=PATH_L[path][0], l2=PATH_L[path][1], l3=PATH_L[path][2];
  int d1=2*l1+1, d2=2*l2+1, d3=2*l3+1;
  int off=PATH_OFF[path];
  int total=d1*d2*d3;
  __shared__ double Cc[169];
  __shared__ double red[256];
  int tid=threadIdx.x;
  double fct[20]; fct[0]=1.0;
  for (int i=1;i<20;i++) fct[i]=fct[i-1]*(double)i;
  for (int e=tid; e<d1*d2; e+=256){
    int a=e/d2, b=e%d2;
    int m1=a-l1, m2=b-l2, m3=m1+m2;
    Cc[e] = (abs(m3)<=l3) ? dev_cg(l1,m1,l2,m2,l3,m3,fct) : 0.0;
  }
  __syncthreads();
  double tv[9]; double ss=0.0; int cnt=0;
  for (int e=tid; e<total; e+=256){
    int i=e/(d2*d3); int j=(e/d3)%d2; int k=e%d3;
    int c1[2], c2[2]; Cpx u1[2], u2[2];
    int n1 = unz(l1,i,c1,u1);
    int n2 = unz(l2,j,c2,u2);
    double re=0.0;
    for (int ii=0;ii<n1;ii++)
      for (int jj=0;jj<n2;jj++){
        int c = c1[ii]-l1 + c2[jj]-l2 + l3;
        if (c<0 || c>2*l3) continue;
        Cpx u3 = uent(l3,k,c);
        if (u3.re==0.0 && u3.im==0.0) continue;
        double cgv = Cc[c1[ii]*d2 + c2[jj]];
        if (cgv==0.0) continue;
        double pr = u1[ii].re*u2[jj].re - u1[ii].im*u2[jj].im;
        double pi = u1[ii].re*u2[jj].im + u1[ii].im*u2[jj].re;
        re += (pr*u3.re + pi*u3.im)*cgv;
      }
    tv[cnt++]=re; ss+=re*re;
  }
  red[tid]=ss; __syncthreads();
  for (int s=128;s>0;s>>=1){ if (tid<s) red[tid]+=red[tid+s]; __syncthreads(); }
  double rnorm = rsqrt(red[0]);
  cnt=0;
  for (int e=tid; e<total; e+=256) d_w3j[off+e] = (float)(tv[cnt++]*rnorm);
}

// ---------------- spherical harmonics + exp(key bias) ----------------
__global__ void k_sh(const float* __restrict__ pbw, const float* __restrict__ pbb){
  int n = blockIdx.x*256 + threadIdx.x;
  if (n>=NLR) return;
  int h=n>>6, w=n&63;
  double y = -1.0 + 2.0*(double)h/63.0;
  double x = -1.0 + 2.0*(double)w/63.0;
  double r = sqrt(x*x+y*y); if (r < 1e-8) r = 1e-8;
  double xn=x/r, yn=y/r;
  const double c0=0.28209479177387814, c2=1.0925484305920792, c20=0.31539156525252005;
  float sh[6];
  sh[0]=(float)c0;
  sh[1]=(float)(c2*xn*yn);
  sh[2]=0.0f;
  sh[3]=(float)(-c20);
  sh[4]=0.0f;
  sh[5]=(float)(0.5*c2*(xn*xn-yn*yn));
  #pragma unroll
  for (int i=0;i<6;i++) d_sh[n*6+i]=sh[i];
  for (int blk=0;blk<2;blk++){
    float b = pbb[blk];
    #pragma unroll
    for (int i=0;i<6;i++) b = fmaf(sh[i], pbw[blk*6+i], b);
    d_eb[blk*NLR+n]=expf(b);
  }
}

// ---------------- coefficient precompute ----------------
__global__ void k_coef(const float* __restrict__ liw4, const float* __restrict__ liw6,
                       const float* __restrict__ tvw,  const float* __restrict__ tow,
                       const float* __restrict__ low4, const float* __restrict__ low6){
  __shared__ float a_s[96];
  int tid = threadIdx.x;
  if (tid < 96){
    int c = tid & 7; int pp = (tid>>3)%6; int blk = tid/48;
    const float* liw = (pp==0||pp==1||pp==4) ? (liw4+blk*8) : (liw6+blk*8);
    float s=0.f;
    for (int u=0;u<8;u++) s = fmaf(liw[u], tvw[((blk*6+pp)*8+u)*8 + c], s);
    a_s[tid]=s;
  }
  __syncthreads();
  if (tid < 16){
    int q = tid&7, blk = tid>>3;
    const float* liw = (q==0||q==1||q==4||q==5)? (liw4+blk*8) : (liw6+blk*8);
    const float* low = (q<4)? (low4+blk*8) : (low6+blk*8);
    float b[8];
    #pragma unroll
    for (int v=0;v<8;v++){
      float s=0.f;
      for (int u=0;u<8;u++){
        float lu = liw[u];
        for (int w=0;w<8;w++)
          s = fmaf(lu*tow[(((blk*8+q)*8+u)*8+v)*8+w], low[w], s);
      }
      b[v]=s;
    }
    int pbase = (q&1)? 3 : 0;
    const float invs = (1.0f/sqrtf(24.0f)) * (1.0f/16.0f) * (1.0f/sqrtf(8.0f));
    for (int pp=0;pp<3;pp++){
      float s=0.f;
      #pragma unroll
      for (int v=0;v<8;v++) s = fmaf(b[v], a_s[(blk*6+pbase+pp)*8 + v], s);
      d_coef[(blk*8+q)*3+pp] = s*invs;
    }
  }
}

// ---------------- feature init ----------------
__global__ void k_featinit(const float* __restrict__ f4, const float* __restrict__ f6){
  int p = blockIdx.x*256 + threadIdx.x;
  if (p>=NPTS) return;
  #pragma unroll
  for (int i=0;i<9;i++)  d_feat0[p*22+i]   = f4[p*9+i];
  #pragma unroll
  for (int j=0;j<13;j++) d_feat0[p*22+9+j] = f6[p*13+j];
}

// ---------------- per-point prep: qT, kT, value tensors g (eb folded) -----
__global__ void __launch_bounds__(128) k_prepare(const float* __restrict__ ls4,
                                                 const float* __restrict__ ls6,
                                                 int blk, int sel){
  const float* fin = sel ? d_feat1 : d_feat0;
  __shared__ float wv[W3J_OUT_OFF];
  int tid = threadIdx.x;
  for (int i=tid;i<W3J_OUT_OFF;i+=128) wv[i]=d_w3j[i];
  __syncthreads();
  int p = blockIdx.x*128 + tid;
  float f[22];
  float s4=0.f, s6=0.f;
  #pragma unroll
  for (int i=0;i<9;i++){ f[i]=fin[p*22+i]; s4=fmaf(f[i],f[i],s4); }
  #pragma unroll
  for (int i=9;i<22;i++){ f[i]=fin[p*22+i]; s6=fmaf(f[i],f[i],s6); }
  float inv4=1.f/fmaxf(sqrtf(s4),1e-12f);
  float inv6=1.f/fmaxf(sqrtf(s6),1e-12f);
  float e4=expf(ls4[blk]), e6=expf(ls6[blk]);
  #pragma unroll
  for (int i=0;i<9;i++){ float kk=f[i]*inv4; d_kvT[i*NPTS+p]=kk; d_qvT[i*NPTS+p]=kk*e4; }
  #pragma unroll
  for (int i=9;i<22;i++){ float kk=f[i]*inv6; d_kvT[i*NPTS+p]=kk; d_qvT[i*NPTS+p]=kk*e6; }
  int n = p & (NLR-1);
  float ebv = d_eb[blk*NLR+n];
  float sh0=d_sh[n*6];
  float sh2[5];
  #pragma unroll
  for (int j=0;j<5;j++) sh2[j]=d_sh[n*6+1+j];
  float* g = d_gv + p*68;
  { float a[9];
    #pragma unroll
    for (int k=0;k<9;k++) a[k]=0.f;
    #pragma unroll 1
    for (int i=0;i<9;i++){ float fi=f[i];
      #pragma unroll
      for (int k=0;k<9;k++) a[k]=fmaf(fi,wv[i*9+k],a[k]); }
    #pragma unroll
    for (int k=0;k<9;k++) g[k]=a[k]*sh0*ebv; }
  { float a[9];
    #pragma unroll
    for (int k=0;k<9;k++) a[k]=0.f;
    #pragma unroll 1
    for (int i=0;i<9;i++){ float fi=f[i];
      #pragma unroll 1
      for (int j=0;j<5;j++){ float c=fi*sh2[j];
        #pragma unroll
        for (int k=0;k<9;k++) a[k]=fmaf(c,wv[81+(i*5+j)*9+k],a[k]); } }
    #pragma unroll
    for (int k=0;k<9;k++) g[9+k]=a[k]*ebv; }
  { float a[9];
    #pragma unroll
    for (int k=0;k<9;k++) a[k]=0.f;
    #pragma unroll 1
    for (int i=0;i<13;i++){ float fi=f[9+i];
      #pragma unroll 1
      for (int j=0;j<5;j++){ float c=fi*sh2[j];
        #pragma unroll
        for (int k=0;k<9;k++) a[k]=fmaf(c,wv[486+(i*5+j)*9+k],a[k]); } }
    #pragma unroll
    for (int k=0;k<9;k++) g[18+k]=a[k]*ebv; }
  { float a[13];
    #pragma unroll
    for (int k=0;k<13;k++) a[k]=0.f;
    #pragma unroll 1
    for (int i=0;i<13;i++){ float fi=f[9+i];
      #pragma unroll
      for (int k=0;k<13;k++) a[k]=fmaf(fi,wv[1071+i*13+k],a[k]); }
    #pragma unroll
    for (int k=0;k<13;k++) g[27+k]=a[k]*sh0*ebv; }
  { float a[13];
    #pragma unroll
    for (int k=0;k<13;k++) a[k]=0.f;
    #pragma unroll 1
    for (int i=0;i<9;i++){ float fi=f[i];
      #pragma unroll 1
      for (int j=0;j<5;j++){ float c=fi*sh2[j];
        #pragma unroll
        for (int k=0;k<13;k++) a[k]=fmaf(c,wv[1240+(i*5+j)*13+k],a[k]); } }
    #pragma unroll
    for (int k=0;k<13;k++) g[40+k]=a[k]*ebv; }
  { float a[13];
    #pragma unroll
    for (int k=0;k<13;k++) a[k]=0.f;
    #pragma unroll 1
    for (int i=0;i<13;i++){ float fi=f[9+i];
      #pragma unroll 1
      for (int j=0;j<5;j++){ float c=fi*sh2[j];
        #pragma unroll
        for (int k=0;k<13;k++) a[k]=fmaf(c,wv[1825+(i*5+j)*13+k],a[k]); } }
    #pragma unroll
    for (int k=0;k<13;k++) g[53+k]=a[k]*ebv; }
  g[66]=ebv; g[67]=0.f;
}

// ---------------- tiled attention (software-pipelined, KT=16, occ 3) -----
// Phase A: S = Q K^T (K=22), thread tile 2 rows x 4 keys -> exp -> Ws[key][row]
// Phase B: acc += W^T G, thread tile 8 rows x 4 cols
// Next-tile K/G LDGs issued before phase A; STS after phase B. 2 barriers/tile.
__global__ void __launch_bounds__(288,3) k_attn(){
  __shared__ float Qs[22*RT];       // 2816 f
  __shared__ float Ks[2][22*KT];    // 2*352 f
  __shared__ float Gs[2][KT*68];    // 2*1088 f
  __shared__ float Ws[KT*RT];       // 2048 f
  const int tid = threadIdx.x;
  const int batch = blockIdx.y, split = blockIdx.z;
  const int prow = batch*NLR + blockIdx.x*RT;

  for (int i=tid;i<22*RT;i+=288) Qs[i] = d_qvT[(i>>7)*NPTS + prow + (i&127)];

  const int rgA = tid & 63, kgA = tid >> 6;   // phase A: 2 rows x 4 keys (tid<256)
  const int rgB = tid & 15, cgB = tid >> 4;   // phase B: 8 rows x 4 cols (cgB<17)
  const int gkey = tid/17, gcol = tid - gkey*17;   // G loader mapping (tid<272)
  float acc[32];
  #pragma unroll
  for (int i=0;i<32;i++) acc[i]=0.f;

  const int m0 = split*(NLR/SPLITS);
  const int ntiles = (NLR/SPLITS)/KT;   // 16

  float kr0, kr1=0.f;
  float4 gr = make_float4(0.f,0.f,0.f,0.f);
  {
    const int mb = batch*NLR + m0;
    kr0 = d_kvT[(tid>>4)*NPTS + mb + (tid&15)];
    if (tid<64) kr1 = d_kvT[((288+tid)>>4)*NPTS + mb + ((288+tid)&15)];
    if (tid<272) gr = *(const float4*)(d_gv + (size_t)(mb+gkey)*68 + gcol*4);
    Ks[0][tid]=kr0;
    if (tid<64) Ks[0][288+tid]=kr1;
    if (tid<272) *(float4*)(&Gs[0][gkey*68 + gcol*4]) = gr;
  }
  __syncthreads();

  for (int t=0;t<ntiles;t++){
    const int b = t&1;
    // issue next tile's global loads (latency overlapped with phase A)
    if (t+1<ntiles){
      const int mb = batch*NLR + m0 + (t+1)*KT;
      kr0 = d_kvT[(tid>>4)*NPTS + mb + (tid&15)];
      if (tid<64) kr1 = d_kvT[((288+tid)>>4)*NPTS + mb + ((288+tid)&15)];
      if (tid<272) gr = *(const float4*)(d_gv + (size_t)(mb+gkey)*68 + gcol*4);
    }
    // phase A
    if (tid < 256){
      float s[8];
      #pragma unroll
      for (int i=0;i<8;i++) s[i]=0.f;
      #pragma unroll 2
      for (int kk=0;kk<22;kk++){
        float2 q2 = *(const float2*)(Qs + kk*RT + rgA*2);
        float4 k4 = *(const float4*)(&Ks[b][kk*KT + kgA*4]);
        s[0]=fmaf(q2.x,k4.x,s[0]); s[1]=fmaf(q2.y,k4.x,s[1]);
        s[2]=fmaf(q2.x,k4.y,s[2]); s[3]=fmaf(q2.y,k4.y,s[3]);
        s[4]=fmaf(q2.x,k4.z,s[4]); s[5]=fmaf(q2.y,k4.z,s[5]);
        s[6]=fmaf(q2.x,k4.w,s[6]); s[7]=fmaf(q2.y,k4.w,s[7]);
      }
      #pragma unroll
      for (int j=0;j<4;j++){
        float2 w;
        w.x = __expf(s[j*2+0]);
        w.y = __expf(s[j*2+1]);
        *(float2*)(Ws + (kgA*4+j)*RT + rgA*2) = w;
      }
    }
    __syncthreads();
    // phase B
    if (cgB < 17){
      #pragma unroll 2
      for (int key=0;key<KT;key++){
        float4 wa = *(const float4*)(Ws + key*RT + rgB*8);
        float4 wb = *(const float4*)(Ws + key*RT + rgB*8 + 4);
        float4 g4 = *(const float4*)(&Gs[b][key*68 + cgB*4]);
        #pragma unroll
        for (int r=0;r<8;r++){
          float wv = (r==0)?wa.x:(r==1)?wa.y:(r==2)?wa.z:(r==3)?wa.w:
                     (r==4)?wb.x:(r==5)?wb.y:(r==6)?wb.z:wb.w;
          acc[r*4+0]=fmaf(wv,g4.x,acc[r*4+0]);
          acc[r*4+1]=fmaf(wv,g4.y,acc[r*4+1]);
          acc[r*4+2]=fmaf(wv,g4.z,acc[r*4+2]);
          acc[r*4+3]=fmaf(wv,g4.w,acc[r*4+3]);
        }
      }
    }
    // store next tile into alternate buffers
    if (t+1<ntiles){
      const int nb = b^1;
      Ks[nb][tid]=kr0;
      if (tid<64) Ks[nb][288+tid]=kr1;
      if (tid<272) *(float4*)(&Gs[nb][gkey*68 + gcol*4]) = gr;
    }
    __syncthreads();
  }
  if (cgB < 17){
    #pragma unroll
    for (int r=0;r<8;r++){
      int p = prow + rgB*8 + r;
      *(float4*)(d_part + ((size_t)split*NPTS + p)*68 + cgB*4) =
        make_float4(acc[r*4],acc[r*4+1],acc[r*4+2],acc[r*4+3]);
    }
  }
}

// ---------------- split reduce + transpose to [c][p] ----------------
__global__ void k_reduce(){
  int p = blockIdx.x*128 + threadIdx.x;
  if (p>=NPTS) return;
  float accv[68];
  #pragma unroll
  for (int i=0;i<68;i++) accv[i]=0.f;
  #pragma unroll 4
  for (int sp=0;sp<SPLITS;sp++){
    const float4* b = (const float4*)(d_part + ((size_t)sp*NPTS+p)*68);
    #pragma unroll
    for (int i=0;i<17;i++){
      float4 v=b[i];
      accv[i*4+0]+=v.x; accv[i*4+1]+=v.y; accv[i*4+2]+=v.z; accv[i*4+3]+=v.w;
    }
  }
  float inv = 1.f/accv[66];
  #pragma unroll 1
  for (int c=0;c<66;c++) d_G[c*NPTS+p] = accv[c]*inv;
}

// ---------------- per-point output tensor products ----------------
template<int D1,int D2,int D3>
__device__ __forceinline__ void qpath(const float* __restrict__ w3, const float* __restrict__ f,
                                      int p, float c0, float c1, float c2,
                                      int g0, int g1, int g2, float* out){
  #pragma unroll 1
  for (int j=0;j<D2;j++){
    float gm = c0*d_G[(g0+j)*NPTS+p] + c1*d_G[(g1+j)*NPTS+p] + c2*d_G[(g2+j)*NPTS+p];
    #pragma unroll
    for (int i=0;i<D1;i++){
      float cf = gm*f[i];
      #pragma unroll
      for (int k=0;k<D3;k++) out[k] = fmaf(cf, w3[(i*D2+j)*D3+k], out[k]);
    }
  }
}

__global__ void __launch_bounds__(256) k_output(int blk, int sel){
  const float* fin = sel ? d_feat1 : d_feat0;
  float* fout = sel ? d_feat0 : d_feat1;
  __shared__ float w3s[6292];
  int tid = threadIdx.x;
  int half = blockIdx.y;
  int base = half ? 7026 : 2670;
  int len  = half ? 6292 : 4356;
  for (int i=tid;i<len;i+=256) w3s[i]=d_w3j[base+i];
  __syncthreads();
  int p = blockIdx.x*256 + tid;
  float f4[9], f6[13];
  #pragma unroll
  for (int i=0;i<9;i++) f4[i]=fin[p*22+i];
  #pragma unroll
  for (int i=0;i<13;i++) f6[i]=fin[p*22+9+i];
  const float* cf = d_coef + blk*24;
  if (half==0){
    float d4[9];
    #pragma unroll
    for (int k=0;k<9;k++) d4[k]=0.f;
    qpath<9,9,9>   (w3s+0,    f4, p, cf[0], cf[1], cf[2],  0, 9,18, d4);
    qpath<9,13,9>  (w3s+729,  f4, p, cf[3], cf[4], cf[5], 27,40,53, d4);
    qpath<13,9,9>  (w3s+1782, f6, p, cf[6], cf[7], cf[8],  0, 9,18, d4);
    qpath<13,13,9> (w3s+2835, f6, p, cf[9], cf[10],cf[11],27,40,53, d4);
    #pragma unroll
    for (int k=0;k<9;k++) fout[p*22+k] = f4[k]+d4[k];
  } else {
    float d6[13];
    #pragma unroll
    for (int k=0;k<13;k++) d6[k]=0.f;
    qpath<9,9,13>  (w3s+0,    f4, p, cf[12],cf[13],cf[14], 0, 9,18, d6);
    qpath<9,13,13> (w3s+1053, f4, p, cf[15],cf[16],cf[17],27,40,53, d6);
    qpath<13,9,13> (w3s+2574, f6, p, cf[18],cf[19],cf[20], 0, 9,18, d6);
    qpath<13,13,13>(w3s+4095, f6, p, cf[21],cf[22],cf[23],27,40,53, d6);
    #pragma unroll
    for (int k=0;k<13;k++) fout[p*22+9+k] = f6[k]+d6[k];
  }
}

// ---------------- upsample ----------------
__global__ void k_upsample(const float* __restrict__ upw, float* __restrict__ out){
  int idx = blockIdx.x*256 + threadIdx.x;
  if (idx >= NBATCH*65536) return;
  int b = idx >> 16;
  int nh = idx & 65535;
  int rw = nh & 3; int t = nh >> 2; int w = t & 63; t >>= 6; int rh = t & 3; int h = t >> 2;
  int p = b*NLR + h*64 + w;
  float u4 = upw[(rh*4+rw)*2 + 0];
  float u6 = upw[(rh*4+rw)*2 + 1];
  float* o4 = out + (size_t)idx*9;
  float* o6 = out + 1179648 + (size_t)idx*13;
  #pragma unroll
  for (int k=0;k<9;k++)  o4[k] = d_feat0[p*22+k]*u4;
  #pragma unroll
  for (int k=0;k<13;k++) o6[k] = d_feat0[p*22+9+k]*u6;
}

extern "C" void kernel_launch(void* const* d_in, const int* in_sizes, int n_in,
                              void* d_out, int out_size) {
  const float* f4   = (const float*)d_in[0];
  const float* f6   = (const float*)d_in[1];
  const float* ls4  = (const float*)d_in[2];
  const float* ls6  = (const float*)d_in[3];
  const float* pbw  = (const float*)d_in[4];
  const float* pbb  = (const float*)d_in[5];
  const float* liw4 = (const float*)d_in[6];
  const float* liw6 = (const float*)d_in[7];
  const float* tvw  = (const float*)d_in[8];
  const float* tow  = (const float*)d_in[9];
  const float* low4 = (const float*)d_in[10];
  const float* low6 = (const float*)d_in[11];
  const float* upw  = (const float*)d_in[12];
  float* out = (float*)d_out;

  k_w3j<<<14,256>>>();
  k_sh<<<16,256>>>(pbw, pbb);
  k_coef<<<1,128>>>(liw4, liw6, tvw, tow, low4, low6);
  k_featinit<<<32,256>>>(f4, f6);
  for (int blk=0; blk<2; blk++){
    k_prepare<<<64,128>>>(ls4, ls6, blk, blk&1);
    k_attn<<<dim3(NLR/RT, NBATCH, SPLITS), 288>>>();
    k_reduce<<<NPTS/128,128>>>();
    k_output<<<dim3(32,2),256>>>(blk, blk&1);
  }
  k_upsample<<<512,256>>>(upw, out);
}

// round 10
// speedup vs baseline: 1.5990x; 1.3198x over previous
#include <cuda_runtime.h>
#include <cuda_bf16.h>
#include <math.h>

#define NBATCH 2
#define NLR    4096
#define NPTS   (NBATCH*NLR)
#define SPLITS 16
#define KT     32
#define RT     128
#define GST    72

#define W3J_TOTAL   13318
#define W3J_OUT_OFF 2670

__device__ float d_feat0[NPTS*22];
__device__ float d_feat1[NPTS*22];
__device__ float d_qvT[22*NPTS];
__device__ float d_kvT[22*NPTS];
__device__ __align__(16) float d_gv  [NPTS*GST];
__device__ __align__(16) float d_part[SPLITS*NPTS*68];
__device__ float d_G   [66*NPTS];
__device__ float d_sh  [NLR*6];
__device__ float d_eb  [2*NLR];
__device__ float d_w3j [W3J_TOTAL];
__device__ float d_coef[2*8*3];

__constant__ int PATH_L[14][3] = {
  {4,0,4},{4,2,4},{6,2,4},{6,0,6},{4,2,6},{6,2,6},
  {4,4,4},{4,6,4},{6,4,4},{6,6,4},{4,4,6},{4,6,6},{6,4,6},{6,6,6}};
__constant__ int PATH_OFF[15] = {
  0,81,486,1071,1240,1825,2670,3399,4452,5505,7026,8079,9600,11121,13318};

// ---------------- tf32 helpers ----------------
__device__ __forceinline__ unsigned tf32bits(float x){
  unsigned u;
  asm("cvt.rna.tf32.f32 %0, %1;" : "=r"(u) : "f"(x));
  return u;
}
__device__ __forceinline__ float tf32r(float x){
  return __uint_as_float(tf32bits(x));
}
__device__ __forceinline__ void mma_tf32(float* c,
    unsigned a0, unsigned a1, unsigned a2, unsigned a3,
    unsigned b0, unsigned b1){
  asm volatile(
    "mma.sync.aligned.m16n8k8.row.col.f32.tf32.tf32.f32 "
    "{%0,%1,%2,%3}, {%4,%5,%6,%7}, {%8,%9}, {%0,%1,%2,%3};"
    : "+f"(c[0]), "+f"(c[1]), "+f"(c[2]), "+f"(c[3])
    : "r"(a0), "r"(a1), "r"(a2), "r"(a3), "r"(b0), "r"(b1));
}

// ---------------- W3J (real Wigner/CG) ----------------
struct Cpx { double re, im; };

__device__ __forceinline__ double dev_cg(int j1,int m1,int j2,int m2,int j3,int m3,const double* f){
  if (m1+m2 != m3) return 0.0;
  if (j3 < abs(j1-j2) || j3 > j1+j2) return 0.0;
  double pref = sqrt((2.0*j3+1.0)*f[j3+j1-j2]*f[j3-j1+j2]*f[j1+j2-j3]/f[j1+j2+j3+1]);
  pref *= sqrt(f[j3+m3]*f[j3-m3]*f[j1-m1]*f[j1+m1]*f[j2-m2]*f[j2+m2]);
  double s = 0.0;
  int kmax = j1+j2-j3;
  for (int k=0;k<=kmax;k++){
    int a3=j1-m1-k, a4=j2+m2-k, a5=j3-j2+m1+k, a6=j3-j1-m2+k;
    if (a3<0||a4<0||a5<0||a6<0) continue;
    double t = 1.0/(f[k]*f[kmax-k]*f[a3]*f[a4]*f[a5]*f[a6]);
    s += (k&1)? -t : t;
  }
  return pref*s;
}

__device__ __forceinline__ int unz(int l, int r, int* cols, Cpx* vals){
  const double s2 = 0.70710678118654752440;
  if (r == l){ cols[0]=l; vals[0]=Cpx{1.0,0.0}; return 1; }
  if (r > l){ int m=r-l; double sg=(m&1)?-1.0:1.0;
    cols[0]=l+m; vals[0]=Cpx{sg*s2,0.0};
    cols[1]=l-m; vals[1]=Cpx{s2,0.0}; return 2; }
  int m=l-r; double sg=(m&1)?-1.0:1.0;
  cols[0]=l-m; vals[0]=Cpx{0.0,s2};
  cols[1]=l+m; vals[1]=Cpx{0.0,-sg*s2}; return 2;
}

__device__ __forceinline__ Cpx uent(int l,int r,int c){
  const double s2 = 0.70710678118654752440;
  Cpx z = Cpx{0.0,0.0};
  if (r==l){ if (c==l) z = Cpx{1.0,0.0}; return z; }
  if (r>l){ int m=r-l; double sg=(m&1)?-1.0:1.0;
    if (c==l+m) z = Cpx{sg*s2,0.0}; else if (c==l-m) z = Cpx{s2,0.0}; return z; }
  int m=l-r; double sg=(m&1)?-1.0:1.0;
  if (c==l-m) z = Cpx{0.0,s2}; else if (c==l+m) z = Cpx{0.0,-sg*s2};
  return z;
}

__global__ void k_w3j(){
  int path = blockIdx.x;
  int l1=PATH_L[path][0], l2=PATH_L[path][1], l3=PATH_L[path][2];
  int d1=2*l1+1, d2=2*l2+1, d3=2*l3+1;
  int off=PATH_OFF[path];
  int total=d1*d2*d3;
  __shared__ double Cc[169];
  __shared__ double red[256];
  int tid=threadIdx.x;
  double fct[20]; fct[0]=1.0;
  for (int i=1;i<20;i++) fct[i]=fct[i-1]*(double)i;
  for (int e=tid; e<d1*d2; e+=256){
    int a=e/d2, b=e%d2;
    int m1=a-l1, m2=b-l2, m3=m1+m2;
    Cc[e] = (abs(m3)<=l3) ? dev_cg(l1,m1,l2,m2,l3,m3,fct) : 0.0;
  }
  __syncthreads();
  double tv[9]; double ss=0.0; int cnt=0;
  for (int e=tid; e<total; e+=256){
    int i=e/(d2*d3); int j=(e/d3)%d2; int k=e%d3;
    int c1[2], c2[2]; Cpx u1[2], u2[2];
    int n1 = unz(l1,i,c1,u1);
    int n2 = unz(l2,j,c2,u2);
    double re=0.0;
    for (int ii=0;ii<n1;ii++)
      for (int jj=0;jj<n2;jj++){
        int c = c1[ii]-l1 + c2[jj]-l2 + l3;
        if (c<0 || c>2*l3) continue;
        Cpx u3 = uent(l3,k,c);
        if (u3.re==0.0 && u3.im==0.0) continue;
        double cgv = Cc[c1[ii]*d2 + c2[jj]];
        if (cgv==0.0) continue;
        double pr = u1[ii].re*u2[jj].re - u1[ii].im*u2[jj].im;
        double pi = u1[ii].re*u2[jj].im + u1[ii].im*u2[jj].re;
        re += (pr*u3.re + pi*u3.im)*cgv;
      }
    tv[cnt++]=re; ss+=re*re;
  }
  red[tid]=ss; __syncthreads();
  for (int s=128;s>0;s>>=1){ if (tid<s) red[tid]+=red[tid+s]; __syncthreads(); }
  double rnorm = rsqrt(red[0]);
  cnt=0;
  for (int e=tid; e<total; e+=256) d_w3j[off+e] = (float)(tv[cnt++]*rnorm);
}

// ---------------- spherical harmonics + exp(key bias) ----------------
__global__ void k_sh(const float* __restrict__ pbw, const float* __restrict__ pbb){
  int n = blockIdx.x*256 + threadIdx.x;
  if (n>=NLR) return;
  int h=n>>6, w=n&63;
  double y = -1.0 + 2.0*(double)h/63.0;
  double x = -1.0 + 2.0*(double)w/63.0;
  double r = sqrt(x*x+y*y); if (r < 1e-8) r = 1e-8;
  double xn=x/r, yn=y/r;
  const double c0=0.28209479177387814, c2=1.0925484305920792, c20=0.31539156525252005;
  float sh[6];
  sh[0]=(float)c0;
  sh[1]=(float)(c2*xn*yn);
  sh[2]=0.0f;
  sh[3]=(float)(-c20);
  sh[4]=0.0f;
  sh[5]=(float)(0.5*c2*(xn*xn-yn*yn));
  #pragma unroll
  for (int i=0;i<6;i++) d_sh[n*6+i]=sh[i];
  for (int blk=0;blk<2;blk++){
    float b = pbb[blk];
    #pragma unroll
    for (int i=0;i<6;i++) b = fmaf(sh[i], pbw[blk*6+i], b);
    d_eb[blk*NLR+n]=expf(b);
  }
}

// ---------------- coefficient precompute ----------------
__global__ void k_coef(const float* __restrict__ liw4, const float* __restrict__ liw6,
                       const float* __restrict__ tvw,  const float* __restrict__ tow,
                       const float* __restrict__ low4, const float* __restrict__ low6){
  __shared__ float a_s[96];
  int tid = threadIdx.x;
  if (tid < 96){
    int c = tid & 7; int pp = (tid>>3)%6; int blk = tid/48;
    const float* liw = (pp==0||pp==1||pp==4) ? (liw4+blk*8) : (liw6+blk*8);
    float s=0.f;
    for (int u=0;u<8;u++) s = fmaf(liw[u], tvw[((blk*6+pp)*8+u)*8 + c], s);
    a_s[tid]=s;
  }
  __syncthreads();
  if (tid < 16){
    int q = tid&7, blk = tid>>3;
    const float* liw = (q==0||q==1||q==4||q==5)? (liw4+blk*8) : (liw6+blk*8);
    const float* low = (q<4)? (low4+blk*8) : (low6+blk*8);
    float b[8];
    #pragma unroll
    for (int v=0;v<8;v++){
      float s=0.f;
      for (int u=0;u<8;u++){
        float lu = liw[u];
        for (int w=0;w<8;w++)
          s = fmaf(lu*tow[(((blk*8+q)*8+u)*8+v)*8+w], low[w], s);
      }
      b[v]=s;
    }
    int pbase = (q&1)? 3 : 0;
    const float invs = (1.0f/sqrtf(24.0f)) * (1.0f/16.0f) * (1.0f/sqrtf(8.0f));
    for (int pp=0;pp<3;pp++){
      float s=0.f;
      #pragma unroll
      for (int v=0;v<8;v++) s = fmaf(b[v], a_s[(blk*6+pbase+pp)*8 + v], s);
      d_coef[(blk*8+q)*3+pp] = s*invs;
    }
  }
}

// ---------------- feature init ----------------
__global__ void k_featinit(const float* __restrict__ f4, const float* __restrict__ f6){
  int p = blockIdx.x*256 + threadIdx.x;
  if (p>=NPTS) return;
  #pragma unroll
  for (int i=0;i<9;i++)  d_feat0[p*22+i]   = f4[p*9+i];
  #pragma unroll
  for (int j=0;j<13;j++) d_feat0[p*22+9+j] = f6[p*13+j];
}

// ---------------- per-point prep: qT, kT, value tensors g (eb folded, tf32) --
__global__ void __launch_bounds__(128) k_prepare(const float* __restrict__ ls4,
                                                 const float* __restrict__ ls6,
                                                 int blk, int sel){
  const float* fin = sel ? d_feat1 : d_feat0;
  __shared__ float wv[W3J_OUT_OFF];
  int tid = threadIdx.x;
  for (int i=tid;i<W3J_OUT_OFF;i+=128) wv[i]=d_w3j[i];
  __syncthreads();
  int p = blockIdx.x*128 + tid;
  float f[22];
  float s4=0.f, s6=0.f;
  #pragma unroll
  for (int i=0;i<9;i++){ f[i]=fin[p*22+i]; s4=fmaf(f[i],f[i],s4); }
  #pragma unroll
  for (int i=9;i<22;i++){ f[i]=fin[p*22+i]; s6=fmaf(f[i],f[i],s6); }
  float inv4=1.f/fmaxf(sqrtf(s4),1e-12f);
  float inv6=1.f/fmaxf(sqrtf(s6),1e-12f);
  float e4=expf(ls4[blk]), e6=expf(ls6[blk]);
  #pragma unroll
  for (int i=0;i<9;i++){ float kk=f[i]*inv4; d_kvT[i*NPTS+p]=kk; d_qvT[i*NPTS+p]=kk*e4; }
  #pragma unroll
  for (int i=9;i<22;i++){ float kk=f[i]*inv6; d_kvT[i*NPTS+p]=kk; d_qvT[i*NPTS+p]=kk*e6; }
  int n = p & (NLR-1);
  float ebv = d_eb[blk*NLR+n];
  float sh0=d_sh[n*6];
  float sh2[5];
  #pragma unroll
  for (int j=0;j<5;j++) sh2[j]=d_sh[n*6+1+j];
  float* g = d_gv + (size_t)p*GST;
  { float a[9];
    #pragma unroll
    for (int k=0;k<9;k++) a[k]=0.f;
    #pragma unroll 1
    for (int i=0;i<9;i++){ float fi=f[i];
      #pragma unroll
      for (int k=0;k<9;k++) a[k]=fmaf(fi,wv[i*9+k],a[k]); }
    #pragma unroll
    for (int k=0;k<9;k++) g[k]=tf32r(a[k]*sh0*ebv); }
  { float a[9];
    #pragma unroll
    for (int k=0;k<9;k++) a[k]=0.f;
    #pragma unroll 1
    for (int i=0;i<9;i++){ float fi=f[i];
      #pragma unroll 1
      for (int j=0;j<5;j++){ float c=fi*sh2[j];
        #pragma unroll
        for (int k=0;k<9;k++) a[k]=fmaf(c,wv[81+(i*5+j)*9+k],a[k]); } }
    #pragma unroll
    for (int k=0;k<9;k++) g[9+k]=tf32r(a[k]*ebv); }
  { float a[9];
    #pragma unroll
    for (int k=0;k<9;k++) a[k]=0.f;
    #pragma unroll 1
    for (int i=0;i<13;i++){ float fi=f[9+i];
      #pragma unroll 1
      for (int j=0;j<5;j++){ float c=fi*sh2[j];
        #pragma unroll
        for (int k=0;k<9;k++) a[k]=fmaf(c,wv[486+(i*5+j)*9+k],a[k]); } }
    #pragma unroll
    for (int k=0;k<9;k++) g[18+k]=tf32r(a[k]*ebv); }
  { float a[13];
    #pragma unroll
    for (int k=0;k<13;k++) a[k]=0.f;
    #pragma unroll 1
    for (int i=0;i<13;i++){ float fi=f[9+i];
      #pragma unroll
      for (int k=0;k<13;k++) a[k]=fmaf(fi,wv[1071+i*13+k],a[k]); }
    #pragma unroll
    for (int k=0;k<13;k++) g[27+k]=tf32r(a[k]*sh0*ebv); }
  { float a[13];
    #pragma unroll
    for (int k=0;k<13;k++) a[k]=0.f;
    #pragma unroll 1
    for (int i=0;i<9;i++){ float fi=f[i];
      #pragma unroll 1
      for (int j=0;j<5;j++){ float c=fi*sh2[j];
        #pragma unroll
        for (int k=0;k<13;k++) a[k]=fmaf(c,wv[1240+(i*5+j)*13+k],a[k]); } }
    #pragma unroll
    for (int k=0;k<13;k++) g[40+k]=tf32r(a[k]*ebv); }
  { float a[13];
    #pragma unroll
    for (int k=0;k<13;k++) a[k]=0.f;
    #pragma unroll 1
    for (int i=0;i<13;i++){ float fi=f[9+i];
      #pragma unroll 1
      for (int j=0;j<5;j++){ float c=fi*sh2[j];
        #pragma unroll
        for (int k=0;k<13;k++) a[k]=fmaf(c,wv[1825+(i*5+j)*13+k],a[k]); } }
    #pragma unroll
    for (int k=0;k<13;k++) g[53+k]=tf32r(a[k]*ebv); }
  g[66]=tf32r(ebv);
  #pragma unroll
  for (int k=67;k<GST;k++) g[k]=0.f;
}

// ---------------- attention: scalar QK -> exp -> HMMA tf32 PV -------------
// CTA: 128 rows x 256 keys (split into 8 tiles of KT=32). 256 threads, 8 warps.
// Warp w owns row strip [16w, 16w+16). Thread (w,l) computes the m16n8k8
// A-fragment scores directly: rows r0=16w+l/4, r1=r0+8; keys k0=ks*8+l%4, k1=k0+4.
// After exp + tf32 round, those 4 regs ARE the A fragment -> MMA against G.
__global__ void __launch_bounds__(256,2) k_attn(){
  __shared__ float Qs [22*RT];    // 2816 f
  __shared__ float Ks2[22*KT];    // 704 f (key order permuted: pairs (k, k+4))
  __shared__ float Gs [KT*GST];   // 2304 f
  const int tid = threadIdx.x;
  const int w = tid>>5, l = tid&31;
  const int batch = blockIdx.y, split = blockIdx.z;
  const int prow = batch*NLR + blockIdx.x*RT;

  for (int i=tid;i<22*RT;i+=256) Qs[i] = d_qvT[(i>>7)*NPTS + prow + (i&127)];

  const int r0 = 16*w + (l>>2);
  const int lj = l & 3;
  float accd[9][4];
  #pragma unroll
  for (int n=0;n<9;n++){
    #pragma unroll
    for (int c=0;c<4;c++) accd[n][c]=0.f;
  }

  const int m0 = split*(NLR/SPLITS);
  const int ntiles = (NLR/SPLITS)/KT;   // 8
  for (int t=0;t<ntiles;t++){
    const int mbase = batch*NLR + m0 + t*KT;
    __syncthreads();
    // load K permuted: slot kd*32 + ks*8 + 2j+half <- key ks*8 + j + 4*half
    for (int i=tid;i<22*KT;i+=256){
      int kd=i>>5, pos=i&31;
      int ks=pos>>3, idx=pos&7;
      int key = ks*8 + (idx>>1) + 4*(idx&1);
      Ks2[i] = d_kvT[kd*NPTS + mbase + key];
    }
    for (int i=tid;i<KT*(GST/4);i+=256){
      int key=i/(GST/4), c4=i%(GST/4);
      *(float4*)(Gs + key*GST + c4*4) =
        *(const float4*)(d_gv + (size_t)(mbase+key)*GST + c4*4);
    }
    __syncthreads();
    // phase A: 16 scores per thread (4 per ks-group)
    float s[4][4];
    #pragma unroll
    for (int ks=0;ks<4;ks++){
      #pragma unroll
      for (int c=0;c<4;c++) s[ks][c]=0.f;
    }
    #pragma unroll 2
    for (int kd=0;kd<22;kd++){
      float q0 = Qs[kd*RT + r0];
      float q1 = Qs[kd*RT + r0 + 8];
      #pragma unroll
      for (int ks=0;ks<4;ks++){
        float2 kk = *(const float2*)(Ks2 + kd*KT + ks*8 + 2*lj);
        s[ks][0]=fmaf(q0,kk.x,s[ks][0]);
        s[ks][1]=fmaf(q1,kk.x,s[ks][1]);
        s[ks][2]=fmaf(q0,kk.y,s[ks][2]);
        s[ks][3]=fmaf(q1,kk.y,s[ks][3]);
      }
    }
    // exp + tf32 round -> A fragments; MMA against G
    #pragma unroll
    for (int ks=0;ks<4;ks++){
      unsigned a0 = tf32bits(__expf(s[ks][0]));
      unsigned a1 = tf32bits(__expf(s[ks][1]));
      unsigned a2 = tf32bits(__expf(s[ks][2]));
      unsigned a3 = tf32bits(__expf(s[ks][3]));
      const int krow0 = (ks*8 + lj)*GST;
      const int krow1 = (ks*8 + 4 + lj)*GST;
      const int ncol = (l>>2);
      #pragma unroll
      for (int n=0;n<9;n++){
        unsigned b0 = __float_as_uint(Gs[krow0 + n*8 + ncol]);
        unsigned b1 = __float_as_uint(Gs[krow1 + n*8 + ncol]);
        mma_tf32(accd[n], a0,a1,a2,a3, b0,b1);
      }
    }
  }
  // write partials: D frag (row=r0/r0+8, col = n*8 + 2*lj, +1)
  {
    const int p0 = prow + r0;
    const int p1 = p0 + 8;
    float* base0 = d_part + ((size_t)split*NPTS + p0)*68;
    float* base1 = d_part + ((size_t)split*NPTS + p1)*68;
    #pragma unroll
    for (int n=0;n<9;n++){
      int col = n*8 + 2*lj;
      if (col < 68){
        *(float2*)(base0 + col) = make_float2(accd[n][0], accd[n][1]);
        *(float2*)(base1 + col) = make_float2(accd[n][2], accd[n][3]);
      }
    }
  }
}

// ---------------- split reduce + transpose to [c][p] ----------------
__global__ void k_reduce(){
  int p = blockIdx.x*128 + threadIdx.x;
  if (p>=NPTS) return;
  float accv[68];
  #pragma unroll
  for (int i=0;i<68;i++) accv[i]=0.f;
  #pragma unroll 4
  for (int sp=0;sp<SPLITS;sp++){
    const float4* b = (const float4*)(d_part + ((size_t)sp*NPTS+p)*68);
    #pragma unroll
    for (int i=0;i<17;i++){
      float4 v=b[i];
      accv[i*4+0]+=v.x; accv[i*4+1]+=v.y; accv[i*4+2]+=v.z; accv[i*4+3]+=v.w;
    }
  }
  float inv = 1.f/accv[66];
  #pragma unroll 1
  for (int c=0;c<66;c++) d_G[c*NPTS+p] = accv[c]*inv;
}

// ---------------- per-point output tensor products ----------------
template<int D1,int D2,int D3>
__device__ __forceinline__ void qpath(const float* __restrict__ w3, const float* __restrict__ f,
                                      int p, float c0, float c1, float c2,
                                      int g0, int g1, int g2, float* out){
  #pragma unroll 1
  for (int j=0;j<D2;j++){
    float gm = c0*d_G[(g0+j)*NPTS+p] + c1*d_G[(g1+j)*NPTS+p] + c2*d_G[(g2+j)*NPTS+p];
    #pragma unroll
    for (int i=0;i<D1;i++){
      float cf = gm*f[i];
      #pragma unroll
      for (int k=0;k<D3;k++) out[k] = fmaf(cf, w3[(i*D2+j)*D3+k], out[k]);
    }
  }
}

__global__ void __launch_bounds__(256) k_output(int blk, int sel){
  const float* fin = sel ? d_feat1 : d_feat0;
  float* fout = sel ? d_feat0 : d_feat1;
  __shared__ float w3s[6292];
  int tid = threadIdx.x;
  int half = blockIdx.y;
  int base = half ? 7026 : 2670;
  int len  = half ? 6292 : 4356;
  for (int i=tid;i<len;i+=256) w3s[i]=d_w3j[base+i];
  __syncthreads();
  int p = blockIdx.x*256 + tid;
  float f4[9], f6[13];
  #pragma unroll
  for (int i=0;i<9;i++) f4[i]=fin[p*22+i];
  #pragma unroll
  for (int i=0;i<13;i++) f6[i]=fin[p*22+9+i];
  const float* cf = d_coef + blk*24;
  if (half==0){
    float d4[9];
    #pragma unroll
    for (int k=0;k<9;k++) d4[k]=0.f;
    qpath<9,9,9>   (w3s+0,    f4, p, cf[0], cf[1], cf[2],  0, 9,18, d4);
    qpath<9,13,9>  (w3s+729,  f4, p, cf[3], cf[4], cf[5], 27,40,53, d4);
    qpath<13,9,9>  (w3s+1782, f6, p, cf[6], cf[7], cf[8],  0, 9,18, d4);
    qpath<13,13,9> (w3s+2835, f6, p, cf[9], cf[10],cf[11],27,40,53, d4);
    #pragma unroll
    for (int k=0;k<9;k++) fout[p*22+k] = f4[k]+d4[k];
  } else {
    float d6[13];
    #pragma unroll
    for (int k=0;k<13;k++) d6[k]=0.f;
    qpath<9,9,13>  (w3s+0,    f4, p, cf[12],cf[13],cf[14], 0, 9,18, d6);
    qpath<9,13,13> (w3s+1053, f4, p, cf[15],cf[16],cf[17],27,40,53, d6);
    qpath<13,9,13> (w3s+2574, f6, p, cf[18],cf[19],cf[20], 0, 9,18, d6);
    qpath<13,13,13>(w3s+4095, f6, p, cf[21],cf[22],cf[23],27,40,53, d6);
    #pragma unroll
    for (int k=0;k<13;k++) fout[p*22+9+k] = f6[k]+d6[k];
  }
}

// ---------------- upsample ----------------
__global__ void k_upsample(const float* __restrict__ upw, float* __restrict__ out){
  int idx = blockIdx.x*256 + threadIdx.x;
  if (idx >= NBATCH*65536) return;
  int b = idx >> 16;
  int nh = idx & 65535;
  int rw = nh & 3; int t = nh >> 2; int w = t & 63; t >>= 6; int rh = t & 3; int h = t >> 2;
  int p = b*NLR + h*64 + w;
  float u4 = upw[(rh*4+rw)*2 + 0];
  float u6 = upw[(rh*4+rw)*2 + 1];
  float* o4 = out + (size_t)idx*9;
  float* o6 = out + 1179648 + (size_t)idx*13;
  #pragma unroll
  for (int k=0;k<9;k++)  o4[k] = d_feat0[p*22+k]*u4;
  #pragma unroll
  for (int k=0;k<13;k++) o6[k] = d_feat0[p*22+9+k]*u6;
}

extern "C" void kernel_launch(void* const* d_in, const int* in_sizes, int n_in,
                              void* d_out, int out_size) {
  const float* f4   = (const float*)d_in[0];
  const float* f6   = (const float*)d_in[1];
  const float* ls4  = (const float*)d_in[2];
  const float* ls6  = (const float*)d_in[3];
  const float* pbw  = (const float*)d_in[4];
  const float* pbb  = (const float*)d_in[5];
  const float* liw4 = (const float*)d_in[6];
  const float* liw6 = (const float*)d_in[7];
  const float* tvw  = (const float*)d_in[8];
  const float* tow  = (const float*)d_in[9];
  const float* low4 = (const float*)d_in[10];
  const float* low6 = (const float*)d_in[11];
  const float* upw  = (const float*)d_in[12];
  float* out = (float*)d_out;

  k_w3j<<<14,256>>>();
  k_sh<<<16,256>>>(pbw, pbb);
  k_coef<<<1,128>>>(liw4, liw6, tvw, tow, low4, low6);
  k_featinit<<<32,256>>>(f4, f6);
  for (int blk=0; blk<2; blk++){
    k_prepare<<<64,128>>>(ls4, ls6, blk, blk&1);
    k_attn<<<dim3(NLR/RT, NBATCH, SPLITS), 256>>>();
    k_reduce<<<NPTS/128,128>>>();
    k_output<<<dim3(32,2),256>>>(blk, blk&1);
  }
  k_upsample<<<512,256>>>(upw, out);
}

// round 11
// speedup vs baseline: 1.8482x; 1.1559x over previous
#include <cuda_runtime.h>
#include <cuda_bf16.h>
#include <math.h>

#define NBATCH 2
#define NLR    4096
#define NPTS   (NBATCH*NLR)
#define SPLITS 16
#define KT     32
#define RT     128
#define GST    76
#define KST    28

#define W3J_TOTAL   13318
#define W3J_OUT_OFF 2670

__device__ float d_feat0[NPTS*22];
__device__ float d_feat1[NPTS*22];
__device__ float d_qvT[22*NPTS];
__device__ float d_kvT[22*NPTS];
__device__ __align__(16) float d_gv  [NPTS*GST];
__device__ __align__(16) float d_part[SPLITS*NPTS*68];
__device__ float d_G   [66*NPTS];
__device__ float d_sh  [NLR*6];
__device__ float d_eb  [2*NLR];
__device__ float d_w3j [W3J_TOTAL];
__device__ float d_coef[2*8*3];

__constant__ int PATH_L[14][3] = {
  {4,0,4},{4,2,4},{6,2,4},{6,0,6},{4,2,6},{6,2,6},
  {4,4,4},{4,6,4},{6,4,4},{6,6,4},{4,4,6},{4,6,6},{6,4,6},{6,6,6}};
__constant__ int PATH_OFF[15] = {
  0,81,486,1071,1240,1825,2670,3399,4452,5505,7026,8079,9600,11121,13318};

// ---------------- tf32 helpers ----------------
__device__ __forceinline__ unsigned tf32bits(float x){
  unsigned u;
  asm("cvt.rna.tf32.f32 %0, %1;" : "=r"(u) : "f"(x));
  return u;
}
__device__ __forceinline__ float tf32r(float x){
  return __uint_as_float(tf32bits(x));
}
__device__ __forceinline__ void mma_tf32(float* c,
    unsigned a0, unsigned a1, unsigned a2, unsigned a3,
    unsigned b0, unsigned b1){
  asm volatile(
    "mma.sync.aligned.m16n8k8.row.col.f32.tf32.tf32.f32 "
    "{%0,%1,%2,%3}, {%4,%5,%6,%7}, {%8,%9}, {%0,%1,%2,%3};"
    : "+f"(c[0]), "+f"(c[1]), "+f"(c[2]), "+f"(c[3])
    : "r"(a0), "r"(a1), "r"(a2), "r"(a3), "r"(b0), "r"(b1));
}

// ---------------- W3J (real Wigner/CG) ----------------
struct Cpx { double re, im; };

__device__ __forceinline__ double dev_cg(int j1,int m1,int j2,int m2,int j3,int m3,const double* f){
  if (m1+m2 != m3) return 0.0;
  if (j3 < abs(j1-j2) || j3 > j1+j2) return 0.0;
  double pref = sqrt((2.0*j3+1.0)*f[j3+j1-j2]*f[j3-j1+j2]*f[j1+j2-j3]/f[j1+j2+j3+1]);
  pref *= sqrt(f[j3+m3]*f[j3-m3]*f[j1-m1]*f[j1+m1]*f[j2-m2]*f[j2+m2]);
  double s = 0.0;
  int kmax = j1+j2-j3;
  for (int k=0;k<=kmax;k++){
    int a3=j1-m1-k, a4=j2+m2-k, a5=j3-j2+m1+k, a6=j3-j1-m2+k;
    if (a3<0||a4<0||a5<0||a6<0) continue;
    double t = 1.0/(f[k]*f[kmax-k]*f[a3]*f[a4]*f[a5]*f[a6]);
    s += (k&1)? -t : t;
  }
  return pref*s;
}

__device__ __forceinline__ int unz(int l, int r, int* cols, Cpx* vals){
  const double s2 = 0.70710678118654752440;
  if (r == l){ cols[0]=l; vals[0]=Cpx{1.0,0.0}; return 1; }
  if (r > l){ int m=r-l; double sg=(m&1)?-1.0:1.0;
    cols[0]=l+m; vals[0]=Cpx{sg*s2,0.0};
    cols[1]=l-m; vals[1]=Cpx{s2,0.0}; return 2; }
  int m=l-r; double sg=(m&1)?-1.0:1.0;
  cols[0]=l-m; vals[0]=Cpx{0.0,s2};
  cols[1]=l+m; vals[1]=Cpx{0.0,-sg*s2}; return 2;
}

__device__ __forceinline__ Cpx uent(int l,int r,int c){
  const double s2 = 0.70710678118654752440;
  Cpx z = Cpx{0.0,0.0};
  if (r==l){ if (c==l) z = Cpx{1.0,0.0}; return z; }
  if (r>l){ int m=r-l; double sg=(m&1)?-1.0:1.0;
    if (c==l+m) z = Cpx{sg*s2,0.0}; else if (c==l-m) z = Cpx{s2,0.0}; return z; }
  int m=l-r; double sg=(m&1)?-1.0:1.0;
  if (c==l-m) z = Cpx{0.0,s2}; else if (c==l+m) z = Cpx{0.0,-sg*s2};
  return z;
}

__global__ void k_w3j(){
  int path = blockIdx.x;
  int l1=PATH_L[path][0], l2=PATH_L[path][1], l3=PATH_L[path][2];
  int d1=2*l1+1, d2=2*l2+1, d3=2*l3+1;
  int off=PATH_OFF[path];
  int total=d1*d2*d3;
  __shared__ double Cc[169];
  __shared__ double red[256];
  int tid=threadIdx.x;
  double fct[20]; fct[0]=1.0;
  for (int i=1;i<20;i++) fct[i]=fct[i-1]*(double)i;
  for (int e=tid; e<d1*d2; e+=256){
    int a=e/d2, b=e%d2;
    int m1=a-l1, m2=b-l2, m3=m1+m2;
    Cc[e] = (abs(m3)<=l3) ? dev_cg(l1,m1,l2,m2,l3,m3,fct) : 0.0;
  }
  __syncthreads();
  double tv[9]; double ss=0.0; int cnt=0;
  for (int e=tid; e<total; e+=256){
    int i=e/(d2*d3); int j=(e/d3)%d2; int k=e%d3;
    int c1[2], c2[2]; Cpx u1[2], u2[2];
    int n1 = unz(l1,i,c1,u1);
    int n2 = unz(l2,j,c2,u2);
    double re=0.0;
    for (int ii=0;ii<n1;ii++)
      for (int jj=0;jj<n2;jj++){
        int c = c1[ii]-l1 + c2[jj]-l2 + l3;
        if (c<0 || c>2*l3) continue;
        Cpx u3 = uent(l3,k,c);
        if (u3.re==0.0 && u3.im==0.0) continue;
        double cgv = Cc[c1[ii]*d2 + c2[jj]];
        if (cgv==0.0) continue;
        double pr = u1[ii].re*u2[jj].re - u1[ii].im*u2[jj].im;
        double pi = u1[ii].re*u2[jj].im + u1[ii].im*u2[jj].re;
        re += (pr*u3.re + pi*u3.im)*cgv;
      }
    tv[cnt++]=re; ss+=re*re;
  }
  red[tid]=ss; __syncthreads();
  for (int s=128;s>0;s>>=1){ if (tid<s) red[tid]+=red[tid+s]; __syncthreads(); }
  double rnorm = rsqrt(red[0]);
  cnt=0;
  for (int e=tid; e<total; e+=256) d_w3j[off+e] = (float)(tv[cnt++]*rnorm);
}

// ---------------- spherical harmonics + exp(key bias) ----------------
__global__ void k_sh(const float* __restrict__ pbw, const float* __restrict__ pbb){
  int n = blockIdx.x*256 + threadIdx.x;
  if (n>=NLR) return;
  int h=n>>6, w=n&63;
  double y = -1.0 + 2.0*(double)h/63.0;
  double x = -1.0 + 2.0*(double)w/63.0;
  double r = sqrt(x*x+y*y); if (r < 1e-8) r = 1e-8;
  double xn=x/r, yn=y/r;
  const double c0=0.28209479177387814, c2=1.0925484305920792, c20=0.31539156525252005;
  float sh[6];
  sh[0]=(float)c0;
  sh[1]=(float)(c2*xn*yn);
  sh[2]=0.0f;
  sh[3]=(float)(-c20);
  sh[4]=0.0f;
  sh[5]=(float)(0.5*c2*(xn*xn-yn*yn));
  #pragma unroll
  for (int i=0;i<6;i++) d_sh[n*6+i]=sh[i];
  for (int blk=0;blk<2;blk++){
    float b = pbb[blk];
    #pragma unroll
    for (int i=0;i<6;i++) b = fmaf(sh[i], pbw[blk*6+i], b);
    d_eb[blk*NLR+n]=expf(b);
  }
}

// ---------------- coefficient precompute ----------------
__global__ void k_coef(const float* __restrict__ liw4, const float* __restrict__ liw6,
                       const float* __restrict__ tvw,  const float* __restrict__ tow,
                       const float* __restrict__ low4, const float* __restrict__ low6){
  __shared__ float a_s[96];
  int tid = threadIdx.x;
  if (tid < 96){
    int c = tid & 7; int pp = (tid>>3)%6; int blk = tid/48;
    const float* liw = (pp==0||pp==1||pp==4) ? (liw4+blk*8) : (liw6+blk*8);
    float s=0.f;
    for (int u=0;u<8;u++) s = fmaf(liw[u], tvw[((blk*6+pp)*8+u)*8 + c], s);
    a_s[tid]=s;
  }
  __syncthreads();
  if (tid < 16){
    int q = tid&7, blk = tid>>3;
    const float* liw = (q==0||q==1||q==4||q==5)? (liw4+blk*8) : (liw6+blk*8);
    const float* low = (q<4)? (low4+blk*8) : (low6+blk*8);
    float b[8];
    #pragma unroll
    for (int v=0;v<8;v++){
      float s=0.f;
      for (int u=0;u<8;u++){
        float lu = liw[u];
        for (int w=0;w<8;w++)
          s = fmaf(lu*tow[(((blk*8+q)*8+u)*8+v)*8+w], low[w], s);
      }
      b[v]=s;
    }
    int pbase = (q&1)? 3 : 0;
    const float invs = (1.0f/sqrtf(24.0f)) * (1.0f/16.0f) * (1.0f/sqrtf(8.0f));
    for (int pp=0;pp<3;pp++){
      float s=0.f;
      #pragma unroll
      for (int v=0;v<8;v++) s = fmaf(b[v], a_s[(blk*6+pbase+pp)*8 + v], s);
      d_coef[(blk*8+q)*3+pp] = s*invs;
    }
  }
}

// ---------------- feature init ----------------
__global__ void k_featinit(const float* __restrict__ f4, const float* __restrict__ f6){
  int p = blockIdx.x*256 + threadIdx.x;
  if (p>=NPTS) return;
  #pragma unroll
  for (int i=0;i<9;i++)  d_feat0[p*22+i]   = f4[p*9+i];
  #pragma unroll
  for (int j=0;j<13;j++) d_feat0[p*22+9+j] = f6[p*13+j];
}

// ---------------- per-point prep: qT, kT, value tensors g (eb folded, tf32) --
__global__ void __launch_bounds__(128) k_prepare(const float* __restrict__ ls4,
                                                 const float* __restrict__ ls6,
                                                 int blk, int sel){
  const float* fin = sel ? d_feat1 : d_feat0;
  __shared__ float wv[W3J_OUT_OFF];
  int tid = threadIdx.x;
  for (int i=tid;i<W3J_OUT_OFF;i+=128) wv[i]=d_w3j[i];
  __syncthreads();
  int p = blockIdx.x*128 + tid;
  float f[22];
  float s4=0.f, s6=0.f;
  #pragma unroll
  for (int i=0;i<9;i++){ f[i]=fin[p*22+i]; s4=fmaf(f[i],f[i],s4); }
  #pragma unroll
  for (int i=9;i<22;i++){ f[i]=fin[p*22+i]; s6=fmaf(f[i],f[i],s6); }
  float inv4=1.f/fmaxf(sqrtf(s4),1e-12f);
  float inv6=1.f/fmaxf(sqrtf(s6),1e-12f);
  float e4=expf(ls4[blk]), e6=expf(ls6[blk]);
  #pragma unroll
  for (int i=0;i<9;i++){ float kk=f[i]*inv4; d_kvT[i*NPTS+p]=kk; d_qvT[i*NPTS+p]=kk*e4; }
  #pragma unroll
  for (int i=9;i<22;i++){ float kk=f[i]*inv6; d_kvT[i*NPTS+p]=kk; d_qvT[i*NPTS+p]=kk*e6; }
  int n = p & (NLR-1);
  float ebv = d_eb[blk*NLR+n];
  float sh0=d_sh[n*6];
  float sh2[5];
  #pragma unroll
  for (int j=0;j<5;j++) sh2[j]=d_sh[n*6+1+j];
  float* g = d_gv + (size_t)p*GST;
  { float a[9];
    #pragma unroll
    for (int k=0;k<9;k++) a[k]=0.f;
    #pragma unroll 1
    for (int i=0;i<9;i++){ float fi=f[i];
      #pragma unroll
      for (int k=0;k<9;k++) a[k]=fmaf(fi,wv[i*9+k],a[k]); }
    #pragma unroll
    for (int k=0;k<9;k++) g[k]=tf32r(a[k]*sh0*ebv); }
  { float a[9];
    #pragma unroll
    for (int k=0;k<9;k++) a[k]=0.f;
    #pragma unroll 1
    for (int i=0;i<9;i++){ float fi=f[i];
      #pragma unroll 1
      for (int j=0;j<5;j++){ float c=fi*sh2[j];
        #pragma unroll
        for (int k=0;k<9;k++) a[k]=fmaf(c,wv[81+(i*5+j)*9+k],a[k]); } }
    #pragma unroll
    for (int k=0;k<9;k++) g[9+k]=tf32r(a[k]*ebv); }
  { float a[9];
    #pragma unroll
    for (int k=0;k<9;k++) a[k]=0.f;
    #pragma unroll 1
    for (int i=0;i<13;i++){ float fi=f[9+i];
      #pragma unroll 1
      for (int j=0;j<5;j++){ float c=fi*sh2[j];
        #pragma unroll
        for (int k=0;k<9;k++) a[k]=fmaf(c,wv[486+(i*5+j)*9+k],a[k]); } }
    #pragma unroll
    for (int k=0;k<9;k++) g[18+k]=tf32r(a[k]*ebv); }
  { float a[13];
    #pragma unroll
    for (int k=0;k<13;k++) a[k]=0.f;
    #pragma unroll 1
    for (int i=0;i<13;i++){ float fi=f[9+i];
      #pragma unroll
      for (int k=0;k<13;k++) a[k]=fmaf(fi,wv[1071+i*13+k],a[k]); }
    #pragma unroll
    for (int k=0;k<13;k++) g[27+k]=tf32r(a[k]*sh0*ebv); }
  { float a[13];
    #pragma unroll
    for (int k=0;k<13;k++) a[k]=0.f;
    #pragma unroll 1
    for (int i=0;i<9;i++){ float fi=f[i];
      #pragma unroll 1
      for (int j=0;j<5;j++){ float c=fi*sh2[j];
        #pragma unroll
        for (int k=0;k<13;k++) a[k]=fmaf(c,wv[1240+(i*5+j)*13+k],a[k]); } }
    #pragma unroll
    for (int k=0;k<13;k++) g[40+k]=tf32r(a[k]*ebv); }
  { float a[13];
    #pragma unroll
    for (int k=0;k<13;k++) a[k]=0.f;
    #pragma unroll 1
    for (int i=0;i<13;i++){ float fi=f[9+i];
      #pragma unroll 1
      for (int j=0;j<5;j++){ float c=fi*sh2[j];
        #pragma unroll
        for (int k=0;k<13;k++) a[k]=fmaf(c,wv[1825+(i*5+j)*13+k],a[k]); } }
    #pragma unroll
    for (int k=0;k<13;k++) g[53+k]=tf32r(a[k]*ebv); }
  g[66]=tf32r(ebv);
  #pragma unroll
  for (int k=67;k<GST;k++) g[k]=0.f;
}

// ---------------- attention: full-HMMA (tf32 split QK + tf32 PV) ----------
// CTA: 128 rows x 256 keys (8 tiles of KT=32). 256 threads, 8 warps.
// Warp w owns rows [16w,16w+16). QK: S = QK^T via m16n8k8 with 2-term
// compensated tf32 split (hi*hi + hi*lo + lo*hi). The QK D-fragment feeds the
// PV A-fragment directly (key order internal; G rows addressed as 2lj,2lj+1).
__global__ void __launch_bounds__(256,3) k_attn(){
  __shared__ float Qs[24*RT];      // 3072 f (rows 22,23 zero)
  __shared__ float Ks[KT*KST];     // 896 f  [key][kd], kd padded to 28
  __shared__ float Gs[KT*GST];     // 2432 f
  const int tid = threadIdx.x;
  const int w = tid>>5, l = tid&31;
  const int batch = blockIdx.y, split = blockIdx.z;
  const int prow = batch*NLR + blockIdx.x*RT;

  for (int i=tid;i<24*RT;i+=256){
    int kd=i>>7, r=i&127;
    Qs[i] = (kd<22)? d_qvT[kd*NPTS + prow + r] : 0.f;
  }
  __syncthreads();

  const int r0 = 16*w + (l>>2);
  const int lj = l & 3;
  // Q fragments (hi/lo) for 3 k-steps — Q invariant across key tiles
  unsigned qh[3][4], ql[3][4];
  #pragma unroll
  for (int ks=0;ks<3;ks++){
    float v0 = Qs[(ks*8+lj)*RT + r0];
    float v1 = Qs[(ks*8+lj)*RT + r0+8];
    float v2 = Qs[(ks*8+lj+4)*RT + r0];
    float v3 = Qs[(ks*8+lj+4)*RT + r0+8];
    qh[ks][0]=tf32bits(v0); ql[ks][0]=tf32bits(v0-__uint_as_float(qh[ks][0]));
    qh[ks][1]=tf32bits(v1); ql[ks][1]=tf32bits(v1-__uint_as_float(qh[ks][1]));
    qh[ks][2]=tf32bits(v2); ql[ks][2]=tf32bits(v2-__uint_as_float(qh[ks][2]));
    qh[ks][3]=tf32bits(v3); ql[ks][3]=tf32bits(v3-__uint_as_float(qh[ks][3]));
  }

  float accd[9][4];
  #pragma unroll
  for (int n=0;n<9;n++){
    #pragma unroll
    for (int c=0;c<4;c++) accd[n][c]=0.f;
  }

  const int m0 = split*(NLR/SPLITS);
  const int ntiles = (NLR/SPLITS)/KT;   // 8
  for (int t=0;t<ntiles;t++){
    const int mbase = batch*NLR + m0 + t*KT;
    __syncthreads();
    for (int i=tid;i<KT*KST;i+=256){
      int key=i/KST, kd=i-key*KST;
      Ks[i] = (kd<22)? d_kvT[kd*NPTS + mbase + key] : 0.f;
    }
    for (int i=tid;i<KT*(GST/4);i+=256){
      int key=i/(GST/4), c4=i-key*(GST/4);
      *(float4*)(Gs + key*GST + c4*4) =
        *(const float4*)(d_gv + (size_t)(mbase+key)*GST + c4*4);
    }
    __syncthreads();
    #pragma unroll
    for (int kg=0;kg<4;kg++){
      float sc[4];
      sc[0]=0.f; sc[1]=0.f; sc[2]=0.f; sc[3]=0.f;
      const int krow = (kg*8 + (l>>2))*KST;
      #pragma unroll
      for (int ks=0;ks<3;ks++){
        float b0f = Ks[krow + ks*8 + lj];
        float b1f = Ks[krow + ks*8 + lj + 4];
        unsigned b0h = tf32bits(b0f);
        unsigned b1h = tf32bits(b1f);
        unsigned b0l = tf32bits(b0f - __uint_as_float(b0h));
        unsigned b1l = tf32bits(b1f - __uint_as_float(b1h));
        mma_tf32(sc, qh[ks][0],qh[ks][1],qh[ks][2],qh[ks][3], b0h,b1h);
        mma_tf32(sc, qh[ks][0],qh[ks][1],qh[ks][2],qh[ks][3], b0l,b1l);
        mma_tf32(sc, ql[ks][0],ql[ks][1],ql[ks][2],ql[ks][3], b0h,b1h);
      }
      unsigned a0 = tf32bits(__expf(sc[0]));
      unsigned a1 = tf32bits(__expf(sc[2]));
      unsigned a2 = tf32bits(__expf(sc[1]));
      unsigned a3 = tf32bits(__expf(sc[3]));
      const int gr0 = (kg*8 + 2*lj)*GST;
      const int gr1 = gr0 + GST;
      const int ncol = (l>>2);
      #pragma unroll
      for (int n=0;n<9;n++){
        unsigned b0 = __float_as_uint(Gs[gr0 + n*8 + ncol]);
        unsigned b1 = __float_as_uint(Gs[gr1 + n*8 + ncol]);
        mma_tf32(accd[n], a0,a1,a2,a3, b0,b1);
      }
    }
  }
  {
    const int p0 = prow + r0;
    const int p1 = p0 + 8;
    float* base0 = d_part + ((size_t)split*NPTS + p0)*68;
    float* base1 = d_part + ((size_t)split*NPTS + p1)*68;
    #pragma unroll
    for (int n=0;n<9;n++){
      int col = n*8 + 2*lj;
      if (col < 68){
        *(float2*)(base0 + col) = make_float2(accd[n][0], accd[n][1]);
        *(float2*)(base1 + col) = make_float2(accd[n][2], accd[n][3]);
      }
    }
  }
}

// ---------------- split reduce + transpose to [c][p] ----------------
__global__ void k_reduce(){
  int p = blockIdx.x*128 + threadIdx.x;
  if (p>=NPTS) return;
  float accv[68];
  #pragma unroll
  for (int i=0;i<68;i++) accv[i]=0.f;
  #pragma unroll 4
  for (int sp=0;sp<SPLITS;sp++){
    const float4* b = (const float4*)(d_part + ((size_t)sp*NPTS+p)*68);
    #pragma unroll
    for (int i=0;i<17;i++){
      float4 v=b[i];
      accv[i*4+0]+=v.x; accv[i*4+1]+=v.y; accv[i*4+2]+=v.z; accv[i*4+3]+=v.w;
    }
  }
  float inv = 1.f/accv[66];
  #pragma unroll 1
  for (int c=0;c<66;c++) d_G[c*NPTS+p] = accv[c]*inv;
}

// ---------------- per-point output tensor products ----------------
template<int D1,int D2,int D3>
__device__ __forceinline__ void qpath(const float* __restrict__ w3, const float* __restrict__ f,
                                      int p, float c0, float c1, float c2,
                                      int g0, int g1, int g2, float* out){
  #pragma unroll 1
  for (int j=0;j<D2;j++){
    float gm = c0*d_G[(g0+j)*NPTS+p] + c1*d_G[(g1+j)*NPTS+p] + c2*d_G[(g2+j)*NPTS+p];
    #pragma unroll
    for (int i=0;i<D1;i++){
      float cf = gm*f[i];
      #pragma unroll
      for (int k=0;k<D3;k++) out[k] = fmaf(cf, w3[(i*D2+j)*D3+k], out[k]);
    }
  }
}

__global__ void __launch_bounds__(256) k_output(int blk, int sel){
  const float* fin = sel ? d_feat1 : d_feat0;
  float* fout = sel ? d_feat0 : d_feat1;
  __shared__ float w3s[6292];
  int tid = threadIdx.x;
  int half = blockIdx.y;
  int base = half ? 7026 : 2670;
  int len  = half ? 6292 : 4356;
  for (int i=tid;i<len;i+=256) w3s[i]=d_w3j[base+i];
  __syncthreads();
  int p = blockIdx.x*256 + tid;
  float f4[9], f6[13];
  #pragma unroll
  for (int i=0;i<9;i++) f4[i]=fin[p*22+i];
  #pragma unroll
  for (int i=0;i<13;i++) f6[i]=fin[p*22+9+i];
  const float* cf = d_coef + blk*24;
  if (half==0){
    float d4[9];
    #pragma unroll
    for (int k=0;k<9;k++) d4[k]=0.f;
    qpath<9,9,9>   (w3s+0,    f4, p, cf[0], cf[1], cf[2],  0, 9,18, d4);
    qpath<9,13,9>  (w3s+729,  f4, p, cf[3], cf[4], cf[5], 27,40,53, d4);
    qpath<13,9,9>  (w3s+1782, f6, p, cf[6], cf[7], cf[8],  0, 9,18, d4);
    qpath<13,13,9> (w3s+2835, f6, p, cf[9], cf[10],cf[11],27,40,53, d4);
    #pragma unroll
    for (int k=0;k<9;k++) fout[p*22+k] = f4[k]+d4[k];
  } else {
    float d6[13];
    #pragma unroll
    for (int k=0;k<13;k++) d6[k]=0.f;
    qpath<9,9,13>  (w3s+0,    f4, p, cf[12],cf[13],cf[14], 0, 9,18, d6);
    qpath<9,13,13> (w3s+1053, f4, p, cf[15],cf[16],cf[17],27,40,53, d6);
    qpath<13,9,13> (w3s+2574, f6, p, cf[18],cf[19],cf[20], 0, 9,18, d6);
    qpath<13,13,13>(w3s+4095, f6, p, cf[21],cf[22],cf[23],27,40,53, d6);
    #pragma unroll
    for (int k=0;k<13;k++) fout[p*22+9+k] = f6[k]+d6[k];
  }
}

// ---------------- upsample ----------------
__global__ void k_upsample(const float* __restrict__ upw, float* __restrict__ out){
  int idx = blockIdx.x*256 + threadIdx.x;
  if (idx >= NBATCH*65536) return;
  int b = idx >> 16;
  int nh = idx & 65535;
  int rw = nh & 3; int t = nh >> 2; int w = t & 63; t >>= 6; int rh = t & 3; int h = t >> 2;
  int p = b*NLR + h*64 + w;
  float u4 = upw[(rh*4+rw)*2 + 0];
  float u6 = upw[(rh*4+rw)*2 + 1];
  float* o4 = out + (size_t)idx*9;
  float* o6 = out + 1179648 + (size_t)idx*13;
  #pragma unroll
  for (int k=0;k<9;k++)  o4[k] = d_feat0[p*22+k]*u4;
  #pragma unroll
  for (int k=0;k<13;k++) o6[k] = d_feat0[p*22+9+k]*u6;
}

extern "C" void kernel_launch(void* const* d_in, const int* in_sizes, int n_in,
                              void* d_out, int out_size) {
  const float* f4   = (const float*)d_in[0];
  const float* f6   = (const float*)d_in[1];
  const float* ls4  = (const float*)d_in[2];
  const float* ls6  = (const float*)d_in[3];
  const float* pbw  = (const float*)d_in[4];
  const float* pbb  = (const float*)d_in[5];
  const float* liw4 = (const float*)d_in[6];
  const float* liw6 = (const float*)d_in[7];
  const float* tvw  = (const float*)d_in[8];
  const float* tow  = (const float*)d_in[9];
  const float* low4 = (const float*)d_in[10];
  const float* low6 = (const float*)d_in[11];
  const float* upw  = (const float*)d_in[12];
  float* out = (float*)d_out;

  k_w3j<<<14,256>>>();
  k_sh<<<16,256>>>(pbw, pbb);
  k_coef<<<1,128>>>(liw4, liw6, tvw, tow, low4, low6);
  k_featinit<<<32,256>>>(f4, f6);
  for (int blk=0; blk<2; blk++){
    k_prepare<<<64,128>>>(ls4, ls6, blk, blk&1);
    k_attn<<<dim3(NLR/RT, NBATCH, SPLITS), 256>>>();
    k_reduce<<<NPTS/128,128>>>();
    k_output<<<dim3(32,2),256>>>(blk, blk&1);
  }
  k_upsample<<<512,256>>>(upw, out);
}

// round 12
// speedup vs baseline: 1.9865x; 1.0749x over previous
#include <cuda_runtime.h>
#include <cuda_bf16.h>
#include <math.h>

#define NBATCH 2
#define NLR    4096
#define NPTS   (NBATCH*NLR)
#define SPLITS 16
#define KT     32
#define RT     128
#define GST    76
#define KST    28

#define W3J_TOTAL   13318
#define W3J_OUT_OFF 2670

__device__ float d_feat0[NPTS*22];
__device__ float d_feat1[NPTS*22];
__device__ float d_qvT[22*NPTS];
__device__ __align__(16) float d_kv[NPTS*KST];
__device__ __align__(16) float d_gv  [NPTS*GST];
__device__ __align__(16) float d_part[SPLITS*NPTS*68];
__device__ float d_G   [66*NPTS];
__device__ float d_sh  [NLR*6];
__device__ float d_eb  [2*NLR];
__device__ float d_w3j [W3J_TOTAL];
__device__ float d_coef[2*8*3];

__constant__ int PATH_L[14][3] = {
  {4,0,4},{4,2,4},{6,2,4},{6,0,6},{4,2,6},{6,2,6},
  {4,4,4},{4,6,4},{6,4,4},{6,6,4},{4,4,6},{4,6,6},{6,4,6},{6,6,6}};
__constant__ int PATH_OFF[15] = {
  0,81,486,1071,1240,1825,2670,3399,4452,5505,7026,8079,9600,11121,13318};

// ---------------- tf32 helpers ----------------
__device__ __forceinline__ unsigned tf32bits(float x){
  unsigned u;
  asm("cvt.rna.tf32.f32 %0, %1;" : "=r"(u) : "f"(x));
  return u;
}
__device__ __forceinline__ float tf32r(float x){
  return __uint_as_float(tf32bits(x));
}
__device__ __forceinline__ void mma_tf32(float* c,
    unsigned a0, unsigned a1, unsigned a2, unsigned a3,
    unsigned b0, unsigned b1){
  asm volatile(
    "mma.sync.aligned.m16n8k8.row.col.f32.tf32.tf32.f32 "
    "{%0,%1,%2,%3}, {%4,%5,%6,%7}, {%8,%9}, {%0,%1,%2,%3};"
    : "+f"(c[0]), "+f"(c[1]), "+f"(c[2]), "+f"(c[3])
    : "r"(a0), "r"(a1), "r"(a2), "r"(a3), "r"(b0), "r"(b1));
}

// ---------------- W3J (real Wigner/CG) ----------------
struct Cpx { double re, im; };

__device__ __forceinline__ double dev_cg(int j1,int m1,int j2,int m2,int j3,int m3,const double* f){
  if (m1+m2 != m3) return 0.0;
  if (j3 < abs(j1-j2) || j3 > j1+j2) return 0.0;
  double pref = sqrt((2.0*j3+1.0)*f[j3+j1-j2]*f[j3-j1+j2]*f[j1+j2-j3]/f[j1+j2+j3+1]);
  pref *= sqrt(f[j3+m3]*f[j3-m3]*f[j1-m1]*f[j1+m1]*f[j2-m2]*f[j2+m2]);
  double s = 0.0;
  int kmax = j1+j2-j3;
  for (int k=0;k<=kmax;k++){
    int a3=j1-m1-k, a4=j2+m2-k, a5=j3-j2+m1+k, a6=j3-j1-m2+k;
    if (a3<0||a4<0||a5<0||a6<0) continue;
    double t = 1.0/(f[k]*f[kmax-k]*f[a3]*f[a4]*f[a5]*f[a6]);
    s += (k&1)? -t : t;
  }
  return pref*s;
}

__device__ __forceinline__ int unz(int l, int r, int* cols, Cpx* vals){
  const double s2 = 0.70710678118654752440;
  if (r == l){ cols[0]=l; vals[0]=Cpx{1.0,0.0}; return 1; }
  if (r > l){ int m=r-l; double sg=(m&1)?-1.0:1.0;
    cols[0]=l+m; vals[0]=Cpx{sg*s2,0.0};
    cols[1]=l-m; vals[1]=Cpx{s2,0.0}; return 2; }
  int m=l-r; double sg=(m&1)?-1.0:1.0;
  cols[0]=l-m; vals[0]=Cpx{0.0,s2};
  cols[1]=l+m; vals[1]=Cpx{0.0,-sg*s2}; return 2;
}

__device__ __forceinline__ Cpx uent(int l,int r,int c){
  const double s2 = 0.70710678118654752440;
  Cpx z = Cpx{0.0,0.0};
  if (r==l){ if (c==l) z = Cpx{1.0,0.0}; return z; }
  if (r>l){ int m=r-l; double sg=(m&1)?-1.0:1.0;
    if (c==l+m) z = Cpx{sg*s2,0.0}; else if (c==l-m) z = Cpx{s2,0.0}; return z; }
  int m=l-r; double sg=(m&1)?-1.0:1.0;
  if (c==l-m) z = Cpx{0.0,s2}; else if (c==l+m) z = Cpx{0.0,-sg*s2};
  return z;
}

__global__ void k_w3j(){
  int path = blockIdx.x;
  int l1=PATH_L[path][0], l2=PATH_L[path][1], l3=PATH_L[path][2];
  int d1=2*l1+1, d2=2*l2+1, d3=2*l3+1;
  int off=PATH_OFF[path];
  int total=d1*d2*d3;
  __shared__ double Cc[169];
  __shared__ double red[256];
  int tid=threadIdx.x;
  double fct[20]; fct[0]=1.0;
  for (int i=1;i<20;i++) fct[i]=fct[i-1]*(double)i;
  for (int e=tid; e<d1*d2; e+=256){
    int a=e/d2, b=e%d2;
    int m1=a-l1, m2=b-l2, m3=m1+m2;
    Cc[e] = (abs(m3)<=l3) ? dev_cg(l1,m1,l2,m2,l3,m3,fct) : 0.0;
  }
  __syncthreads();
  double tv[9]; double ss=0.0; int cnt=0;
  for (int e=tid; e<total; e+=256){
    int i=e/(d2*d3); int j=(e/d3)%d2; int k=e%d3;
    int c1[2], c2[2]; Cpx u1[2], u2[2];
    int n1 = unz(l1,i,c1,u1);
    int n2 = unz(l2,j,c2,u2);
    double re=0.0;
    for (int ii=0;ii<n1;ii++)
      for (int jj=0;jj<n2;jj++){
        int c = c1[ii]-l1 + c2[jj]-l2 + l3;
        if (c<0 || c>2*l3) continue;
        Cpx u3 = uent(l3,k,c);
        if (u3.re==0.0 && u3.im==0.0) continue;
        double cgv = Cc[c1[ii]*d2 + c2[jj]];
        if (cgv==0.0) continue;
        double pr = u1[ii].re*u2[jj].re - u1[ii].im*u2[jj].im;
        double pi = u1[ii].re*u2[jj].im + u1[ii].im*u2[jj].re;
        re += (pr*u3.re + pi*u3.im)*cgv;
      }
    tv[cnt++]=re; ss+=re*re;
  }
  red[tid]=ss; __syncthreads();
  for (int s=128;s>0;s>>=1){ if (tid<s) red[tid]+=red[tid+s]; __syncthreads(); }
  double rnorm = rsqrt(red[0]);
  cnt=0;
  for (int e=tid; e<total; e+=256) d_w3j[off+e] = (float)(tv[cnt++]*rnorm);
}

// ---------------- spherical harmonics + exp(key bias) ----------------
__global__ void k_sh(const float* __restrict__ pbw, const float* __restrict__ pbb){
  int n = blockIdx.x*256 + threadIdx.x;
  if (n>=NLR) return;
  int h=n>>6, w=n&63;
  double y = -1.0 + 2.0*(double)h/63.0;
  double x = -1.0 + 2.0*(double)w/63.0;
  double r = sqrt(x*x+y*y); if (r < 1e-8) r = 1e-8;
  double xn=x/r, yn=y/r;
  const double c0=0.28209479177387814, c2=1.0925484305920792, c20=0.31539156525252005;
  float sh[6];
  sh[0]=(float)c0;
  sh[1]=(float)(c2*xn*yn);
  sh[2]=0.0f;
  sh[3]=(float)(-c20);
  sh[4]=0.0f;
  sh[5]=(float)(0.5*c2*(xn*xn-yn*yn));
  #pragma unroll
  for (int i=0;i<6;i++) d_sh[n*6+i]=sh[i];
  for (int blk=0;blk<2;blk++){
    float b = pbb[blk];
    #pragma unroll
    for (int i=0;i<6;i++) b = fmaf(sh[i], pbw[blk*6+i], b);
    d_eb[blk*NLR+n]=expf(b);
  }
}

// ---------------- coefficient precompute ----------------
__global__ void k_coef(const float* __restrict__ liw4, const float* __restrict__ liw6,
                       const float* __restrict__ tvw,  const float* __restrict__ tow,
                       const float* __restrict__ low4, const float* __restrict__ low6){
  __shared__ float a_s[96];
  int tid = threadIdx.x;
  if (tid < 96){
    int c = tid & 7; int pp = (tid>>3)%6; int blk = tid/48;
    const float* liw = (pp==0||pp==1||pp==4) ? (liw4+blk*8) : (liw6+blk*8);
    float s=0.f;
    for (int u=0;u<8;u++) s = fmaf(liw[u], tvw[((blk*6+pp)*8+u)*8 + c], s);
    a_s[tid]=s;
  }
  __syncthreads();
  if (tid < 16){
    int q = tid&7, blk = tid>>3;
    const float* liw = (q==0||q==1||q==4||q==5)? (liw4+blk*8) : (liw6+blk*8);
    const float* low = (q<4)? (low4+blk*8) : (low6+blk*8);
    float b[8];
    #pragma unroll
    for (int v=0;v<8;v++){
      float s=0.f;
      for (int u=0;u<8;u++){
        float lu = liw[u];
        for (int w=0;w<8;w++)
          s = fmaf(lu*tow[(((blk*8+q)*8+u)*8+v)*8+w], low[w], s);
      }
      b[v]=s;
    }
    int pbase = (q&1)? 3 : 0;
    const float invs = (1.0f/sqrtf(24.0f)) * (1.0f/16.0f) * (1.0f/sqrtf(8.0f));
    for (int pp=0;pp<3;pp++){
      float s=0.f;
      #pragma unroll
      for (int v=0;v<8;v++) s = fmaf(b[v], a_s[(blk*6+pbase+pp)*8 + v], s);
      d_coef[(blk*8+q)*3+pp] = s*invs;
    }
  }
}

// ---------------- feature init ----------------
__global__ void k_featinit(const float* __restrict__ f4, const float* __restrict__ f6){
  int p = blockIdx.x*256 + threadIdx.x;
  if (p>=NPTS) return;
  #pragma unroll
  for (int i=0;i<9;i++)  d_feat0[p*22+i]   = f4[p*9+i];
  #pragma unroll
  for (int j=0;j<13;j++) d_feat0[p*22+9+j] = f6[p*13+j];
}

// ---------------- per-point prep: qT, k row-major, value tensors g --------
__global__ void __launch_bounds__(128) k_prepare(const float* __restrict__ ls4,
                                                 const float* __restrict__ ls6,
                                                 int blk, int sel){
  const float* fin = sel ? d_feat1 : d_feat0;
  __shared__ float wv[W3J_OUT_OFF];
  int tid = threadIdx.x;
  for (int i=tid;i<W3J_OUT_OFF;i+=128) wv[i]=d_w3j[i];
  __syncthreads();
  int p = blockIdx.x*128 + tid;
  float f[22];
  float s4=0.f, s6=0.f;
  #pragma unroll
  for (int i=0;i<9;i++){ f[i]=fin[p*22+i]; s4=fmaf(f[i],f[i],s4); }
  #pragma unroll
  for (int i=9;i<22;i++){ f[i]=fin[p*22+i]; s6=fmaf(f[i],f[i],s6); }
  float inv4=1.f/fmaxf(sqrtf(s4),1e-12f);
  float inv6=1.f/fmaxf(sqrtf(s6),1e-12f);
  float e4=expf(ls4[blk]), e6=expf(ls6[blk]);
  {
    float kvloc[KST];
    #pragma unroll
    for (int i=0;i<9;i++){ float kk=f[i]*inv4; kvloc[i]=kk; d_qvT[i*NPTS+p]=kk*e4; }
    #pragma unroll
    for (int i=9;i<22;i++){ float kk=f[i]*inv6; kvloc[i]=kk; d_qvT[i*NPTS+p]=kk*e6; }
    #pragma unroll
    for (int i=22;i<KST;i++) kvloc[i]=0.f;
    float4* dst = (float4*)(d_kv + (size_t)p*KST);
    #pragma unroll
    for (int j=0;j<KST/4;j++)
      dst[j] = make_float4(kvloc[j*4],kvloc[j*4+1],kvloc[j*4+2],kvloc[j*4+3]);
  }
  int n = p & (NLR-1);
  float ebv = d_eb[blk*NLR+n];
  float sh0=d_sh[n*6];
  float sh2[5];
  #pragma unroll
  for (int j=0;j<5;j++) sh2[j]=d_sh[n*6+1+j];
  float* g = d_gv + (size_t)p*GST;
  { float a[9];
    #pragma unroll
    for (int k=0;k<9;k++) a[k]=0.f;
    #pragma unroll 1
    for (int i=0;i<9;i++){ float fi=f[i];
      #pragma unroll
      for (int k=0;k<9;k++) a[k]=fmaf(fi,wv[i*9+k],a[k]); }
    #pragma unroll
    for (int k=0;k<9;k++) g[k]=tf32r(a[k]*sh0*ebv); }
  { float a[9];
    #pragma unroll
    for (int k=0;k<9;k++) a[k]=0.f;
    #pragma unroll 1
    for (int i=0;i<9;i++){ float fi=f[i];
      #pragma unroll 1
      for (int j=0;j<5;j++){ float c=fi*sh2[j];
        #pragma unroll
        for (int k=0;k<9;k++) a[k]=fmaf(c,wv[81+(i*5+j)*9+k],a[k]); } }
    #pragma unroll
    for (int k=0;k<9;k++) g[9+k]=tf32r(a[k]*ebv); }
  { float a[9];
    #pragma unroll
    for (int k=0;k<9;k++) a[k]=0.f;
    #pragma unroll 1
    for (int i=0;i<13;i++){ float fi=f[9+i];
      #pragma unroll 1
      for (int j=0;j<5;j++){ float c=fi*sh2[j];
        #pragma unroll
        for (int k=0;k<9;k++) a[k]=fmaf(c,wv[486+(i*5+j)*9+k],a[k]); } }
    #pragma unroll
    for (int k=0;k<9;k++) g[18+k]=tf32r(a[k]*ebv); }
  { float a[13];
    #pragma unroll
    for (int k=0;k<13;k++) a[k]=0.f;
    #pragma unroll 1
    for (int i=0;i<13;i++){ float fi=f[9+i];
      #pragma unroll
      for (int k=0;k<13;k++) a[k]=fmaf(fi,wv[1071+i*13+k],a[k]); }
    #pragma unroll
    for (int k=0;k<13;k++) g[27+k]=tf32r(a[k]*sh0*ebv); }
  { float a[13];
    #pragma unroll
    for (int k=0;k<13;k++) a[k]=0.f;
    #pragma unroll 1
    for (int i=0;i<9;i++){ float fi=f[i];
      #pragma unroll 1
      for (int j=0;j<5;j++){ float c=fi*sh2[j];
        #pragma unroll
        for (int k=0;k<13;k++) a[k]=fmaf(c,wv[1240+(i*5+j)*13+k],a[k]); } }
    #pragma unroll
    for (int k=0;k<13;k++) g[40+k]=tf32r(a[k]*ebv); }
  { float a[13];
    #pragma unroll
    for (int k=0;k<13;k++) a[k]=0.f;
    #pragma unroll 1
    for (int i=0;i<13;i++){ float fi=f[9+i];
      #pragma unroll 1
      for (int j=0;j<5;j++){ float c=fi*sh2[j];
        #pragma unroll
        for (int k=0;k<13;k++) a[k]=fmaf(c,wv[1825+(i*5+j)*13+k],a[k]); } }
    #pragma unroll
    for (int k=0;k<13;k++) g[53+k]=tf32r(a[k]*ebv); }
  g[66]=tf32r(ebv);
  #pragma unroll
  for (int k=67;k<GST;k++) g[k]=0.f;
}

// ---------------- attention: full-HMMA (tf32 split QK + tf32 PV) ----------
// CTA: 128 rows x 256 keys (8 tiles of KT=32). 256 threads, 8 warps.
// Ks smem layout [key][28] == d_kv global layout -> contiguous float4 fill.
__global__ void __launch_bounds__(256,3) k_attn(){
  __shared__ float Qs[24*RT];      // 3072 f (rows 22,23 zero)
  __shared__ float Ks[KT*KST];     // 896 f  [key][kd]
  __shared__ float Gs[KT*GST];     // 2432 f
  const int tid = threadIdx.x;
  const int w = tid>>5, l = tid&31;
  const int batch = blockIdx.y, split = blockIdx.z;
  const int prow = batch*NLR + blockIdx.x*RT;

  for (int i=tid;i<24*RT;i+=256){
    int kd=i>>7, r=i&127;
    Qs[i] = (kd<22)? d_qvT[kd*NPTS + prow + r] : 0.f;
  }
  __syncthreads();

  const int r0 = 16*w + (l>>2);
  const int lj = l & 3;
  unsigned qh[3][4], ql[3][4];
  #pragma unroll
  for (int ks=0;ks<3;ks++){
    float v0 = Qs[(ks*8+lj)*RT + r0];
    float v1 = Qs[(ks*8+lj)*RT + r0+8];
    float v2 = Qs[(ks*8+lj+4)*RT + r0];
    float v3 = Qs[(ks*8+lj+4)*RT + r0+8];
    qh[ks][0]=tf32bits(v0); ql[ks][0]=tf32bits(v0-__uint_as_float(qh[ks][0]));
    qh[ks][1]=tf32bits(v1); ql[ks][1]=tf32bits(v1-__uint_as_float(qh[ks][1]));
    qh[ks][2]=tf32bits(v2); ql[ks][2]=tf32bits(v2-__uint_as_float(qh[ks][2]));
    qh[ks][3]=tf32bits(v3); ql[ks][3]=tf32bits(v3-__uint_as_float(qh[ks][3]));
  }

  float accd[9][4];
  #pragma unroll
  for (int n=0;n<9;n++){
    #pragma unroll
    for (int c=0;c<4;c++) accd[n][c]=0.f;
  }

  const int m0 = split*(NLR/SPLITS);
  const int ntiles = (NLR/SPLITS)/KT;   // 8
  for (int t=0;t<ntiles;t++){
    const int mbase = batch*NLR + m0 + t*KT;
    __syncthreads();
    { const float4* src = (const float4*)(d_kv + (size_t)mbase*KST);
      float4* dst = (float4*)Ks;
      for (int i=tid;i<KT*(KST/4);i+=256) dst[i]=src[i]; }
    for (int i=tid;i<KT*(GST/4);i+=256){
      int key=i/(GST/4), c4=i-key*(GST/4);
      *(float4*)(Gs + key*GST + c4*4) =
        *(const float4*)(d_gv + (size_t)(mbase+key)*GST + c4*4);
    }
    __syncthreads();
    #pragma unroll
    for (int kg=0;kg<4;kg++){
      float sc[4];
      sc[0]=0.f; sc[1]=0.f; sc[2]=0.f; sc[3]=0.f;
      const int krow = (kg*8 + (l>>2))*KST;
      #pragma unroll
      for (int ks=0;ks<3;ks++){
        float b0f = Ks[krow + ks*8 + lj];
        float b1f = Ks[krow + ks*8 + lj + 4];
        unsigned b0h = tf32bits(b0f);
        unsigned b1h = tf32bits(b1f);
        unsigned b0l = tf32bits(b0f - __uint_as_float(b0h));
        unsigned b1l = tf32bits(b1f - __uint_as_float(b1h));
        mma_tf32(sc, qh[ks][0],qh[ks][1],qh[ks][2],qh[ks][3], b0h,b1h);
        mma_tf32(sc, qh[ks][0],qh[ks][1],qh[ks][2],qh[ks][3], b0l,b1l);
        mma_tf32(sc, ql[ks][0],ql[ks][1],ql[ks][2],ql[ks][3], b0h,b1h);
      }
      unsigned a0 = tf32bits(__expf(sc[0]));
      unsigned a1 = tf32bits(__expf(sc[2]));
      unsigned a2 = tf32bits(__expf(sc[1]));
      unsigned a3 = tf32bits(__expf(sc[3]));
      const int gr0 = (kg*8 + 2*lj)*GST;
      const int gr1 = gr0 + GST;
      const int ncol = (l>>2);
      #pragma unroll
      for (int n=0;n<9;n++){
        unsigned b0 = __float_as_uint(Gs[gr0 + n*8 + ncol]);
        unsigned b1 = __float_as_uint(Gs[gr1 + n*8 + ncol]);
        mma_tf32(accd[n], a0,a1,a2,a3, b0,b1);
      }
    }
  }
  {
    const int p0 = prow + r0;
    const int p1 = p0 + 8;
    float* base0 = d_part + ((size_t)split*NPTS + p0)*68;
    float* base1 = d_part + ((size_t)split*NPTS + p1)*68;
    #pragma unroll
    for (int n=0;n<9;n++){
      int col = n*8 + 2*lj;
      if (col < 68){
        *(float2*)(base0 + col) = make_float2(accd[n][0], accd[n][1]);
        *(float2*)(base1 + col) = make_float2(accd[n][2], accd[n][3]);
      }
    }
  }
}

// ---------------- split reduce + transpose to [c][p] ----------------
__global__ void k_reduce(){
  int p = blockIdx.x*128 + threadIdx.x;
  if (p>=NPTS) return;
  float accv[68];
  #pragma unroll
  for (int i=0;i<68;i++) accv[i]=0.f;
  #pragma unroll 4
  for (int sp=0;sp<SPLITS;sp++){
    const float4* b = (const float4*)(d_part + ((size_t)sp*NPTS+p)*68);
    #pragma unroll
    for (int i=0;i<17;i++){
      float4 v=b[i];
      accv[i*4+0]+=v.x; accv[i*4+1]+=v.y; accv[i*4+2]+=v.z; accv[i*4+3]+=v.w;
    }
  }
  float inv = 1.f/accv[66];
  #pragma unroll 1
  for (int c=0;c<66;c++) d_G[c*NPTS+p] = accv[c]*inv;
}

// ---------------- per-point output tensor products ----------------
template<int D1,int D2,int D3>
__device__ __forceinline__ void qpath(const float* __restrict__ w3, const float* __restrict__ f,
                                      int p, float c0, float c1, float c2,
                                      int g0, int g1, int g2, float* out){
  #pragma unroll 1
  for (int j=0;j<D2;j++){
    float gm = c0*d_G[(g0+j)*NPTS+p] + c1*d_G[(g1+j)*NPTS+p] + c2*d_G[(g2+j)*NPTS+p];
    #pragma unroll
    for (int i=0;i<D1;i++){
      float cf = gm*f[i];
      #pragma unroll
      for (int k=0;k<D3;k++) out[k] = fmaf(cf, w3[(i*D2+j)*D3+k], out[k]);
    }
  }
}

__global__ void __launch_bounds__(256) k_output(int blk, int sel){
  const float* fin = sel ? d_feat1 : d_feat0;
  float* fout = sel ? d_feat0 : d_feat1;
  __shared__ float w3s[6292];
  int tid = threadIdx.x;
  int half = blockIdx.y;
  int base = half ? 7026 : 2670;
  int len  = half ? 6292 : 4356;
  for (int i=tid;i<len;i+=256) w3s[i]=d_w3j[base+i];
  __syncthreads();
  int p = blockIdx.x*256 + tid;
  float f4[9], f6[13];
  #pragma unroll
  for (int i=0;i<9;i++) f4[i]=fin[p*22+i];
  #pragma unroll
  for (int i=0;i<13;i++) f6[i]=fin[p*22+9+i];
  const float* cf = d_coef + blk*24;
  if (half==0){
    float d4[9];
    #pragma unroll
    for (int k=0;k<9;k++) d4[k]=0.f;
    qpath<9,9,9>   (w3s+0,    f4, p, cf[0], cf[1], cf[2],  0, 9,18, d4);
    qpath<9,13,9>  (w3s+729,  f4, p, cf[3], cf[4], cf[5], 27,40,53, d4);
    qpath<13,9,9>  (w3s+1782, f6, p, cf[6], cf[7], cf[8],  0, 9,18, d4);
    qpath<13,13,9> (w3s+2835, f6, p, cf[9], cf[10],cf[11],27,40,53, d4);
    #pragma unroll
    for (int k=0;k<9;k++) fout[p*22+k] = f4[k]+d4[k];
  } else {
    float d6[13];
    #pragma unroll
    for (int k=0;k<13;k++) d6[k]=0.f;
    qpath<9,9,13>  (w3s+0,    f4, p, cf[12],cf[13],cf[14], 0, 9,18, d6);
    qpath<9,13,13> (w3s+1053, f4, p, cf[15],cf[16],cf[17],27,40,53, d6);
    qpath<13,9,13> (w3s+2574, f6, p, cf[18],cf[19],cf[20], 0, 9,18, d6);
    qpath<13,13,13>(w3s+4095, f6, p, cf[21],cf[22],cf[23],27,40,53, d6);
    #pragma unroll
    for (int k=0;k<13;k++) fout[p*22+9+k] = f6[k]+d6[k];
  }
}

// ---------------- upsample ----------------
__global__ void k_upsample(const float* __restrict__ upw, float* __restrict__ out){
  int idx = blockIdx.x*256 + threadIdx.x;
  if (idx >= NBATCH*65536) return;
  int b = idx >> 16;
  int nh = idx & 65535;
  int rw = nh & 3; int t = nh >> 2; int w = t & 63; t >>= 6; int rh = t & 3; int h = t >> 2;
  int p = b*NLR + h*64 + w;
  float u4 = upw[(rh*4+rw)*2 + 0];
  float u6 = upw[(rh*4+rw)*2 + 1];
  float* o4 = out + (size_t)idx*9;
  float* o6 = out + 1179648 + (size_t)idx*13;
  #pragma unroll
  for (int k=0;k<9;k++)  o4[k] = d_feat0[p*22+k]*u4;
  #pragma unroll
  for (int k=0;k<13;k++) o6[k] = d_feat0[p*22+9+k]*u6;
}

extern "C" void kernel_launch(void* const* d_in, const int* in_sizes, int n_in,
                              void* d_out, int out_size) {
  const float* f4   = (const float*)d_in[0];
  const float* f6   = (const float*)d_in[1];
  const float* ls4  = (const float*)d_in[2];
  const float* ls6  = (const float*)d_in[3];
  const float* pbw  = (const float*)d_in[4];
  const float* pbb  = (const float*)d_in[5];
  const float* liw4 = (const float*)d_in[6];
  const float* liw6 = (const float*)d_in[7];
  const float* tvw  = (const float*)d_in[8];
  const float* tow  = (const float*)d_in[9];
  const float* low4 = (const float*)d_in[10];
  const float* low6 = (const float*)d_in[11];
  const float* upw  = (const float*)d_in[12];
  float* out = (float*)d_out;

  k_w3j<<<14,256>>>();
  k_sh<<<16,256>>>(pbw, pbb);
  k_coef<<<1,128>>>(liw4, liw6, tvw, tow, low4, low6);
  k_featinit<<<32,256>>>(f4, f6);
  for (int blk=0; blk<2; blk++){
    k_prepare<<<64,128>>>(ls4, ls6, blk, blk&1);
    k_attn<<<dim3(NLR/RT, NBATCH, SPLITS), 256>>>();
    k_reduce<<<NPTS/128,128>>>();
    k_output<<<dim3(32,2),256>>>(blk, blk&1);
  }
  k_upsample<<<512,256>>>(upw, out);
}

// round 14
// speedup vs baseline: 2.0165x; 1.0151x over previous
#include <cuda_runtime.h>
#include <cuda_bf16.h>
#include <math.h>

#define NBATCH 2
#define NLR    4096
#define NPTS   (NBATCH*NLR)
#define SPLITS 16
#define KT     32
#define RT     128
#define GST    76
#define KST    28

#define W3J_TOTAL   13318
#define W3J_OUT_OFF 2670

__device__ float d_feat0[NPTS*22];
__device__ float d_feat1[NPTS*22];
__device__ float d_qvT[22*NPTS];
__device__ __align__(16) float d_kv[NPTS*KST];
__device__ __align__(16) float d_gv  [NPTS*GST];
__device__ __align__(16) float d_part[SPLITS*NPTS*68];
__device__ float d_G   [66*NPTS];
__device__ float d_sh  [NLR*6];
__device__ float d_eb  [2*NLR];
__device__ float d_w3j [W3J_TOTAL];
__device__ float d_coef[2*8*3];

__constant__ int PATH_L[14][3] = {
  {4,0,4},{4,2,4},{6,2,4},{6,0,6},{4,2,6},{6,2,6},
  {4,4,4},{4,6,4},{6,4,4},{6,6,4},{4,4,6},{4,6,6},{6,4,6},{6,6,6}};
__constant__ int PATH_OFF[15] = {
  0,81,486,1071,1240,1825,2670,3399,4452,5505,7026,8079,9600,11121,13318};

// ---------------- tf32 helpers ----------------
__device__ __forceinline__ unsigned tf32bits(float x){
  unsigned u;
  asm("cvt.rna.tf32.f32 %0, %1;" : "=r"(u) : "f"(x));
  return u;
}
__device__ __forceinline__ float tf32r(float x){
  return __uint_as_float(tf32bits(x));
}
__device__ __forceinline__ void mma_tf32(float* c,
    unsigned a0, unsigned a1, unsigned a2, unsigned a3,
    unsigned b0, unsigned b1){
  asm volatile(
    "mma.sync.aligned.m16n8k8.row.col.f32.tf32.tf32.f32 "
    "{%0,%1,%2,%3}, {%4,%5,%6,%7}, {%8,%9}, {%0,%1,%2,%3};"
    : "+f"(c[0]), "+f"(c[1]), "+f"(c[2]), "+f"(c[3])
    : "r"(a0), "r"(a1), "r"(a2), "r"(a3), "r"(b0), "r"(b1));
}

// ---------------- W3J (real Wigner/CG) ----------------
struct Cpx { double re, im; };

__device__ __forceinline__ double dev_cg(int j1,int m1,int j2,int m2,int j3,int m3,const double* f){
  if (m1+m2 != m3) return 0.0;
  if (j3 < abs(j1-j2) || j3 > j1+j2) return 0.0;
  double pref = sqrt((2.0*j3+1.0)*f[j3+j1-j2]*f[j3-j1+j2]*f[j1+j2-j3]/f[j1+j2+j3+1]);
  pref *= sqrt(f[j3+m3]*f[j3-m3]*f[j1-m1]*f[j1+m1]*f[j2-m2]*f[j2+m2]);
  double s = 0.0;
  int kmax = j1+j2-j3;
  for (int k=0;k<=kmax;k++){
    int a3=j1-m1-k, a4=j2+m2-k, a5=j3-j2+m1+k, a6=j3-j1-m2+k;
    if (a3<0||a4<0||a5<0||a6<0) continue;
    double t = 1.0/(f[k]*f[kmax-k]*f[a3]*f[a4]*f[a5]*f[a6]);
    s += (k&1)? -t : t;
  }
  return pref*s;
}

__device__ __forceinline__ int unz(int l, int r, int* cols, Cpx* vals){
  const double s2 = 0.70710678118654752440;
  if (r == l){ cols[0]=l; vals[0]=Cpx{1.0,0.0}; return 1; }
  if (r > l){ int m=r-l; double sg=(m&1)?-1.0:1.0;
    cols[0]=l+m; vals[0]=Cpx{sg*s2,0.0};
    cols[1]=l-m; vals[1]=Cpx{s2,0.0}; return 2; }
  int m=l-r; double sg=(m&1)?-1.0:1.0;
  cols[0]=l-m; vals[0]=Cpx{0.0,s2};
  cols[1]=l+m; vals[1]=Cpx{0.0,-sg*s2}; return 2;
}

__device__ __forceinline__ Cpx uent(int l,int r,int c){
  const double s2 = 0.70710678118654752440;
  Cpx z = Cpx{0.0,0.0};
  if (r==l){ if (c==l) z = Cpx{1.0,0.0}; return z; }
  if (r>l){ int m=r-l; double sg=(m&1)?-1.0:1.0;
    if (c==l+m) z = Cpx{sg*s2,0.0}; else if (c==l-m) z = Cpx{s2,0.0}; return z; }
  int m=l-r; double sg=(m&1)?-1.0:1.0;
  if (c==l-m) z = Cpx{0.0,s2}; else if (c==l+m) z = Cpx{0.0,-sg*s2};
  return z;
}

__global__ void k_w3j(){
  int path = blockIdx.x;
  int l1=PATH_L[path][0], l2=PATH_L[path][1], l3=PATH_L[path][2];
  int d1=2*l1+1, d2=2*l2+1, d3=2*l3+1;
  int off=PATH_OFF[path];
  int total=d1*d2*d3;
  __shared__ double Cc[169];
  __shared__ double red[256];
  int tid=threadIdx.x;
  double fct[20]; fct[0]=1.0;
  for (int i=1;i<20;i++) fct[i]=fct[i-1]*(double)i;
  for (int e=tid; e<d1*d2; e+=256){
    int a=e/d2, b=e%d2;
    int m1=a-l1, m2=b-l2, m3=m1+m2;
    Cc[e] = (abs(m3)<=l3) ? dev_cg(l1,m1,l2,m2,l3,m3,fct) : 0.0;
  }
  __syncthreads();
  double tv[9]; double ss=0.0; int cnt=0;
  for (int e=tid; e<total; e+=256){
    int i=e/(d2*d3); int j=(e/d3)%d2; int k=e%d3;
    int c1[2], c2[2]; Cpx u1[2], u2[2];
    int n1 = unz(l1,i,c1,u1);
    int n2 = unz(l2,j,c2,u2);
    double re=0.0;
    for (int ii=0;ii<n1;ii++)
      for (int jj=0;jj<n2;jj++){
        int c = c1[ii]-l1 + c2[jj]-l2 + l3;
        if (c<0 || c>2*l3) continue;
        Cpx u3 = uent(l3,k,c);
        if (u3.re==0.0 && u3.im==0.0) continue;
        double cgv = Cc[c1[ii]*d2 + c2[jj]];
        if (cgv==0.0) continue;
        double pr = u1[ii].re*u2[jj].re - u1[ii].im*u2[jj].im;
        double pi = u1[ii].re*u2[jj].im + u1[ii].im*u2[jj].re;
        re += (pr*u3.re + pi*u3.im)*cgv;
      }
    tv[cnt++]=re; ss+=re*re;
  }
  red[tid]=ss; __syncthreads();
  for (int s=128;s>0;s>>=1){ if (tid<s) red[tid]+=red[tid+s]; __syncthreads(); }
  double rnorm = rsqrt(red[0]);
  cnt=0;
  for (int e=tid; e<total; e+=256) d_w3j[off+e] = (float)(tv[cnt++]*rnorm);
}

// ---------------- fused spherical harmonics / bias + coefficients ----------
__global__ void k_shcoef(const float* __restrict__ pbw, const float* __restrict__ pbb,
                         const float* __restrict__ liw4, const float* __restrict__ liw6,
                         const float* __restrict__ tvw,  const float* __restrict__ tow,
                         const float* __restrict__ low4, const float* __restrict__ low6){
  int tid = threadIdx.x;
  if (blockIdx.x < 16){
    int n = blockIdx.x*256 + tid;
    int h=n>>6, w=n&63;
    double y = -1.0 + 2.0*(double)h/63.0;
    double x = -1.0 + 2.0*(double)w/63.0;
    double r = sqrt(x*x+y*y); if (r < 1e-8) r = 1e-8;
    double xn=x/r, yn=y/r;
    const double c0=0.28209479177387814, c2=1.0925484305920792, c20=0.31539156525252005;
    float sh[6];
    sh[0]=(float)c0;
    sh[1]=(float)(c2*xn*yn);
    sh[2]=0.0f;
    sh[3]=(float)(-c20);
    sh[4]=0.0f;
    sh[5]=(float)(0.5*c2*(xn*xn-yn*yn));
    #pragma unroll
    for (int i=0;i<6;i++) d_sh[n*6+i]=sh[i];
    for (int blk=0;blk<2;blk++){
      float b = pbb[blk];
      #pragma unroll
      for (int i=0;i<6;i++) b = fmaf(sh[i], pbw[blk*6+i], b);
      d_eb[blk*NLR+n]=expf(b);
    }
    return;
  }
  // coefficient block
  __shared__ float a_s[96];
  if (tid < 96){
    int c = tid & 7; int pp = (tid>>3)%6; int blk = tid/48;
    const float* liw = (pp==0||pp==1||pp==4) ? (liw4+blk*8) : (liw6+blk*8);
    float s=0.f;
    for (int u=0;u<8;u++) s = fmaf(liw[u], tvw[((blk*6+pp)*8+u)*8 + c], s);
    a_s[tid]=s;
  }
  __syncthreads();
  if (tid < 16){
    int q = tid&7, blk = tid>>3;
    const float* liw = (q==0||q==1||q==4||q==5)? (liw4+blk*8) : (liw6+blk*8);
    const float* low = (q<4)? (low4+blk*8) : (low6+blk*8);
    float b[8];
    #pragma unroll
    for (int v=0;v<8;v++){
      float s=0.f;
      for (int u=0;u<8;u++){
        float lu = liw[u];
        for (int w=0;w<8;w++)
          s = fmaf(lu*tow[(((blk*8+q)*8+u)*8+v)*8+w], low[w], s);
      }
      b[v]=s;
    }
    int pbase = (q&1)? 3 : 0;
    const float invs = (1.0f/sqrtf(24.0f)) * (1.0f/16.0f) * (1.0f/sqrtf(8.0f));
    for (int pp=0;pp<3;pp++){
      float s=0.f;
      #pragma unroll
      for (int v=0;v<8;v++) s = fmaf(b[v], a_s[(blk*6+pbase+pp)*8 + v], s);
      d_coef[(blk*8+q)*3+pp] = s*invs;
    }
  }
}

// ---------------- per-point prep (featinit folded for blk 0) ---------------
__global__ void __launch_bounds__(128) k_prepare(const float* __restrict__ in4,
                                                 const float* __restrict__ in6,
                                                 const float* __restrict__ ls4,
                                                 const float* __restrict__ ls6,
                                                 int blk, int sel){
  __shared__ float wv[W3J_OUT_OFF];
  int tid = threadIdx.x;
  for (int i=tid;i<W3J_OUT_OFF;i+=128) wv[i]=d_w3j[i];
  __syncthreads();
  int p = blockIdx.x*128 + tid;
  float f[22];
  float s4=0.f, s6=0.f;
  if (blk==0){
    #pragma unroll
    for (int i=0;i<9;i++){ f[i]=in4[p*9+i]; s4=fmaf(f[i],f[i],s4); d_feat0[p*22+i]=f[i]; }
    #pragma unroll
    for (int i=0;i<13;i++){ f[9+i]=in6[p*13+i]; s6=fmaf(f[9+i],f[9+i],s6); d_feat0[p*22+9+i]=f[9+i]; }
  } else {
    const float* fin = sel ? d_feat1 : d_feat0;
    #pragma unroll
    for (int i=0;i<9;i++){ f[i]=fin[p*22+i]; s4=fmaf(f[i],f[i],s4); }
    #pragma unroll
    for (int i=9;i<22;i++){ f[i]=fin[p*22+i]; s6=fmaf(f[i],f[i],s6); }
  }
  float inv4=1.f/fmaxf(sqrtf(s4),1e-12f);
  float inv6=1.f/fmaxf(sqrtf(s6),1e-12f);
  float e4=expf(ls4[blk]), e6=expf(ls6[blk]);
  {
    float kvloc[KST];
    #pragma unroll
    for (int i=0;i<9;i++){ float kk=f[i]*inv4; kvloc[i]=kk; d_qvT[i*NPTS+p]=kk*e4; }
    #pragma unroll
    for (int i=9;i<22;i++){ float kk=f[i]*inv6; kvloc[i]=kk; d_qvT[i*NPTS+p]=kk*e6; }
    #pragma unroll
    for (int i=22;i<KST;i++) kvloc[i]=0.f;
    float4* dst = (float4*)(d_kv + (size_t)p*KST);
    #pragma unroll
    for (int j=0;j<KST/4;j++)
      dst[j] = make_float4(kvloc[j*4],kvloc[j*4+1],kvloc[j*4+2],kvloc[j*4+3]);
  }
  int n = p & (NLR-1);
  float ebv = d_eb[blk*NLR+n];
  float sh0=d_sh[n*6];
  float sh2[5];
  #pragma unroll
  for (int j=0;j<5;j++) sh2[j]=d_sh[n*6+1+j];
  float* g = d_gv + (size_t)p*GST;
  { float a[9];
    #pragma unroll
    for (int k=0;k<9;k++) a[k]=0.f;
    #pragma unroll 1
    for (int i=0;i<9;i++){ float fi=f[i];
      #pragma unroll
      for (int k=0;k<9;k++) a[k]=fmaf(fi,wv[i*9+k],a[k]); }
    #pragma unroll
    for (int k=0;k<9;k++) g[k]=tf32r(a[k]*sh0*ebv); }
  { float a[9];
    #pragma unroll
    for (int k=0;k<9;k++) a[k]=0.f;
    #pragma unroll 1
    for (int i=0;i<9;i++){ float fi=f[i];
      #pragma unroll 1
      for (int j=0;j<5;j++){ float c=fi*sh2[j];
        #pragma unroll
        for (int k=0;k<9;k++) a[k]=fmaf(c,wv[81+(i*5+j)*9+k],a[k]); } }
    #pragma unroll
    for (int k=0;k<9;k++) g[9+k]=tf32r(a[k]*ebv); }
  { float a[9];
    #pragma unroll
    for (int k=0;k<9;k++) a[k]=0.f;
    #pragma unroll 1
    for (int i=0;i<13;i++){ float fi=f[9+i];
      #pragma unroll 1
      for (int j=0;j<5;j++){ float c=fi*sh2[j];
        #pragma unroll
        for (int k=0;k<9;k++) a[k]=fmaf(c,wv[486+(i*5+j)*9+k],a[k]); } }
    #pragma unroll
    for (int k=0;k<9;k++) g[18+k]=tf32r(a[k]*ebv); }
  { float a[13];
    #pragma unroll
    for (int k=0;k<13;k++) a[k]=0.f;
    #pragma unroll 1
    for (int i=0;i<13;i++){ float fi=f[9+i];
      #pragma unroll
      for (int k=0;k<13;k++) a[k]=fmaf(fi,wv[1071+i*13+k],a[k]); }
    #pragma unroll
    for (int k=0;k<13;k++) g[27+k]=tf32r(a[k]*sh0*ebv); }
  { float a[13];
    #pragma unroll
    for (int k=0;k<13;k++) a[k]=0.f;
    #pragma unroll 1
    for (int i=0;i<9;i++){ float fi=f[i];
      #pragma unroll 1
      for (int j=0;j<5;j++){ float c=fi*sh2[j];
        #pragma unroll
        for (int k=0;k<13;k++) a[k]=fmaf(c,wv[1240+(i*5+j)*13+k],a[k]); } }
    #pragma unroll
    for (int k=0;k<13;k++) g[40+k]=tf32r(a[k]*ebv); }
  { float a[13];
    #pragma unroll
    for (int k=0;k<13;k++) a[k]=0.f;
    #pragma unroll 1
    for (int i=0;i<13;i++){ float fi=f[9+i];
      #pragma unroll 1
      for (int j=0;j<5;j++){ float c=fi*sh2[j];
        #pragma unroll
        for (int k=0;k<13;k++) a[k]=fmaf(c,wv[1825+(i*5+j)*13+k],a[k]); } }
    #pragma unroll
    for (int k=0;k<13;k++) g[53+k]=tf32r(a[k]*ebv); }
  g[66]=tf32r(ebv);
  #pragma unroll
  for (int k=67;k<GST;k++) g[k]=0.f;
}

// ---------------- attention: full-HMMA (tf32 split QK + tf32 PV) ----------
__global__ void __launch_bounds__(256,3) k_attn(){
  __shared__ float Qs[24*RT];
  __shared__ float Ks[KT*KST];
  __shared__ float Gs[KT*GST];
  const int tid = threadIdx.x;
  const int w = tid>>5, l = tid&31;
  const int batch = blockIdx.y, split = blockIdx.z;
  const int prow = batch*NLR + blockIdx.x*RT;

  for (int i=tid;i<24*RT;i+=256){
    int kd=i>>7, r=i&127;
    Qs[i] = (kd<22)? d_qvT[kd*NPTS + prow + r] : 0.f;
  }
  __syncthreads();

  const int r0 = 16*w + (l>>2);
  const int lj = l & 3;
  unsigned qh[3][4], ql[3][4];
  #pragma unroll
  for (int ks=0;ks<3;ks++){
    float v0 = Qs[(ks*8+lj)*RT + r0];
    float v1 = Qs[(ks*8+lj)*RT + r0+8];
    float v2 = Qs[(ks*8+lj+4)*RT + r0];
    float v3 = Qs[(ks*8+lj+4)*RT + r0+8];
    qh[ks][0]=tf32bits(v0); ql[ks][0]=tf32bits(v0-__uint_as_float(qh[ks][0]));
    qh[ks][1]=tf32bits(v1); ql[ks][1]=tf32bits(v1-__uint_as_float(qh[ks][1]));
    qh[ks][2]=tf32bits(v2); ql[ks][2]=tf32bits(v2-__uint_as_float(qh[ks][2]));
    qh[ks][3]=tf32bits(v3); ql[ks][3]=tf32bits(v3-__uint_as_float(qh[ks][3]));
  }

  float accd[9][4];
  #pragma unroll
  for (int n=0;n<9;n++){
    #pragma unroll
    for (int c=0;c<4;c++) accd[n][c]=0.f;
  }

  const int m0 = split*(NLR/SPLITS);
  const int ntiles = (NLR/SPLITS)/KT;
  for (int t=0;t<ntiles;t++){
    const int mbase = batch*NLR + m0 + t*KT;
    __syncthreads();
    { const float4* src = (const float4*)(d_kv + (size_t)mbase*KST);
      float4* dst = (float4*)Ks;
      for (int i=tid;i<KT*(KST/4);i+=256) dst[i]=src[i]; }
    for (int i=tid;i<KT*(GST/4);i+=256){
      int key=i/(GST/4), c4=i-key*(GST/4);
      *(float4*)(Gs + key*GST + c4*4) =
        *(const float4*)(d_gv + (size_t)(mbase+key)*GST + c4*4);
    }
    __syncthreads();
    #pragma unroll
    for (int kg=0;kg<4;kg++){
      float sc[4];
      sc[0]=0.f; sc[1]=0.f; sc[2]=0.f; sc[3]=0.f;
      const int krow = (kg*8 + (l>>2))*KST;
      #pragma unroll
      for (int ks=0;ks<3;ks++){
        float b0f = Ks[krow + ks*8 + lj];
        float b1f = Ks[krow + ks*8 + lj + 4];
        unsigned b0h = tf32bits(b0f);
        unsigned b1h = tf32bits(b1f);
        unsigned b0l = tf32bits(b0f - __uint_as_float(b0h));
        unsigned b1l = tf32bits(b1f - __uint_as_float(b1h));
        mma_tf32(sc, qh[ks][0],qh[ks][1],qh[ks][2],qh[ks][3], b0h,b1h);
        mma_tf32(sc, qh[ks][0],qh[ks][1],qh[ks][2],qh[ks][3], b0l,b1l);
        mma_tf32(sc, ql[ks][0],ql[ks][1],ql[ks][2],ql[ks][3], b0h,b1h);
      }
      unsigned a0 = tf32bits(__expf(sc[0]));
      unsigned a1 = tf32bits(__expf(sc[2]));
      unsigned a2 = tf32bits(__expf(sc[1]));
      unsigned a3 = tf32bits(__expf(sc[3]));
      const int gr0 = (kg*8 + 2*lj)*GST;
      const int gr1 = gr0 + GST;
      const int ncol = (l>>2);
      #pragma unroll
      for (int n=0;n<9;n++){
        unsigned b0 = __float_as_uint(Gs[gr0 + n*8 + ncol]);
        unsigned b1 = __float_as_uint(Gs[gr1 + n*8 + ncol]);
        mma_tf32(accd[n], a0,a1,a2,a3, b0,b1);
      }
    }
  }
  {
    const int p0 = prow + r0;
    const int p1 = p0 + 8;
    float* base0 = d_part + ((size_t)split*NPTS + p0)*68;
    float* base1 = d_part + ((size_t)split*NPTS + p1)*68;
    #pragma unroll
    for (int n=0;n<9;n++){
      int col = n*8 + 2*lj;
      if (col < 68){
        *(float2*)(base0 + col) = make_float2(accd[n][0], accd[n][1]);
        *(float2*)(base1 + col) = make_float2(accd[n][2], accd[n][3]);
      }
    }
  }
}

// ---------------- split reduce + transpose to [c][p] ----------------
__global__ void k_reduce(){
  int p = blockIdx.x*128 + threadIdx.x;
  if (p>=NPTS) return;
  float accv[68];
  #pragma unroll
  for (int i=0;i<68;i++) accv[i]=0.f;
  #pragma unroll 4
  for (int sp=0;sp<SPLITS;sp++){
    const float4* b = (const float4*)(d_part + ((size_t)sp*NPTS+p)*68);
    #pragma unroll
    for (int i=0;i<17;i++){
      float4 v=b[i];
      accv[i*4+0]+=v.x; accv[i*4+1]+=v.y; accv[i*4+2]+=v.z; accv[i*4+3]+=v.w;
    }
  }
  float inv = 1.f/accv[66];
  #pragma unroll 1
  for (int c=0;c<66;c++) d_G[c*NPTS+p] = accv[c]*inv;
}

// ---------------- per-point output tensor products ----------------
template<int D1,int D2,int D3>
__device__ __forceinline__ void qpath(const float* __restrict__ w3, const float* __restrict__ f,
                                      int p, float c0, float c1, float c2,
                                      int g0, int g1, int g2, float* out){
  #pragma unroll 1
  for (int j=0;j<D2;j++){
    float gm = c0*d_G[(g0+j)*NPTS+p] + c1*d_G[(g1+j)*NPTS+p] + c2*d_G[(g2+j)*NPTS+p];
    #pragma unroll
    for (int i=0;i<D1;i++){
      float cf = gm*f[i];
      #pragma unroll
      for (int k=0;k<D3;k++) out[k] = fmaf(cf, w3[(i*D2+j)*D3+k], out[k]);
    }
  }
}

__global__ void __launch_bounds__(256) k_output(int blk, int sel){
  const float* fin = sel ? d_feat1 : d_feat0;
  float* fout = sel ? d_feat0 : d_feat1;
  __shared__ float w3s[6292];
  int tid = threadIdx.x;
  int half = blockIdx.y;
  int base = half ? 7026 : 2670;
  int len  = half ? 6292 : 4356;
  for (int i=tid;i<len;i+=256) w3s[i]=d_w3j[base+i];
  __syncthreads();
  int p = blockIdx.x*256 + tid;
  float f4[9], f6[13];
  #pragma unroll
  for (int i=0;i<9;i++) f4[i]=fin[p*22+i];
  #pragma unroll
  for (int i=0;i<13;i++) f6[i]=fin[p*22+9+i];
  const float* cf = d_coef + blk*24;
  if (half==0){
    float d4[9];
    #pragma unroll
    for (int k=0;k<9;k++) d4[k]=0.f;
    qpath<9,9,9>   (w3s+0,    f4, p, cf[0], cf[1], cf[2],  0, 9,18, d4);
    qpath<9,13,9>  (w3s+729,  f4, p, cf[3], cf[4], cf[5], 27,40,53, d4);
    qpath<13,9,9>  (w3s+1782, f6, p, cf[6], cf[7], cf[8],  0, 9,18, d4);
    qpath<13,13,9> (w3s+2835, f6, p, cf[9], cf[10],cf[11],27,40,53, d4);
    #pragma unroll
    for (int k=0;k<9;k++) fout[p*22+k] = f4[k]+d4[k];
  } else {
    float d6[13];
    #pragma unroll
    for (int k=0;k<13;k++) d6[k]=0.f;
    qpath<9,9,13>  (w3s+0,    f4, p, cf[12],cf[13],cf[14], 0, 9,18, d6);
    qpath<9,13,13> (w3s+1053, f4, p, cf[15],cf[16],cf[17],27,40,53, d6);
    qpath<13,9,13> (w3s+2574, f6, p, cf[18],cf[19],cf[20], 0, 9,18, d6);
    qpath<13,13,13>(w3s+4095, f6, p, cf[21],cf[22],cf[23],27,40,53, d6);
    #pragma unroll
    for (int k=0;k<13;k++) fout[p*22+9+k] = f6[k]+d6[k];
  }
}

// ---------------- upsample ----------------
__global__ void k_upsample(const float* __restrict__ upw, float* __restrict__ out){
  int idx = blockIdx.x*256 + threadIdx.x;
  if (idx >= NBATCH*65536) return;
  int b = idx >> 16;
  int nh = idx & 65535;
  int rw = nh & 3; int t = nh >> 2; int w = t & 63; t >>= 6; int rh = t & 3; int h = t >> 2;
  int p = b*NLR + h*64 + w;
  float u4 = upw[(rh*4+rw)*2 + 0];
  float u6 = upw[(rh*4+rw)*2 + 1];
  float* o4 = out + (size_t)idx*9;
  float* o6 = out + 1179648 + (size_t)idx*13;
  #pragma unroll
  for (int k=0;k<9;k++)  o4[k] = d_feat0[p*22+k]*u4;
  #pragma unroll
  for (int k=0;k<13;k++) o6[k] = d_feat0[p*22+9+k]*u6;
}

extern "C" void kernel_launch(void* const* d_in, const int* in_sizes, int n_in,
                              void* d_out, int out_size) {
  const float* f4   = (const float*)d_in[0];
  const float* f6   = (const float*)d_in[1];
  const float* ls4  = (const float*)d_in[2];
  const float* ls6  = (const float*)d_in[3];
  const float* pbw  = (const float*)d_in[4];
  const float* pbb  = (const float*)d_in[5];
  const float* liw4 = (const float*)d_in[6];
  const float* liw6 = (const float*)d_in[7];
  const float* tvw  = (const float*)d_in[8];
  const float* tow  = (const float*)d_in[9];
  const float* low4 = (const float*)d_in[10];
  const float* low6 = (const float*)d_in[11];
  const float* upw  = (const float*)d_in[12];
  float* out = (float*)d_out;

  k_w3j<<<14,256>>>();
  k_shcoef<<<17,256>>>(pbw, pbb, liw4, liw6, tvw, tow, low4, low6);
  for (int blk=0; blk<2; blk++){
    k_prepare<<<64,128>>>(f4, f6, ls4, ls6, blk, blk&1);
    k_attn<<<dim3(NLR/RT, NBATCH, SPLITS), 256>>>();
    k_reduce<<<NPTS/128,128>>>();
    k_output<<<dim3(32,2),256>>>(blk, blk&1);
  }
  k_upsample<<<512,256>>>(upw, out);
}

// round 15
// speedup vs baseline: 2.2930x; 1.1371x over previous
#include <cuda_runtime.h>
#include <cuda_bf16.h>
#include <math.h>

#define NBATCH 2
#define NLR    4096
#define NPTS   (NBATCH*NLR)
#define SPLITS 16
#define KT     32
#define RT     128
#define GST    76
#define KST    28

#define W3J_TOTAL   13318
#define W3J_OUT_OFF 2670

__device__ float d_feat0[NPTS*22];
__device__ float d_feat1[NPTS*22];
__device__ float d_qvT[22*NPTS];
__device__ __align__(16) float d_kvh[NPTS*KST];
__device__ __align__(16) float d_kvl[NPTS*KST];
__device__ __align__(16) float d_gv  [NPTS*GST];
__device__ __align__(16) float d_part[SPLITS*NPTS*68];
__device__ float d_G   [66*NPTS];
__device__ float d_sh  [NLR*6];
__device__ float d_eb  [2*NLR];
__device__ float d_w3j [W3J_TOTAL];
__device__ float d_coef[2*8*3];

__constant__ int PATH_L[14][3] = {
  {4,0,4},{4,2,4},{6,2,4},{6,0,6},{4,2,6},{6,2,6},
  {4,4,4},{4,6,4},{6,4,4},{6,6,4},{4,4,6},{4,6,6},{6,4,6},{6,6,6}};
__constant__ int PATH_OFF[15] = {
  0,81,486,1071,1240,1825,2670,3399,4452,5505,7026,8079,9600,11121,13318};

// ---------------- tf32 helpers ----------------
__device__ __forceinline__ unsigned tf32bits(float x){
  unsigned u;
  asm("cvt.rna.tf32.f32 %0, %1;" : "=r"(u) : "f"(x));
  return u;
}
__device__ __forceinline__ float tf32r(float x){
  return __uint_as_float(tf32bits(x));
}
__device__ __forceinline__ void mma_tf32(float* c,
    unsigned a0, unsigned a1, unsigned a2, unsigned a3,
    unsigned b0, unsigned b1){
  asm volatile(
    "mma.sync.aligned.m16n8k8.row.col.f32.tf32.tf32.f32 "
    "{%0,%1,%2,%3}, {%4,%5,%6,%7}, {%8,%9}, {%0,%1,%2,%3};"
    : "+f"(c[0]), "+f"(c[1]), "+f"(c[2]), "+f"(c[3])
    : "r"(a0), "r"(a1), "r"(a2), "r"(a3), "r"(b0), "r"(b1));
}

// ---------------- W3J (real Wigner/CG) ----------------
struct Cpx { double re, im; };

__device__ __forceinline__ double dev_cg(int j1,int m1,int j2,int m2,int j3,int m3,const double* f){
  if (m1+m2 != m3) return 0.0;
  if (j3 < abs(j1-j2) || j3 > j1+j2) return 0.0;
  double pref = sqrt((2.0*j3+1.0)*f[j3+j1-j2]*f[j3-j1+j2]*f[j1+j2-j3]/f[j1+j2+j3+1]);
  pref *= sqrt(f[j3+m3]*f[j3-m3]*f[j1-m1]*f[j1+m1]*f[j2-m2]*f[j2+m2]);
  double s = 0.0;
  int kmax = j1+j2-j3;
  for (int k=0;k<=kmax;k++){
    int a3=j1-m1-k, a4=j2+m2-k, a5=j3-j2+m1+k, a6=j3-j1-m2+k;
    if (a3<0||a4<0||a5<0||a6<0) continue;
    double t = 1.0/(f[k]*f[kmax-k]*f[a3]*f[a4]*f[a5]*f[a6]);
    s += (k&1)? -t : t;
  }
  return pref*s;
}

__device__ __forceinline__ int unz(int l, int r, int* cols, Cpx* vals){
  const double s2 = 0.70710678118654752440;
  if (r == l){ cols[0]=l; vals[0]=Cpx{1.0,0.0}; return 1; }
  if (r > l){ int m=r-l; double sg=(m&1)?-1.0:1.0;
    cols[0]=l+m; vals[0]=Cpx{sg*s2,0.0};
    cols[1]=l-m; vals[1]=Cpx{s2,0.0}; return 2; }
  int m=l-r; double sg=(m&1)?-1.0:1.0;
  cols[0]=l-m; vals[0]=Cpx{0.0,s2};
  cols[1]=l+m; vals[1]=Cpx{0.0,-sg*s2}; return 2;
}

__device__ __forceinline__ Cpx uent(int l,int r,int c){
  const double s2 = 0.70710678118654752440;
  Cpx z = Cpx{0.0,0.0};
  if (r==l){ if (c==l) z = Cpx{1.0,0.0}; return z; }
  if (r>l){ int m=r-l; double sg=(m&1)?-1.0:1.0;
    if (c==l+m) z = Cpx{sg*s2,0.0}; else if (c==l-m) z = Cpx{s2,0.0}; return z; }
  int m=l-r; double sg=(m&1)?-1.0:1.0;
  if (c==l-m) z = Cpx{0.0,s2}; else if (c==l+m) z = Cpx{0.0,-sg*s2};
  return z;
}

__global__ void k_w3j(){
  int path = blockIdx.x;
  int l1=PATH_L[path][0], l2=PATH_L[path][1], l3=PATH_L[path][2];
  int d1=2*l1+1, d2=2*l2+1, d3=2*l3+1;
  int off=PATH_OFF[path];
  int total=d1*d2*d3;
  __shared__ double Cc[169];
  __shared__ double red[256];
  int tid=threadIdx.x;
  double fct[20]; fct[0]=1.0;
  for (int i=1;i<20;i++) fct[i]=fct[i-1]*(double)i;
  for (int e=tid; e<d1*d2; e+=256){
    int a=e/d2, b=e%d2;
    int m1=a-l1, m2=b-l2, m3=m1+m2;
    Cc[e] = (abs(m3)<=l3) ? dev_cg(l1,m1,l2,m2,l3,m3,fct) : 0.0;
  }
  __syncthreads();
  double tv[9]; double ss=0.0; int cnt=0;
  for (int e=tid; e<total; e+=256){
    int i=e/(d2*d3); int j=(e/d3)%d2; int k=e%d3;
    int c1[2], c2[2]; Cpx u1[2], u2[2];
    int n1 = unz(l1,i,c1,u1);
    int n2 = unz(l2,j,c2,u2);
    double re=0.0;
    for (int ii=0;ii<n1;ii++)
      for (int jj=0;jj<n2;jj++){
        int c = c1[ii]-l1 + c2[jj]-l2 + l3;
        if (c<0 || c>2*l3) continue;
        Cpx u3 = uent(l3,k,c);
        if (u3.re==0.0 && u3.im==0.0) continue;
        double cgv = Cc[c1[ii]*d2 + c2[jj]];
        if (cgv==0.0) continue;
        double pr = u1[ii].re*u2[jj].re - u1[ii].im*u2[jj].im;
        double pi = u1[ii].re*u2[jj].im + u1[ii].im*u2[jj].re;
        re += (pr*u3.re + pi*u3.im)*cgv;
      }
    tv[cnt++]=re; ss+=re*re;
  }
  red[tid]=ss; __syncthreads();
  for (int s=128;s>0;s>>=1){ if (tid<s) red[tid]+=red[tid+s]; __syncthreads(); }
  double rnorm = rsqrt(red[0]);
  cnt=0;
  for (int e=tid; e<total; e+=256) d_w3j[off+e] = (float)(tv[cnt++]*rnorm);
}

// ---------------- fused spherical harmonics / bias + coefficients ----------
__global__ void k_shcoef(const float* __restrict__ pbw, const float* __restrict__ pbb,
                         const float* __restrict__ liw4, const float* __restrict__ liw6,
                         const float* __restrict__ tvw,  const float* __restrict__ tow,
                         const float* __restrict__ low4, const float* __restrict__ low6){
  int tid = threadIdx.x;
  if (blockIdx.x < 16){
    int n = blockIdx.x*256 + tid;
    int h=n>>6, w=n&63;
    double y = -1.0 + 2.0*(double)h/63.0;
    double x = -1.0 + 2.0*(double)w/63.0;
    double r = sqrt(x*x+y*y); if (r < 1e-8) r = 1e-8;
    double xn=x/r, yn=y/r;
    const double c0=0.28209479177387814, c2=1.0925484305920792, c20=0.31539156525252005;
    float sh[6];
    sh[0]=(float)c0;
    sh[1]=(float)(c2*xn*yn);
    sh[2]=0.0f;
    sh[3]=(float)(-c20);
    sh[4]=0.0f;
    sh[5]=(float)(0.5*c2*(xn*xn-yn*yn));
    #pragma unroll
    for (int i=0;i<6;i++) d_sh[n*6+i]=sh[i];
    for (int blk=0;blk<2;blk++){
      float b = pbb[blk];
      #pragma unroll
      for (int i=0;i<6;i++) b = fmaf(sh[i], pbw[blk*6+i], b);
      d_eb[blk*NLR+n]=expf(b);
    }
    return;
  }
  __shared__ float a_s[96];
  if (tid < 96){
    int c = tid & 7; int pp = (tid>>3)%6; int blk = tid/48;
    const float* liw = (pp==0||pp==1||pp==4) ? (liw4+blk*8) : (liw6+blk*8);
    float s=0.f;
    for (int u=0;u<8;u++) s = fmaf(liw[u], tvw[((blk*6+pp)*8+u)*8 + c], s);
    a_s[tid]=s;
  }
  __syncthreads();
  if (tid < 16){
    int q = tid&7, blk = tid>>3;
    const float* liw = (q==0||q==1||q==4||q==5)? (liw4+blk*8) : (liw6+blk*8);
    const float* low = (q<4)? (low4+blk*8) : (low6+blk*8);
    float b[8];
    #pragma unroll
    for (int v=0;v<8;v++){
      float s=0.f;
      for (int u=0;u<8;u++){
        float lu = liw[u];
        for (int w=0;w<8;w++)
          s = fmaf(lu*tow[(((blk*8+q)*8+u)*8+v)*8+w], low[w], s);
      }
      b[v]=s;
    }
    int pbase = (q&1)? 3 : 0;
    const float invs = (1.0f/sqrtf(24.0f)) * (1.0f/16.0f) * (1.0f/sqrtf(8.0f));
    for (int pp=0;pp<3;pp++){
      float s=0.f;
      #pragma unroll
      for (int v=0;v<8;v++) s = fmaf(b[v], a_s[(blk*6+pbase+pp)*8 + v], s);
      d_coef[(blk*8+q)*3+pp] = s*invs;
    }
  }
}

// ---------------- per-point prep (featinit folded for blk 0) ---------------
__global__ void __launch_bounds__(64) k_prepare(const float* __restrict__ in4,
                                                const float* __restrict__ in6,
                                                const float* __restrict__ ls4,
                                                const float* __restrict__ ls6,
                                                int blk, int sel){
  __shared__ float wv[W3J_OUT_OFF];
  int tid = threadIdx.x;
  for (int i=tid;i<W3J_OUT_OFF;i+=64) wv[i]=d_w3j[i];
  __syncthreads();
  int p = blockIdx.x*64 + tid;
  float f[22];
  float s4=0.f, s6=0.f;
  if (blk==0){
    #pragma unroll
    for (int i=0;i<9;i++){ f[i]=in4[p*9+i]; s4=fmaf(f[i],f[i],s4); d_feat0[p*22+i]=f[i]; }
    #pragma unroll
    for (int i=0;i<13;i++){ f[9+i]=in6[p*13+i]; s6=fmaf(f[9+i],f[9+i],s6); d_feat0[p*22+9+i]=f[9+i]; }
  } else {
    const float* fin = sel ? d_feat1 : d_feat0;
    #pragma unroll
    for (int i=0;i<9;i++){ f[i]=fin[p*22+i]; s4=fmaf(f[i],f[i],s4); }
    #pragma unroll
    for (int i=9;i<22;i++){ f[i]=fin[p*22+i]; s6=fmaf(f[i],f[i],s6); }
  }
  float inv4=1.f/fmaxf(sqrtf(s4),1e-12f);
  float inv6=1.f/fmaxf(sqrtf(s6),1e-12f);
  float e4=expf(ls4[blk]), e6=expf(ls6[blk]);
  {
    float kh[KST], kl[KST];
    #pragma unroll
    for (int i=0;i<9;i++){
      float kk=f[i]*inv4;
      d_qvT[i*NPTS+p]=kk*e4;
      kh[i]=tf32r(kk); kl[i]=tf32r(kk-kh[i]);
    }
    #pragma unroll
    for (int i=9;i<22;i++){
      float kk=f[i]*inv6;
      d_qvT[i*NPTS+p]=kk*e6;
      kh[i]=tf32r(kk); kl[i]=tf32r(kk-kh[i]);
    }
    #pragma unroll
    for (int i=22;i<KST;i++){ kh[i]=0.f; kl[i]=0.f; }
    float4* dh = (float4*)(d_kvh + (size_t)p*KST);
    float4* dl = (float4*)(d_kvl + (size_t)p*KST);
    #pragma unroll
    for (int j=0;j<KST/4;j++){
      dh[j] = make_float4(kh[j*4],kh[j*4+1],kh[j*4+2],kh[j*4+3]);
      dl[j] = make_float4(kl[j*4],kl[j*4+1],kl[j*4+2],kl[j*4+3]);
    }
  }
  int n = p & (NLR-1);
  float ebv = d_eb[blk*NLR+n];
  float sh0=d_sh[n*6];
  float sh2[5];
  #pragma unroll
  for (int j=0;j<5;j++) sh2[j]=d_sh[n*6+1+j];
  float* g = d_gv + (size_t)p*GST;
  { float a[9];
    #pragma unroll
    for (int k=0;k<9;k++) a[k]=0.f;
    #pragma unroll 1
    for (int i=0;i<9;i++){ float fi=f[i];
      #pragma unroll
      for (int k=0;k<9;k++) a[k]=fmaf(fi,wv[i*9+k],a[k]); }
    #pragma unroll
    for (int k=0;k<9;k++) g[k]=tf32r(a[k]*sh0*ebv); }
  { float a[9];
    #pragma unroll
    for (int k=0;k<9;k++) a[k]=0.f;
    #pragma unroll 1
    for (int i=0;i<9;i++){ float fi=f[i];
      #pragma unroll 1
      for (int j=0;j<5;j++){ float c=fi*sh2[j];
        #pragma unroll
        for (int k=0;k<9;k++) a[k]=fmaf(c,wv[81+(i*5+j)*9+k],a[k]); } }
    #pragma unroll
    for (int k=0;k<9;k++) g[9+k]=tf32r(a[k]*ebv); }
  { float a[9];
    #pragma unroll
    for (int k=0;k<9;k++) a[k]=0.f;
    #pragma unroll 1
    for (int i=0;i<13;i++){ float fi=f[9+i];
      #pragma unroll 1
      for (int j=0;j<5;j++){ float c=fi*sh2[j];
        #pragma unroll
        for (int k=0;k<9;k++) a[k]=fmaf(c,wv[486+(i*5+j)*9+k],a[k]); } }
    #pragma unroll
    for (int k=0;k<9;k++) g[18+k]=tf32r(a[k]*ebv); }
  { float a[13];
    #pragma unroll
    for (int k=0;k<13;k++) a[k]=0.f;
    #pragma unroll 1
    for (int i=0;i<13;i++){ float fi=f[9+i];
      #pragma unroll
      for (int k=0;k<13;k++) a[k]=fmaf(fi,wv[1071+i*13+k],a[k]); }
    #pragma unroll
    for (int k=0;k<13;k++) g[27+k]=tf32r(a[k]*sh0*ebv); }
  { float a[13];
    #pragma unroll
    for (int k=0;k<13;k++) a[k]=0.f;
    #pragma unroll 1
    for (int i=0;i<9;i++){ float fi=f[i];
      #pragma unroll 1
      for (int j=0;j<5;j++){ float c=fi*sh2[j];
        #pragma unroll
        for (int k=0;k<13;k++) a[k]=fmaf(c,wv[1240+(i*5+j)*13+k],a[k]); } }
    #pragma unroll
    for (int k=0;k<13;k++) g[40+k]=tf32r(a[k]*ebv); }
  { float a[13];
    #pragma unroll
    for (int k=0;k<13;k++) a[k]=0.f;
    #pragma unroll 1
    for (int i=0;i<13;i++){ float fi=f[9+i];
      #pragma unroll 1
      for (int j=0;j<5;j++){ float c=fi*sh2[j];
        #pragma unroll
        for (int k=0;k<13;k++) a[k]=fmaf(c,wv[1825+(i*5+j)*13+k],a[k]); } }
    #pragma unroll
    for (int k=0;k<13;k++) g[53+k]=tf32r(a[k]*ebv); }
  g[66]=tf32r(ebv);
  #pragma unroll
  for (int k=67;k<GST;k++) g[k]=0.f;
}

// ---------------- attention: full-HMMA, K hi/lo precomputed ----------------
__global__ void __launch_bounds__(256,3) k_attn(){
  __shared__ float Qs [24*RT];
  __shared__ float Ksh[KT*KST];
  __shared__ float Ksl[KT*KST];
  __shared__ float Gs [KT*GST];
  const int tid = threadIdx.x;
  const int w = tid>>5, l = tid&31;
  const int batch = blockIdx.y, split = blockIdx.z;
  const int prow = batch*NLR + blockIdx.x*RT;

  for (int i=tid;i<24*RT;i+=256){
    int kd=i>>7, r=i&127;
    Qs[i] = (kd<22)? d_qvT[kd*NPTS + prow + r] : 0.f;
  }
  __syncthreads();

  const int r0 = 16*w + (l>>2);
  const int lj = l & 3;
  unsigned qh[3][4], ql[3][4];
  #pragma unroll
  for (int ks=0;ks<3;ks++){
    float v0 = Qs[(ks*8+lj)*RT + r0];
    float v1 = Qs[(ks*8+lj)*RT + r0+8];
    float v2 = Qs[(ks*8+lj+4)*RT + r0];
    float v3 = Qs[(ks*8+lj+4)*RT + r0+8];
    qh[ks][0]=tf32bits(v0); ql[ks][0]=tf32bits(v0-__uint_as_float(qh[ks][0]));
    qh[ks][1]=tf32bits(v1); ql[ks][1]=tf32bits(v1-__uint_as_float(qh[ks][1]));
    qh[ks][2]=tf32bits(v2); ql[ks][2]=tf32bits(v2-__uint_as_float(qh[ks][2]));
    qh[ks][3]=tf32bits(v3); ql[ks][3]=tf32bits(v3-__uint_as_float(qh[ks][3]));
  }

  float accd[9][4];
  #pragma unroll
  for (int n=0;n<9;n++){
    #pragma unroll
    for (int c=0;c<4;c++) accd[n][c]=0.f;
  }

  const int m0 = split*(NLR/SPLITS);
  const int ntiles = (NLR/SPLITS)/KT;
  for (int t=0;t<ntiles;t++){
    const int mbase = batch*NLR + m0 + t*KT;
    __syncthreads();
    { const float4* srch = (const float4*)(d_kvh + (size_t)mbase*KST);
      const float4* srcl = (const float4*)(d_kvl + (size_t)mbase*KST);
      float4* dsth = (float4*)Ksh;
      float4* dstl = (float4*)Ksl;
      for (int i=tid;i<KT*(KST/4);i+=256){ dsth[i]=srch[i]; dstl[i]=srcl[i]; } }
    for (int i=tid;i<KT*(GST/4);i+=256){
      int key=i/(GST/4), c4=i-key*(GST/4);
      *(float4*)(Gs + key*GST + c4*4) =
        *(const float4*)(d_gv + (size_t)(mbase+key)*GST + c4*4);
    }
    __syncthreads();
    #pragma unroll
    for (int kg=0;kg<4;kg++){
      float sc[4];
      sc[0]=0.f; sc[1]=0.f; sc[2]=0.f; sc[3]=0.f;
      const int krow = (kg*8 + (l>>2))*KST;
      #pragma unroll
      for (int ks=0;ks<3;ks++){
        unsigned b0h = __float_as_uint(Ksh[krow + ks*8 + lj]);
        unsigned b1h = __float_as_uint(Ksh[krow + ks*8 + lj + 4]);
        unsigned b0l = __float_as_uint(Ksl[krow + ks*8 + lj]);
        unsigned b1l = __float_as_uint(Ksl[krow + ks*8 + lj + 4]);
        mma_tf32(sc, qh[ks][0],qh[ks][1],qh[ks][2],qh[ks][3], b0h,b1h);
        mma_tf32(sc, qh[ks][0],qh[ks][1],qh[ks][2],qh[ks][3], b0l,b1l);
        mma_tf32(sc, ql[ks][0],ql[ks][1],ql[ks][2],ql[ks][3], b0h,b1h);
      }
      unsigned a0 = tf32bits(__expf(sc[0]));
      unsigned a1 = tf32bits(__expf(sc[2]));
      unsigned a2 = tf32bits(__expf(sc[1]));
      unsigned a3 = tf32bits(__expf(sc[3]));
      const int gr0 = (kg*8 + 2*lj)*GST;
      const int gr1 = gr0 + GST;
      const int ncol = (l>>2);
      #pragma unroll
      for (int n=0;n<9;n++){
        unsigned b0 = __float_as_uint(Gs[gr0 + n*8 + ncol]);
        unsigned b1 = __float_as_uint(Gs[gr1 + n*8 + ncol]);
        mma_tf32(accd[n], a0,a1,a2,a3, b0,b1);
      }
    }
  }
  {
    const int p0 = prow + r0;
    const int p1 = p0 + 8;
    float* base0 = d_part + ((size_t)split*NPTS + p0)*68;
    float* base1 = d_part + ((size_t)split*NPTS + p1)*68;
    #pragma unroll
    for (int n=0;n<9;n++){
      int col = n*8 + 2*lj;
      if (col < 68){
        *(float2*)(base0 + col) = make_float2(accd[n][0], accd[n][1]);
        *(float2*)(base1 + col) = make_float2(accd[n][2], accd[n][3]);
      }
    }
  }
}

// ---------------- coalesced split reduce (warp per point) ------------------
__global__ void k_reduce(){
  const int lane = threadIdx.x & 31;
  const int p = blockIdx.x*8 + (threadIdx.x>>5);
  float4 acc = make_float4(0.f,0.f,0.f,0.f);
  if (lane < 17){
    #pragma unroll 4
    for (int sp=0;sp<SPLITS;sp++){
      float4 v = *(const float4*)(d_part + ((size_t)sp*NPTS + p)*68 + lane*4);
      acc.x+=v.x; acc.y+=v.y; acc.z+=v.z; acc.w+=v.w;
    }
  }
  float den = __shfl_sync(0xffffffffu, acc.z, 16);
  float inv = 1.f/den;
  if (lane < 17){
    int c = lane*4;
    if (c   < 66) d_G[(c  )*NPTS+p] = acc.x*inv;
    if (c+1 < 66) d_G[(c+1)*NPTS+p] = acc.y*inv;
    if (c+2 < 66) d_G[(c+2)*NPTS+p] = acc.z*inv;
    if (c+3 < 66) d_G[(c+3)*NPTS+p] = acc.w*inv;
  }
}

// ---------------- per-point output tensor products ----------------
template<int D1,int D2,int D3>
__device__ __forceinline__ void qpath(const float* __restrict__ w3, const float* __restrict__ f,
                                      int p, float c0, float c1, float c2,
                                      int g0, int g1, int g2, float* out){
  #pragma unroll 1
  for (int j=0;j<D2;j++){
    float gm = c0*d_G[(g0+j)*NPTS+p] + c1*d_G[(g1+j)*NPTS+p] + c2*d_G[(g2+j)*NPTS+p];
    #pragma unroll
    for (int i=0;i<D1;i++){
      float cf = gm*f[i];
      #pragma unroll
      for (int k=0;k<D3;k++) out[k] = fmaf(cf, w3[(i*D2+j)*D3+k], out[k]);
    }
  }
}

__global__ void __launch_bounds__(128) k_output(int blk, int sel){
  const float* fin = sel ? d_feat1 : d_feat0;
  float* fout = sel ? d_feat0 : d_feat1;
  __shared__ float w3s[6292];
  int tid = threadIdx.x;
  int half = blockIdx.y;
  int base = half ? 7026 : 2670;
  int len  = half ? 6292 : 4356;
  for (int i=tid;i<len;i+=128) w3s[i]=d_w3j[base+i];
  __syncthreads();
  int p = blockIdx.x*128 + tid;
  float f4[9], f6[13];
  #pragma unroll
  for (int i=0;i<9;i++) f4[i]=fin[p*22+i];
  #pragma unroll
  for (int i=0;i<13;i++) f6[i]=fin[p*22+9+i];
  const float* cf = d_coef + blk*24;
  if (half==0){
    float d4[9];
    #pragma unroll
    for (int k=0;k<9;k++) d4[k]=0.f;
    qpath<9,9,9>   (w3s+0,    f4, p, cf[0], cf[1], cf[2],  0, 9,18, d4);
    qpath<9,13,9>  (w3s+729,  f4, p, cf[3], cf[4], cf[5], 27,40,53, d4);
    qpath<13,9,9>  (w3s+1782, f6, p, cf[6], cf[7], cf[8],  0, 9,18, d4);
    qpath<13,13,9> (w3s+2835, f6, p, cf[9], cf[10],cf[11],27,40,53, d4);
    #pragma unroll
    for (int k=0;k<9;k++) fout[p*22+k] = f4[k]+d4[k];
  } else {
    float d6[13];
    #pragma unroll
    for (int k=0;k<13;k++) d6[k]=0.f;
    qpath<9,9,13>  (w3s+0,    f4, p, cf[12],cf[13],cf[14], 0, 9,18, d6);
    qpath<9,13,13> (w3s+1053, f4, p, cf[15],cf[16],cf[17],27,40,53, d6);
    qpath<13,9,13> (w3s+2574, f6, p, cf[18],cf[19],cf[20], 0, 9,18, d6);
    qpath<13,13,13>(w3s+4095, f6, p, cf[21],cf[22],cf[23],27,40,53, d6);
    #pragma unroll
    for (int k=0;k<13;k++) fout[p*22+9+k] = f6[k]+d6[k];
  }
}

// ---------------- upsample ----------------
__global__ void k_upsample(const float* __restrict__ upw, float* __restrict__ out){
  int idx = blockIdx.x*256 + threadIdx.x;
  if (idx >= NBATCH*65536) return;
  int b = idx >> 16;
  int nh = idx & 65535;
  int rw = nh & 3; int t = nh >> 2; int w = t & 63; t >>= 6; int rh = t & 3; int h = t >> 2;
  int p = b*NLR + h*64 + w;
  float u4 = upw[(rh*4+rw)*2 + 0];
  float u6 = upw[(rh*4+rw)*2 + 1];
  float* o4 = out + (size_t)idx*9;
  float* o6 = out + 1179648 + (size_t)idx*13;
  #pragma unroll
  for (int k=0;k<9;k++)  o4[k] = d_feat0[p*22+k]*u4;
  #pragma unroll
  for (int k=0;k<13;k++) o6[k] = d_feat0[p*22+9+k]*u6;
}

extern "C" void kernel_launch(void* const* d_in, const int* in_sizes, int n_in,
                              void* d_out, int out_size) {
  const float* f4   = (const float*)d_in[0];
  const float* f6   = (const float*)d_in[1];
  const float* ls4  = (const float*)d_in[2];
  const float* ls6  = (const float*)d_in[3];
  const float* pbw  = (const float*)d_in[4];
  const float* pbb  = (const float*)d_in[5];
  const float* liw4 = (const float*)d_in[6];
  const float* liw6 = (const float*)d_in[7];
  const float* tvw  = (const float*)d_in[8];
  const float* tow  = (const float*)d_in[9];
  const float* low4 = (const float*)d_in[10];
  const float* low6 = (const float*)d_in[11];
  const float* upw  = (const float*)d_in[12];
  float* out = (float*)d_out;

  k_w3j<<<14,256>>>();
  k_shcoef<<<17,256>>>(pbw, pbb, liw4, liw6, tvw, tow, low4, low6);
  for (int blk=0; blk<2; blk++){
    k_prepare<<<128,64>>>(f4, f6, ls4, ls6, blk, blk&1);
    k_attn<<<dim3(NLR/RT, NBATCH, SPLITS), 256>>>();
    k_reduce<<<NPTS/8,256>>>();
    k_output<<<dim3(64,2),128>>>(blk, blk&1);
  }
  k_upsample<<<512,256>>>(upw, out);
}

// round 16
// speedup vs baseline: 2.4847x; 1.0836x over previous
#include <cuda_runtime.h>
#include <cuda_bf16.h>
#include <math.h>

#define NBATCH 2
#define NLR    4096
#define NPTS   (NBATCH*NLR)
#define SPLITS 16
#define KT     32
#define RT     128
#define GST    76
#define KST    28

#define W3J_TOTAL   13318
#define W3J_OUT_OFF 2670

__device__ float d_feat0[NPTS*22];
__device__ float d_feat1[NPTS*22];
__device__ float d_qvT[22*NPTS];
__device__ __align__(16) float d_kvh[NPTS*KST];
__device__ __align__(16) float d_kvl[NPTS*KST];
__device__ __align__(16) float d_gv  [NPTS*GST];
__device__ __align__(16) float d_part[SPLITS*NPTS*68];
__device__ float d_G   [66*NPTS];
__device__ float d_sh  [NLR*6];
__device__ float d_eb  [2*NLR];
__device__ float d_w3j [W3J_TOTAL];
__device__ float d_coef[2*8*3];

__constant__ int PATH_L[14][3] = {
  {4,0,4},{4,2,4},{6,2,4},{6,0,6},{4,2,6},{6,2,6},
  {4,4,4},{4,6,4},{6,4,4},{6,6,4},{4,4,6},{4,6,6},{6,4,6},{6,6,6}};
__constant__ int PATH_OFF[15] = {
  0,81,486,1071,1240,1825,2670,3399,4452,5505,7026,8079,9600,11121,13318};

// ---------------- tf32 / async helpers ----------------
__device__ __forceinline__ unsigned tf32bits(float x){
  unsigned u;
  asm("cvt.rna.tf32.f32 %0, %1;" : "=r"(u) : "f"(x));
  return u;
}
__device__ __forceinline__ float tf32r(float x){
  return __uint_as_float(tf32bits(x));
}
__device__ __forceinline__ void mma_tf32(float* c,
    unsigned a0, unsigned a1, unsigned a2, unsigned a3,
    unsigned b0, unsigned b1){
  asm volatile(
    "mma.sync.aligned.m16n8k8.row.col.f32.tf32.tf32.f32 "
    "{%0,%1,%2,%3}, {%4,%5,%6,%7}, {%8,%9}, {%0,%1,%2,%3};"
    : "+f"(c[0]), "+f"(c[1]), "+f"(c[2]), "+f"(c[3])
    : "r"(a0), "r"(a1), "r"(a2), "r"(a3), "r"(b0), "r"(b1));
}
__device__ __forceinline__ void cpa16(unsigned s, const void* g){
  asm volatile("cp.async.ca.shared.global [%0], [%1], 16;" :: "r"(s), "l"(g));
}
__device__ __forceinline__ void cpa_commit(){
  asm volatile("cp.async.commit_group;" ::: "memory");
}
__device__ __forceinline__ void cpa_wait0(){
  asm volatile("cp.async.wait_group 0;" ::: "memory");
}

// ---------------- W3J (real Wigner/CG) ----------------
struct Cpx { double re, im; };

__device__ __forceinline__ double dev_cg(int j1,int m1,int j2,int m2,int j3,int m3,const double* f){
  if (m1+m2 != m3) return 0.0;
  if (j3 < abs(j1-j2) || j3 > j1+j2) return 0.0;
  double pref = sqrt((2.0*j3+1.0)*f[j3+j1-j2]*f[j3-j1+j2]*f[j1+j2-j3]/f[j1+j2+j3+1]);
  pref *= sqrt(f[j3+m3]*f[j3-m3]*f[j1-m1]*f[j1+m1]*f[j2-m2]*f[j2+m2]);
  double s = 0.0;
  int kmax = j1+j2-j3;
  for (int k=0;k<=kmax;k++){
    int a3=j1-m1-k, a4=j2+m2-k, a5=j3-j2+m1+k, a6=j3-j1-m2+k;
    if (a3<0||a4<0||a5<0||a6<0) continue;
    double t = 1.0/(f[k]*f[kmax-k]*f[a3]*f[a4]*f[a5]*f[a6]);
    s += (k&1)? -t : t;
  }
  return pref*s;
}

__device__ __forceinline__ int unz(int l, int r, int* cols, Cpx* vals){
  const double s2 = 0.70710678118654752440;
  if (r == l){ cols[0]=l; vals[0]=Cpx{1.0,0.0}; return 1; }
  if (r > l){ int m=r-l; double sg=(m&1)?-1.0:1.0;
    cols[0]=l+m; vals[0]=Cpx{sg*s2,0.0};
    cols[1]=l-m; vals[1]=Cpx{s2,0.0}; return 2; }
  int m=l-r; double sg=(m&1)?-1.0:1.0;
  cols[0]=l-m; vals[0]=Cpx{0.0,s2};
  cols[1]=l+m; vals[1]=Cpx{0.0,-sg*s2}; return 2;
}

__device__ __forceinline__ Cpx uent(int l,int r,int c){
  const double s2 = 0.70710678118654752440;
  Cpx z = Cpx{0.0,0.0};
  if (r==l){ if (c==l) z = Cpx{1.0,0.0}; return z; }
  if (r>l){ int m=r-l; double sg=(m&1)?-1.0:1.0;
    if (c==l+m) z = Cpx{sg*s2,0.0}; else if (c==l-m) z = Cpx{s2,0.0}; return z; }
  int m=l-r; double sg=(m&1)?-1.0:1.0;
  if (c==l-m) z = Cpx{0.0,s2}; else if (c==l+m) z = Cpx{0.0,-sg*s2};
  return z;
}

__global__ void k_w3j(){
  int path = blockIdx.x;
  int l1=PATH_L[path][0], l2=PATH_L[path][1], l3=PATH_L[path][2];
  int d1=2*l1+1, d2=2*l2+1, d3=2*l3+1;
  int off=PATH_OFF[path];
  int total=d1*d2*d3;
  __shared__ double Cc[169];
  __shared__ double red[256];
  int tid=threadIdx.x;
  double fct[20]; fct[0]=1.0;
  for (int i=1;i<20;i++) fct[i]=fct[i-1]*(double)i;
  for (int e=tid; e<d1*d2; e+=256){
    int a=e/d2, b=e%d2;
    int m1=a-l1, m2=b-l2, m3=m1+m2;
    Cc[e] = (abs(m3)<=l3) ? dev_cg(l1,m1,l2,m2,l3,m3,fct) : 0.0;
  }
  __syncthreads();
  double tv[9]; double ss=0.0; int cnt=0;
  for (int e=tid; e<total; e+=256){
    int i=e/(d2*d3); int j=(e/d3)%d2; int k=e%d3;
    int c1[2], c2[2]; Cpx u1[2], u2[2];
    int n1 = unz(l1,i,c1,u1);
    int n2 = unz(l2,j,c2,u2);
    double re=0.0;
    for (int ii=0;ii<n1;ii++)
      for (int jj=0;jj<n2;jj++){
        int c = c1[ii]-l1 + c2[jj]-l2 + l3;
        if (c<0 || c>2*l3) continue;
        Cpx u3 = uent(l3,k,c);
        if (u3.re==0.0 && u3.im==0.0) continue;
        double cgv = Cc[c1[ii]*d2 + c2[jj]];
        if (cgv==0.0) continue;
        double pr = u1[ii].re*u2[jj].re - u1[ii].im*u2[jj].im;
        double pi = u1[ii].re*u2[jj].im + u1[ii].im*u2[jj].re;
        re += (pr*u3.re + pi*u3.im)*cgv;
      }
    tv[cnt++]=re; ss+=re*re;
  }
  red[tid]=ss; __syncthreads();
  for (int s=128;s>0;s>>=1){ if (tid<s) red[tid]+=red[tid+s]; __syncthreads(); }
  double rnorm = rsqrt(red[0]);
  cnt=0;
  for (int e=tid; e<total; e+=256) d_w3j[off+e] = (float)(tv[cnt++]*rnorm);
}

// ---------------- fused spherical harmonics / bias + coefficients ----------
__global__ void k_shcoef(const float* __restrict__ pbw, const float* __restrict__ pbb,
                         const float* __restrict__ liw4, const float* __restrict__ liw6,
                         const float* __restrict__ tvw,  const float* __restrict__ tow,
                         const float* __restrict__ low4, const float* __restrict__ low6){
  int tid = threadIdx.x;
  if (blockIdx.x < 16){
    int n = blockIdx.x*256 + tid;
    int h=n>>6, w=n&63;
    double y = -1.0 + 2.0*(double)h/63.0;
    double x = -1.0 + 2.0*(double)w/63.0;
    double r = sqrt(x*x+y*y); if (r < 1e-8) r = 1e-8;
    double xn=x/r, yn=y/r;
    const double c0=0.28209479177387814, c2=1.0925484305920792, c20=0.31539156525252005;
    float sh[6];
    sh[0]=(float)c0;
    sh[1]=(float)(c2*xn*yn);
    sh[2]=0.0f;
    sh[3]=(float)(-c20);
    sh[4]=0.0f;
    sh[5]=(float)(0.5*c2*(xn*xn-yn*yn));
    #pragma unroll
    for (int i=0;i<6;i++) d_sh[n*6+i]=sh[i];
    for (int blk=0;blk<2;blk++){
      float b = pbb[blk];
      #pragma unroll
      for (int i=0;i<6;i++) b = fmaf(sh[i], pbw[blk*6+i], b);
      d_eb[blk*NLR+n]=expf(b);
    }
    return;
  }
  __shared__ float a_s[96];
  if (tid < 96){
    int c = tid & 7; int pp = (tid>>3)%6; int blk = tid/48;
    const float* liw = (pp==0||pp==1||pp==4) ? (liw4+blk*8) : (liw6+blk*8);
    float s=0.f;
    for (int u=0;u<8;u++) s = fmaf(liw[u], tvw[((blk*6+pp)*8+u)*8 + c], s);
    a_s[tid]=s;
  }
  __syncthreads();
  if (tid < 16){
    int q = tid&7, blk = tid>>3;
    const float* liw = (q==0||q==1||q==4||q==5)? (liw4+blk*8) : (liw6+blk*8);
    const float* low = (q<4)? (low4+blk*8) : (low6+blk*8);
    float b[8];
    #pragma unroll
    for (int v=0;v<8;v++){
      float s=0.f;
      for (int u=0;u<8;u++){
        float lu = liw[u];
        for (int w=0;w<8;w++)
          s = fmaf(lu*tow[(((blk*8+q)*8+u)*8+v)*8+w], low[w], s);
      }
      b[v]=s;
    }
    int pbase = (q&1)? 3 : 0;
    const float invs = (1.0f/sqrtf(24.0f)) * (1.0f/16.0f) * (1.0f/sqrtf(8.0f));
    for (int pp=0;pp<3;pp++){
      float s=0.f;
      #pragma unroll
      for (int v=0;v<8;v++) s = fmaf(b[v], a_s[(blk*6+pbase+pp)*8 + v], s);
      d_coef[(blk*8+q)*3+pp] = s*invs;
    }
  }
}

// ---------------- per-point prep (featinit folded for blk 0) ---------------
__global__ void __launch_bounds__(64) k_prepare(const float* __restrict__ in4,
                                                const float* __restrict__ in6,
                                                const float* __restrict__ ls4,
                                                const float* __restrict__ ls6,
                                                int blk, int sel){
  __shared__ float wv[W3J_OUT_OFF];
  int tid = threadIdx.x;
  for (int i=tid;i<W3J_OUT_OFF;i+=64) wv[i]=d_w3j[i];
  __syncthreads();
  int p = blockIdx.x*64 + tid;
  float f[22];
  float s4=0.f, s6=0.f;
  if (blk==0){
    #pragma unroll
    for (int i=0;i<9;i++){ f[i]=in4[p*9+i]; s4=fmaf(f[i],f[i],s4); d_feat0[p*22+i]=f[i]; }
    #pragma unroll
    for (int i=0;i<13;i++){ f[9+i]=in6[p*13+i]; s6=fmaf(f[9+i],f[9+i],s6); d_feat0[p*22+9+i]=f[9+i]; }
  } else {
    const float* fin = sel ? d_feat1 : d_feat0;
    #pragma unroll
    for (int i=0;i<9;i++){ f[i]=fin[p*22+i]; s4=fmaf(f[i],f[i],s4); }
    #pragma unroll
    for (int i=9;i<22;i++){ f[i]=fin[p*22+i]; s6=fmaf(f[i],f[i],s6); }
  }
  float inv4=1.f/fmaxf(sqrtf(s4),1e-12f);
  float inv6=1.f/fmaxf(sqrtf(s6),1e-12f);
  float e4=expf(ls4[blk]), e6=expf(ls6[blk]);
  {
    float kh[KST], kl[KST];
    #pragma unroll
    for (int i=0;i<9;i++){
      float kk=f[i]*inv4;
      d_qvT[i*NPTS+p]=kk*e4;
      kh[i]=tf32r(kk); kl[i]=tf32r(kk-kh[i]);
    }
    #pragma unroll
    for (int i=9;i<22;i++){
      float kk=f[i]*inv6;
      d_qvT[i*NPTS+p]=kk*e6;
      kh[i]=tf32r(kk); kl[i]=tf32r(kk-kh[i]);
    }
    #pragma unroll
    for (int i=22;i<KST;i++){ kh[i]=0.f; kl[i]=0.f; }
    float4* dh = (float4*)(d_kvh + (size_t)p*KST);
    float4* dl = (float4*)(d_kvl + (size_t)p*KST);
    #pragma unroll
    for (int j=0;j<KST/4;j++){
      dh[j] = make_float4(kh[j*4],kh[j*4+1],kh[j*4+2],kh[j*4+3]);
      dl[j] = make_float4(kl[j*4],kl[j*4+1],kl[j*4+2],kl[j*4+3]);
    }
  }
  int n = p & (NLR-1);
  float ebv = d_eb[blk*NLR+n];
  float sh0=d_sh[n*6];
  float sh2[5];
  #pragma unroll
  for (int j=0;j<5;j++) sh2[j]=d_sh[n*6+1+j];
  float* g = d_gv + (size_t)p*GST;
  { float a[9];
    #pragma unroll
    for (int k=0;k<9;k++) a[k]=0.f;
    #pragma unroll 1
    for (int i=0;i<9;i++){ float fi=f[i];
      #pragma unroll
      for (int k=0;k<9;k++) a[k]=fmaf(fi,wv[i*9+k],a[k]); }
    #pragma unroll
    for (int k=0;k<9;k++) g[k]=tf32r(a[k]*sh0*ebv); }
  { float a[9];
    #pragma unroll
    for (int k=0;k<9;k++) a[k]=0.f;
    #pragma unroll 1
    for (int i=0;i<9;i++){ float fi=f[i];
      #pragma unroll 1
      for (int j=0;j<5;j++){ float c=fi*sh2[j];
        #pragma unroll
        for (int k=0;k<9;k++) a[k]=fmaf(c,wv[81+(i*5+j)*9+k],a[k]); } }
    #pragma unroll
    for (int k=0;k<9;k++) g[9+k]=tf32r(a[k]*ebv); }
  { float a[9];
    #pragma unroll
    for (int k=0;k<9;k++) a[k]=0.f;
    #pragma unroll 1
    for (int i=0;i<13;i++){ float fi=f[9+i];
      #pragma unroll 1
      for (int j=0;j<5;j++){ float c=fi*sh2[j];
        #pragma unroll
        for (int k=0;k<9;k++) a[k]=fmaf(c,wv[486+(i*5+j)*9+k],a[k]); } }
    #pragma unroll
    for (int k=0;k<9;k++) g[18+k]=tf32r(a[k]*ebv); }
  { float a[13];
    #pragma unroll
    for (int k=0;k<13;k++) a[k]=0.f;
    #pragma unroll 1
    for (int i=0;i<13;i++){ float fi=f[9+i];
      #pragma unroll
      for (int k=0;k<13;k++) a[k]=fmaf(fi,wv[1071+i*13+k],a[k]); }
    #pragma unroll
    for (int k=0;k<13;k++) g[27+k]=tf32r(a[k]*sh0*ebv); }
  { float a[13];
    #pragma unroll
    for (int k=0;k<13;k++) a[k]=0.f;
    #pragma unroll 1
    for (int i=0;i<9;i++){ float fi=f[i];
      #pragma unroll 1
      for (int j=0;j<5;j++){ float c=fi*sh2[j];
        #pragma unroll
        for (int k=0;k<13;k++) a[k]=fmaf(c,wv[1240+(i*5+j)*13+k],a[k]); } }
    #pragma unroll
    for (int k=0;k<13;k++) g[40+k]=tf32r(a[k]*ebv); }
  { float a[13];
    #pragma unroll
    for (int k=0;k<13;k++) a[k]=0.f;
    #pragma unroll 1
    for (int i=0;i<13;i++){ float fi=f[9+i];
      #pragma unroll 1
      for (int j=0;j<5;j++){ float c=fi*sh2[j];
        #pragma unroll
        for (int k=0;k<13;k++) a[k]=fmaf(c,wv[1825+(i*5+j)*13+k],a[k]); } }
    #pragma unroll
    for (int k=0;k<13;k++) g[53+k]=tf32r(a[k]*ebv); }
  g[66]=tf32r(ebv);
  #pragma unroll
  for (int k=67;k<GST;k++) g[k]=0.f;
}

// ---------------- attention: full-HMMA, cp.async double buffer -------------
__global__ void __launch_bounds__(256,3) k_attn(){
  __shared__ float Qs [24*RT];          // 12288 B
  __shared__ float Ksh[2][KT*KST];      // 2x3584 B
  __shared__ float Ksl[2][KT*KST];      // 2x3584 B
  __shared__ float Gs [2][KT*GST];      // 2x9728 B
  const int tid = threadIdx.x;
  const int w = tid>>5, l = tid&31;
  const int batch = blockIdx.y, split = blockIdx.z;
  const int prow = batch*NLR + blockIdx.x*RT;
  const int m0 = batch*NLR + split*(NLR/SPLITS);
  const int ntiles = (NLR/SPLITS)/KT;

  // issue async loads for tile 0 into buffer 0
  {
    unsigned sKh = (unsigned)__cvta_generic_to_shared(&Ksh[0][0]);
    unsigned sKl = (unsigned)__cvta_generic_to_shared(&Ksl[0][0]);
    unsigned sG  = (unsigned)__cvta_generic_to_shared(&Gs[0][0]);
    if (tid < KT*KST/4){
      cpa16(sKh + tid*16, d_kvh + (size_t)m0*KST + tid*4);
      cpa16(sKl + tid*16, d_kvl + (size_t)m0*KST + tid*4);
    }
    for (int i=tid;i<KT*GST/4;i+=256)
      cpa16(sG + i*16, d_gv + (size_t)m0*GST + i*4);
    cpa_commit();
  }
  for (int i=tid;i<24*RT;i+=256){
    int kd=i>>7, r=i&127;
    Qs[i] = (kd<22)? d_qvT[kd*NPTS + prow + r] : 0.f;
  }
  cpa_wait0();
  __syncthreads();

  const int r0 = 16*w + (l>>2);
  const int lj = l & 3;
  unsigned qh[3][4], ql[3][4];
  #pragma unroll
  for (int ks=0;ks<3;ks++){
    float v0 = Qs[(ks*8+lj)*RT + r0];
    float v1 = Qs[(ks*8+lj)*RT + r0+8];
    float v2 = Qs[(ks*8+lj+4)*RT + r0];
    float v3 = Qs[(ks*8+lj+4)*RT + r0+8];
    qh[ks][0]=tf32bits(v0); ql[ks][0]=tf32bits(v0-__uint_as_float(qh[ks][0]));
    qh[ks][1]=tf32bits(v1); ql[ks][1]=tf32bits(v1-__uint_as_float(qh[ks][1]));
    qh[ks][2]=tf32bits(v2); ql[ks][2]=tf32bits(v2-__uint_as_float(qh[ks][2]));
    qh[ks][3]=tf32bits(v3); ql[ks][3]=tf32bits(v3-__uint_as_float(qh[ks][3]));
  }

  float accd[9][4];
  #pragma unroll
  for (int n=0;n<9;n++){
    #pragma unroll
    for (int c=0;c<4;c++) accd[n][c]=0.f;
  }

  for (int t=0;t<ntiles;t++){
    const int b = t&1;
    // prefetch next tile into the other buffer
    if (t+1<ntiles){
      const int mb = m0 + (t+1)*KT;
      unsigned sKh = (unsigned)__cvta_generic_to_shared(&Ksh[b^1][0]);
      unsigned sKl = (unsigned)__cvta_generic_to_shared(&Ksl[b^1][0]);
      unsigned sG  = (unsigned)__cvta_generic_to_shared(&Gs[b^1][0]);
      if (tid < KT*KST/4){
        cpa16(sKh + tid*16, d_kvh + (size_t)mb*KST + tid*4);
        cpa16(sKl + tid*16, d_kvl + (size_t)mb*KST + tid*4);
      }
      for (int i=tid;i<KT*GST/4;i+=256)
        cpa16(sG + i*16, d_gv + (size_t)mb*GST + i*4);
      cpa_commit();
    }
    // compute on buffer b
    #pragma unroll
    for (int kg=0;kg<4;kg++){
      float sa[4], sb[4], scc[4];
      #pragma unroll
      for (int i=0;i<4;i++){ sa[i]=0.f; sb[i]=0.f; scc[i]=0.f; }
      const int krow = (kg*8 + (l>>2))*KST;
      #pragma unroll
      for (int ks=0;ks<3;ks++){
        unsigned b0h = __float_as_uint(Ksh[b][krow + ks*8 + lj]);
        unsigned b1h = __float_as_uint(Ksh[b][krow + ks*8 + lj + 4]);
        unsigned b0l = __float_as_uint(Ksl[b][krow + ks*8 + lj]);
        unsigned b1l = __float_as_uint(Ksl[b][krow + ks*8 + lj + 4]);
        mma_tf32(sa,  qh[ks][0],qh[ks][1],qh[ks][2],qh[ks][3], b0h,b1h);
        mma_tf32(sb,  qh[ks][0],qh[ks][1],qh[ks][2],qh[ks][3], b0l,b1l);
        mma_tf32(scc, ql[ks][0],ql[ks][1],ql[ks][2],ql[ks][3], b0h,b1h);
      }
      float s0 = sa[0]+(sb[0]+scc[0]);
      float s1 = sa[1]+(sb[1]+scc[1]);
      float s2 = sa[2]+(sb[2]+scc[2]);
      float s3 = sa[3]+(sb[3]+scc[3]);
      unsigned a0 = tf32bits(__expf(s0));
      unsigned a1 = tf32bits(__expf(s2));
      unsigned a2 = tf32bits(__expf(s1));
      unsigned a3 = tf32bits(__expf(s3));
      const int gr0 = (kg*8 + 2*lj)*GST;
      const int gr1 = gr0 + GST;
      const int ncol = (l>>2);
      #pragma unroll
      for (int n=0;n<9;n++){
        unsigned b0 = __float_as_uint(Gs[b][gr0 + n*8 + ncol]);
        unsigned b1 = __float_as_uint(Gs[b][gr1 + n*8 + ncol]);
        mma_tf32(accd[n], a0,a1,a2,a3, b0,b1);
      }
    }
    if (t+1<ntiles) cpa_wait0();
    __syncthreads();
  }
  {
    const int p0 = prow + r0;
    const int p1 = p0 + 8;
    float* base0 = d_part + ((size_t)split*NPTS + p0)*68;
    float* base1 = d_part + ((size_t)split*NPTS + p1)*68;
    #pragma unroll
    for (int n=0;n<9;n++){
      int col = n*8 + 2*lj;
      if (col < 68){
        *(float2*)(base0 + col) = make_float2(accd[n][0], accd[n][1]);
        *(float2*)(base1 + col) = make_float2(accd[n][2], accd[n][3]);
      }
    }
  }
}

// ---------------- coalesced split reduce (warp per point) ------------------
__global__ void k_reduce(){
  const int lane = threadIdx.x & 31;
  const int p = blockIdx.x*8 + (threadIdx.x>>5);
  float4 acc = make_float4(0.f,0.f,0.f,0.f);
  if (lane < 17){
    #pragma unroll 4
    for (int sp=0;sp<SPLITS;sp++){
      float4 v = *(const float4*)(d_part + ((size_t)sp*NPTS + p)*68 + lane*4);
      acc.x+=v.x; acc.y+=v.y; acc.z+=v.z; acc.w+=v.w;
    }
  }
  float den = __shfl_sync(0xffffffffu, acc.z, 16);
  float inv = 1.f/den;
  if (lane < 17){
    int c = lane*4;
    if (c   < 66) d_G[(c  )*NPTS+p] = acc.x*inv;
    if (c+1 < 66) d_G[(c+1)*NPTS+p] = acc.y*inv;
    if (c+2 < 66) d_G[(c+2)*NPTS+p] = acc.z*inv;
    if (c+3 < 66) d_G[(c+3)*NPTS+p] = acc.w*inv;
  }
}

// ---------------- per-point output tensor products ----------------
template<int D1,int D2,int D3>
__device__ __forceinline__ void qpath(const float* __restrict__ w3, const float* __restrict__ f,
                                      int p, float c0, float c1, float c2,
                                      int g0, int g1, int g2, float* out){
  #pragma unroll 1
  for (int j=0;j<D2;j++){
    float gm = c0*d_G[(g0+j)*NPTS+p] + c1*d_G[(g1+j)*NPTS+p] + c2*d_G[(g2+j)*NPTS+p];
    #pragma unroll
    for (int i=0;i<D1;i++){
      float cf = gm*f[i];
      #pragma unroll
      for (int k=0;k<D3;k++) out[k] = fmaf(cf, w3[(i*D2+j)*D3+k], out[k]);
    }
  }
}

__global__ void __launch_bounds__(128) k_output(int blk, int sel){
  const float* fin = sel ? d_feat1 : d_feat0;
  float* fout = sel ? d_feat0 : d_feat1;
  __shared__ float w3s[6292];
  int tid = threadIdx.x;
  int half = blockIdx.y;
  int base = half ? 7026 : 2670;
  int len  = half ? 6292 : 4356;
  for (int i=tid;i<len;i+=128) w3s[i]=d_w3j[base+i];
  __syncthreads();
  int p = blockIdx.x*128 + tid;
  float f4[9], f6[13];
  #pragma unroll
  for (int i=0;i<9;i++) f4[i]=fin[p*22+i];
  #pragma unroll
  for (int i=0;i<13;i++) f6[i]=fin[p*22+9+i];
  const float* cf = d_coef + blk*24;
  if (half==0){
    float d4[9];
    #pragma unroll
    for (int k=0;k<9;k++) d4[k]=0.f;
    qpath<9,9,9>   (w3s+0,    f4, p, cf[0], cf[1], cf[2],  0, 9,18, d4);
    qpath<9,13,9>  (w3s+729,  f4, p, cf[3], cf[4], cf[5], 27,40,53, d4);
    qpath<13,9,9>  (w3s+1782, f6, p, cf[6], cf[7], cf[8],  0, 9,18, d4);
    qpath<13,13,9> (w3s+2835, f6, p, cf[9], cf[10],cf[11],27,40,53, d4);
    #pragma unroll
    for (int k=0;k<9;k++) fout[p*22+k] = f4[k]+d4[k];
  } else {
    float d6[13];
    #pragma unroll
    for (int k=0;k<13;k++) d6[k]=0.f;
    qpath<9,9,13>  (w3s+0,    f4, p, cf[12],cf[13],cf[14], 0, 9,18, d6);
    qpath<9,13,13> (w3s+1053, f4, p, cf[15],cf[16],cf[17],27,40,53, d6);
    qpath<13,9,13> (w3s+2574, f6, p, cf[18],cf[19],cf[20], 0, 9,18, d6);
    qpath<13,13,13>(w3s+4095, f6, p, cf[21],cf[22],cf[23],27,40,53, d6);
    #pragma unroll
    for (int k=0;k<13;k++) fout[p*22+9+k] = f6[k]+d6[k];
  }
}

// ---------------- upsample ----------------
__global__ void k_upsample(const float* __restrict__ upw, float* __restrict__ out){
  int idx = blockIdx.x*256 + threadIdx.x;
  if (idx >= NBATCH*65536) return;
  int b = idx >> 16;
  int nh = idx & 65535;
  int rw = nh & 3; int t = nh >> 2; int w = t & 63; t >>= 6; int rh = t & 3; int h = t >> 2;
  int p = b*NLR + h*64 + w;
  float u4 = upw[(rh*4+rw)*2 + 0];
  float u6 = upw[(rh*4+rw)*2 + 1];
  float* o4 = out + (size_t)idx*9;
  float* o6 = out + 1179648 + (size_t)idx*13;
  #pragma unroll
  for (int k=0;k<9;k++)  o4[k] = d_feat0[p*22+k]*u4;
  #pragma unroll
  for (int k=0;k<13;k++) o6[k] = d_feat0[p*22+9+k]*u6;
}

extern "C" void kernel_launch(void* const* d_in, const int* in_sizes, int n_in,
                              void* d_out, int out_size) {
  const float* f4   = (const float*)d_in[0];
  const float* f6   = (const float*)d_in[1];
  const float* ls4  = (const float*)d_in[2];
  const float* ls6  = (const float*)d_in[3];
  const float* pbw  = (const float*)d_in[4];
  const float* pbb  = (const float*)d_in[5];
  const float* liw4 = (const float*)d_in[6];
  const float* liw6 = (const float*)d_in[7];
  const float* tvw  = (const float*)d_in[8];
  const float* tow  = (const float*)d_in[9];
  const float* low4 = (const float*)d_in[10];
  const float* low6 = (const float*)d_in[11];
  const float* upw  = (const float*)d_in[12];
  float* out = (float*)d_out;

  k_w3j<<<14,256>>>();
  k_shcoef<<<17,256>>>(pbw, pbb, liw4, liw6, tvw, tow, low4, low6);
  for (int blk=0; blk<2; blk++){
    k_prepare<<<128,64>>>(f4, f6, ls4, ls6, blk, blk&1);
    k_attn<<<dim3(NLR/RT, NBATCH, SPLITS), 256>>>();
    k_reduce<<<NPTS/8,256>>>();
    k_output<<<dim3(64,2),128>>>(blk, blk&1);
  }
  k_upsample<<<512,256>>>(upw, out);
}